// round 6
// baseline (speedup 1.0000x reference)
#include <cuda_runtime.h>
#include <cuda_bf16.h>
#include <cstdint>

typedef unsigned long long u64;

// Problem constants
#define B_      2048
#define N_      64
#define OBS_    8
#define PRED_   12
#define IN_     6
#define E_      512
#define C_      6
#define CN_     7          // C + 1
#define K_      20
#define DSELF_  120        // IN*(OBS+PRED)
#define DNEI_   48         // IN*OBS
#define RTOT_   (B_ * N_)  // 131072
#define NBLK_   (RTOT_ / 256)   // 512
#define EPSF    1e-4f

#define KP_     144        // split-K: [hi(48) | lo(48) | hi(48)]
#define ROWB_   (KP_ * 2)  // 288 bytes per packed row
#define X_ELEMS ((size_t)B_ * K_ * E_)   // 20,971,520

// ---------------- scratch (__device__ globals; no allocation) ----------------
__device__ __nv_bfloat16 g_Ab[(size_t)RTOT_ * KP_];      // packed split-A rows (~38 MB)
__device__ __nv_bfloat16 g_Wb[(size_t)CN_ * E_ * KP_];   // split weights (~1 MB)
__device__ int   g_perm[RTOT_];
__device__ int   g_bcnt[CN_][NBLK_];
__device__ int   g_base[CN_][NBLK_];
__device__ int   g_cnt[CN_];
__device__ int   g_off[CN_];
__device__ float g_anchor[(size_t)C_ * K_ * E_];

// ---------------- kernel 1: per-block class histograms + (folded) weight split ----
__global__ void k_count_wprep(const int* __restrict__ nei_labels,
                              const float* __restrict__ W_nei) {
    if (blockIdx.x < NBLK_) {
        __shared__ int sc[CN_];
        if (threadIdx.x < CN_) sc[threadIdx.x] = 0;
        __syncthreads();
        int i = blockIdx.x * 256 + threadIdx.x;
        atomicAdd(&sc[nei_labels[i]], 1);
        __syncthreads();
        if (threadIdx.x < CN_) g_bcnt[threadIdx.x][blockIdx.x] = sc[threadIdx.x];
    } else {
        int g = (blockIdx.x - NBLK_) * 256 + threadIdx.x;   // (c, n)
        if (g >= CN_ * E_) return;
        int c = g / E_, n = g % E_;
        char* rb = (char*)g_Wb + (size_t)g * ROWB_;
        const float* W = W_nei + (size_t)c * DNEI_ * E_ + n;
        for (int k = 0; k < DNEI_; k++) {
            float w = W[(size_t)k * E_];
            __nv_bfloat16 h = __float2bfloat16(w);
            __nv_bfloat16 l = __float2bfloat16(w - __bfloat162float(h));
            *(__nv_bfloat16*)(rb + k * 2)       = h;   // seg0 (pairs A hi)
            *(__nv_bfloat16*)(rb + 96 + k * 2)  = h;   // seg1 (pairs A lo)
            *(__nv_bfloat16*)(rb + 192 + k * 2) = l;   // seg2 (pairs A hi)
        }
    }
}

// ---------------- kernel 2: per-class scan over blocks ----------------
__global__ void k_prefix() {
    int w    = threadIdx.x >> 5;
    int lane = threadIdx.x & 31;
    __shared__ int tot[CN_];
    if (w < CN_) {
        int acc = 0;
#pragma unroll
        for (int seg = 0; seg < NBLK_ / 32; seg++) {
            int v = g_bcnt[w][seg * 32 + lane];
            int s = v;
#pragma unroll
            for (int d = 1; d < 32; d <<= 1) {
                int t = __shfl_up_sync(0xffffffffu, s, d);
                if (lane >= d) s += t;
            }
            g_base[w][seg * 32 + lane] = acc + s - v;
            acc += __shfl_sync(0xffffffffu, s, 31);
        }
        if (lane == 0) tot[w] = acc;
    }
    __syncthreads();
    if (threadIdx.x == 0) {
        int a = 0;
        for (int c = 0; c < CN_; c++) { g_off[c] = a; g_cnt[c] = tot[c]; a += tot[c]; }
    }
}

// ---------------- kernel 3: scatter + transform + bf16 hi/lo split copy --------
__global__ void k_scattercopy(const float* __restrict__ neis,
                              const int*   __restrict__ nei_labels) {
    __shared__ int s_cur[CN_];
    __shared__ int s_pos[256];
    int tid = threadIdx.x;
    int blk = blockIdx.x;
    if (tid < CN_) s_cur[tid] = g_off[tid] + g_base[tid][blk];
    __syncthreads();

    int row = blk * 256 + tid;
    int c   = nei_labels[row];
    int pos = atomicAdd(&s_cur[c], 1);
    s_pos[tid]  = pos;
    g_perm[pos] = row;
    __syncthreads();

#pragma unroll
    for (int it = 0; it < 12; it++) {
        int idx = it * 256 + tid;
        int r = idx / 12, q = idx % 12;       // q: float4 chunk 0..11
        float4 v = *(const float4*)(neis + ((size_t)blk * 256 + r) * DNEI_ + q * 4);
        v.x = (v.x >= 0.f) ? 1.f / (v.x + EPSF) : 1.f / (v.x - EPSF);
        v.y = (v.y >= 0.f) ? 1.f / (v.y + EPSF) : 1.f / (v.y - EPSF);
        v.z = (v.z >= 0.f) ? 1.f / (v.z + EPSF) : 1.f / (v.z - EPSF);
        v.w = (v.w >= 0.f) ? 1.f / (v.w + EPSF) : 1.f / (v.w - EPSF);

        __nv_bfloat16 hx = __float2bfloat16(v.x), hy = __float2bfloat16(v.y);
        __nv_bfloat16 hz = __float2bfloat16(v.z), hw = __float2bfloat16(v.w);
        __nv_bfloat16 lx = __float2bfloat16(v.x - __bfloat162float(hx));
        __nv_bfloat16 ly = __float2bfloat16(v.y - __bfloat162float(hy));
        __nv_bfloat16 lz = __float2bfloat16(v.z - __bfloat162float(hz));
        __nv_bfloat16 lw = __float2bfloat16(v.w - __bfloat162float(hw));

        uint32_t h01 = ((uint32_t)__bfloat16_as_ushort(hy) << 16) | __bfloat16_as_ushort(hx);
        uint32_t h23 = ((uint32_t)__bfloat16_as_ushort(hw) << 16) | __bfloat16_as_ushort(hz);
        uint32_t l01 = ((uint32_t)__bfloat16_as_ushort(ly) << 16) | __bfloat16_as_ushort(lx);
        uint32_t l23 = ((uint32_t)__bfloat16_as_ushort(lw) << 16) | __bfloat16_as_ushort(lz);

        char* rb = (char*)g_Ab + (size_t)s_pos[r] * ROWB_;
        *(uint2*)(rb + q * 8)        = make_uint2(h01, h23);   // seg0: hi (k 0..47)
        *(uint2*)(rb + 96 + q * 8)   = make_uint2(l01, l23);   // seg1: lo (k 48..95)
        *(uint2*)(rb + 192 + q * 8)  = make_uint2(h01, h23);   // seg2: hi (k 96..143)
    }
}

// ================= mma.sync / cp.async helpers =================
__device__ __forceinline__ uint32_t smem_u32(const void* p) {
    uint32_t a;
    asm("{ .reg .u64 t; cvta.to.shared.u64 t, %1; cvt.u32.u64 %0, t; }" : "=r"(a) : "l"(p));
    return a;
}
__device__ __forceinline__ void cp_async16(uint32_t dst, const void* src, int src_size) {
    asm volatile("cp.async.cg.shared.global [%0], [%1], 16, %2;"
                 :: "r"(dst), "l"(src), "r"(src_size) : "memory");
}
__device__ __forceinline__ void cp_async_wait_all() {
    asm volatile("cp.async.commit_group;\n\tcp.async.wait_group 0;" ::: "memory");
}
__device__ __forceinline__ void ldsm_x4(uint32_t& r0, uint32_t& r1, uint32_t& r2, uint32_t& r3,
                                        uint32_t addr) {
    asm volatile("ldmatrix.sync.aligned.m8n8.x4.shared.b16 {%0,%1,%2,%3}, [%4];"
                 : "=r"(r0), "=r"(r1), "=r"(r2), "=r"(r3) : "r"(addr));
}
__device__ __forceinline__ void mma16816(float* c, const uint32_t* a, uint32_t b0, uint32_t b1) {
    asm volatile("mma.sync.aligned.m16n8k16.row.col.f32.bf16.bf16.f32 "
                 "{%0,%1,%2,%3}, {%4,%5,%6,%7}, {%8,%9}, {%0,%1,%2,%3};"
                 : "+f"(c[0]), "+f"(c[1]), "+f"(c[2]), "+f"(c[3])
                 : "r"(a[0]), "r"(a[1]), "r"(a[2]), "r"(a[3]), "r"(b0), "r"(b1));
}

// ---------------- kernel 4: grouped GEMM via mma.sync bf16 ----------------
// 128x128 tile, K'=144 resident. 256 threads = 8 warps (2x4), warp = 64x32.
#define MT 128
#define NT 128
#define GEMM_MAX_MTILES ((RTOT_ / MT) + CN_)   // 1031
#define GEMM_GRID (GEMM_MAX_MTILES * (E_ / NT))
#define STRIDE_B 304                           // padded row stride — LDSM conflict-free
#define TILE_B   (128 * STRIDE_B)              // 38912 bytes
#define SMEM_HDR 1024                          // s_perm(512) + s_bias(512)
#define SMEM_BYTES (SMEM_HDR + 2 * TILE_B)     // 78848

__global__ void __launch_bounds__(256, 2)
k_gemm_mma(const float* __restrict__ b_nei,
           float*       __restrict__ out_nei) {
    int nt  = blockIdx.x & 3;
    int mid = blockIdx.x >> 2;
    int c = -1, mt = 0, acc_t = 0;
#pragma unroll
    for (int cc = 0; cc < CN_; cc++) {
        int t = (g_cnt[cc] + MT - 1) >> 7;
        if (c < 0 && mid < acc_t + t) { c = cc; mt = mid - acc_t; }
        acc_t += t;
    }
    if (c < 0) return;

    int cnt = g_cnt[c];
    int off = g_off[c];
    int m0  = mt * MT;

    extern __shared__ char smem[];
    int*   s_perm = (int*)smem;                  // [128]
    float* s_bias = (float*)(smem + 512);        // [128]
    char*  a_sm   = smem + SMEM_HDR;
    char*  b_sm   = a_sm + TILE_B;

    int tid  = threadIdx.x;
    int lane = tid & 31;
    int wid  = tid >> 5;
    int wm   = wid & 1;          // 2 warp rows (64 rows each)
    int wn   = wid >> 1;         // 4 warp cols (32 cols each)

    // ---- cp.async tile loads: thread t -> row t>>1, 16B chunks h..h+8 ----
    {
        int r = tid >> 1;
        int h = (tid & 1) * 9;
        // A
        int a_ok = (m0 + r < cnt) ? 16 : 0;
        const char* Asrc = (const char*)g_Ab
                         + (size_t)(off + (a_ok ? (m0 + r) : off ? 0 : 0)) * ROWB_;
        // (clamp src row to a valid packed row when OOB; src unused at size 0)
        Asrc = (const char*)g_Ab + (size_t)(a_ok ? (off + m0 + r) : 0) * ROWB_;
        uint32_t a_dst = smem_u32(a_sm) + (uint32_t)r * STRIDE_B + (uint32_t)h * 16;
#pragma unroll
        for (int i = 0; i < 9; i++)
            cp_async16(a_dst + i * 16, Asrc + (h + i) * 16, a_ok);
        // B (always valid: 128 weight rows out of 512)
        const char* Bsrc = (const char*)g_Wb
                         + ((size_t)c * E_ + nt * NT + r) * ROWB_;
        uint32_t b_dst = smem_u32(b_sm) + (uint32_t)r * STRIDE_B + (uint32_t)h * 16;
#pragma unroll
        for (int i = 0; i < 9; i++)
            cp_async16(b_dst + i * 16, Bsrc + (h + i) * 16, 16);
    }

    // stage perm + bias while cp.async is in flight
    if (tid < 128) {
        int r = m0 + tid;
        s_perm[tid] = (r < cnt) ? g_perm[off + r] : -1;
        s_bias[tid] = b_nei[(size_t)c * E_ + nt * NT + tid];
    }
    cp_async_wait_all();
    __syncthreads();

    // ldmatrix lane address bases
    uint32_t a_u32 = smem_u32(a_sm);
    uint32_t b_u32 = smem_u32(b_sm);
    uint32_t a_base = a_u32 + (uint32_t)(wm * 64 + (lane & 15)) * STRIDE_B
                            + ((lane >> 4) << 4);
    uint32_t b_base = b_u32 + (uint32_t)(wn * 32 + ((lane >> 4) << 3) + (lane & 7)) * STRIDE_B
                            + (((lane >> 3) & 1) << 4);

    float acc[4][4][4];
#pragma unroll
    for (int i = 0; i < 4; i++)
#pragma unroll
        for (int j = 0; j < 4; j++)
#pragma unroll
            for (int q = 0; q < 4; q++) acc[i][j][q] = 0.f;

#pragma unroll
    for (int kc = 0; kc < 9; kc++) {           // K' = 144 = 9 x 16
        uint32_t kb = kc * 32;
        uint32_t B0[4], B1[4];
        ldsm_x4(B0[0], B0[1], B0[2], B0[3], b_base + kb);                 // ntiles 0,1
        ldsm_x4(B1[0], B1[1], B1[2], B1[3], b_base + 16 * STRIDE_B + kb); // ntiles 2,3
#pragma unroll
        for (int mi = 0; mi < 4; mi++) {
            uint32_t A[4];
            ldsm_x4(A[0], A[1], A[2], A[3], a_base + (uint32_t)mi * 16 * STRIDE_B + kb);
            mma16816(acc[mi][0], A, B0[0], B0[1]);
            mma16816(acc[mi][1], A, B0[2], B0[3]);
            mma16816(acc[mi][2], A, B1[0], B1[1]);
            mma16816(acc[mi][3], A, B1[2], B1[3]);
        }
    }

    // epilogue
    int g = lane >> 2, t4 = lane & 3;
#pragma unroll
    for (int mi = 0; mi < 4; mi++) {
#pragma unroll
        for (int half = 0; half < 2; half++) {
            int rloc = wm * 64 + mi * 16 + g + half * 8;
            int rg   = s_perm[rloc];
            if (rg >= 0) {
                float* orow = out_nei + (size_t)rg * E_ + nt * NT + wn * 32;
#pragma unroll
                for (int ni = 0; ni < 4; ni++) {
                    int colo = ni * 8 + t4 * 2;
                    float2 v = make_float2(
                        acc[mi][ni][half * 2 + 0] + s_bias[wn * 32 + colo],
                        acc[mi][ni][half * 2 + 1] + s_bias[wn * 32 + colo + 1]);
                    *(float2*)(orow + colo) = v;
                }
            }
        }
    }
}

// ---------------- kernel 5: anchor ----------------
__global__ void k_anchor(const float* __restrict__ init_trajs,
                         const float* __restrict__ W_self,
                         const float* __restrict__ b_self) {
    int c  = blockIdx.x / K_;
    int kk = blockIdx.x % K_;
    __shared__ float tr[PRED_ * IN_];
    if (threadIdx.x < PRED_ * IN_)
        tr[threadIdx.x] = init_trajs[((size_t)c * K_ + kk) * (PRED_ * IN_) + threadIdx.x];
    __syncthreads();

    int col = threadIdx.x * 4;
    const float* bb = b_self + (size_t)c * E_ + col;
    float4 acc = *(const float4*)bb;
    const float* W = W_self + ((size_t)c * DSELF_ + DNEI_) * E_ + col;
#pragma unroll 8
    for (int j = 0; j < PRED_ * IN_; j++) {
        float  t = tr[j];
        float4 w = *(const float4*)(W + (size_t)j * E_);
        acc.x += t * w.x; acc.y += t * w.y; acc.z += t * w.z; acc.w += t * w.w;
    }
    *(float4*)(g_anchor + ((size_t)c * K_ + kk) * E_ + col) = acc;
}

// ---------------- kernel 6: x path ----------------
__global__ void k_x(const float* __restrict__ obs,
                    const float* __restrict__ W_self,
                    const int*   __restrict__ self_labels,
                    float*       __restrict__ out_x) {
    int b = blockIdx.x;
    __shared__ float ob[DNEI_];
    if (threadIdx.x < DNEI_)
        ob[threadIdx.x] = obs[(size_t)b * DNEI_ + threadIdx.x];
    __syncthreads();

    int c   = self_labels[b];
    int col = threadIdx.x * 4;
    const float* W = W_self + (size_t)c * DSELF_ * E_ + col;
    float4 acc = make_float4(0.f, 0.f, 0.f, 0.f);
#pragma unroll 8
    for (int j = 0; j < DNEI_; j++) {
        float  t = ob[j];
        float4 w = *(const float4*)(W + (size_t)j * E_);
        acc.x += t * w.x; acc.y += t * w.y; acc.z += t * w.z; acc.w += t * w.w;
    }
#pragma unroll
    for (int kk = 0; kk < K_; kk++) {
        float4 an = *(const float4*)(g_anchor + ((size_t)c * K_ + kk) * E_ + col);
        float4 v  = make_float4(acc.x + an.x, acc.y + an.y, acc.z + an.z, acc.w + an.w);
        *(float4*)(out_x + ((size_t)b * K_ + kk) * E_ + col) = v;
    }
}

// ---------------- launcher ----------------
#define WPREP_BLKS ((CN_ * E_ + 255) / 256)    // 14

extern "C" void kernel_launch(void* const* d_in, const int* in_sizes, int n_in,
                              void* d_out, int out_size) {
    const float* obs         = (const float*)d_in[0];
    const float* neis        = (const float*)d_in[1];
    const float* init_trajs  = (const float*)d_in[2];
    const float* W_self      = (const float*)d_in[3];
    const float* b_self      = (const float*)d_in[4];
    const float* W_nei       = (const float*)d_in[5];
    const float* b_nei       = (const float*)d_in[6];
    const int*   self_labels = (const int*)d_in[7];
    const int*   nei_labels  = (const int*)d_in[8];

    float* out_x   = (float*)d_out;
    float* out_nei = (float*)d_out + X_ELEMS;

    cudaFuncSetAttribute(k_gemm_mma, cudaFuncAttributeMaxDynamicSharedMemorySize, SMEM_BYTES);

    // nei_feats path (GEMM is launch #4 -> lands in the ncu capture slot)
    k_count_wprep<<<NBLK_ + WPREP_BLKS, 256>>>(nei_labels, W_nei);
    k_prefix<<<1, 256>>>();
    k_scattercopy<<<NBLK_, 256>>>(neis, nei_labels);
    k_gemm_mma<<<GEMM_GRID, 256, SMEM_BYTES>>>(b_nei, out_nei);

    // x path
    k_anchor<<<C_ * K_, 128>>>(init_trajs, W_self, b_self);
    k_x<<<B_, 128>>>(obs, W_self, self_labels, out_x);
}

// round 7
// speedup vs baseline: 1.0245x; 1.0245x over previous
#include <cuda_runtime.h>
#include <cuda_bf16.h>
#include <cstdint>

typedef unsigned long long u64;

// Problem constants
#define B_      2048
#define N_      64
#define OBS_    8
#define PRED_   12
#define IN_     6
#define E_      512
#define C_      6
#define CN_     7          // C + 1
#define K_      20
#define DSELF_  120        // IN*(OBS+PRED)
#define DNEI_   48         // IN*OBS
#define RTOT_   (B_ * N_)  // 131072
#define NBLK_   (RTOT_ / 256)   // 512
#define EPSF    1e-4f

#define KP_     144        // split-K: [hi(48) | lo(48) | hi(48)]
#define ROWB_   (KP_ * 2)  // 288 bytes per packed row
#define X_ELEMS ((size_t)B_ * K_ * E_)   // 20,971,520

// ---------------- scratch (__device__ globals; no allocation) ----------------
__device__ __nv_bfloat16 g_Ab[(size_t)RTOT_ * KP_];      // packed split-A rows (~38 MB)
__device__ __nv_bfloat16 g_Wb[(size_t)CN_ * E_ * KP_];   // split weights (~1 MB)
__device__ int   g_perm[RTOT_];
__device__ int   g_bcnt[CN_][NBLK_];
__device__ int   g_base[CN_][NBLK_];
__device__ int   g_cnt[CN_];
__device__ int   g_off[CN_];
__device__ float g_anchor[(size_t)C_ * K_ * E_];

// ---------------- kernel 1: per-block class histograms + (folded) weight split ----
__global__ void k_count_wprep(const int* __restrict__ nei_labels,
                              const float* __restrict__ W_nei) {
    if (blockIdx.x < NBLK_) {
        __shared__ int sc[CN_];
        if (threadIdx.x < CN_) sc[threadIdx.x] = 0;
        __syncthreads();
        int i = blockIdx.x * 256 + threadIdx.x;
        atomicAdd(&sc[nei_labels[i]], 1);
        __syncthreads();
        if (threadIdx.x < CN_) g_bcnt[threadIdx.x][blockIdx.x] = sc[threadIdx.x];
    } else {
        int g = (blockIdx.x - NBLK_) * 256 + threadIdx.x;   // (c, n)
        if (g >= CN_ * E_) return;
        int c = g / E_, n = g % E_;
        char* rb = (char*)g_Wb + (size_t)g * ROWB_;
        const float* W = W_nei + (size_t)c * DNEI_ * E_ + n;
#pragma unroll 8
        for (int k = 0; k < DNEI_; k++) {
            float w = W[(size_t)k * E_];
            __nv_bfloat16 h = __float2bfloat16(w);
            __nv_bfloat16 l = __float2bfloat16(w - __bfloat162float(h));
            *(__nv_bfloat16*)(rb + k * 2)       = h;   // seg0 (pairs A hi)
            *(__nv_bfloat16*)(rb + 96 + k * 2)  = h;   // seg1 (pairs A lo)
            *(__nv_bfloat16*)(rb + 192 + k * 2) = l;   // seg2 (pairs A hi)
        }
    }
}

// ---------------- kernel 2: per-class scan over blocks ----------------
__global__ void k_prefix() {
    int w    = threadIdx.x >> 5;
    int lane = threadIdx.x & 31;
    __shared__ int tot[CN_];
    if (w < CN_) {
        int acc = 0;
#pragma unroll
        for (int seg = 0; seg < NBLK_ / 32; seg++) {
            int v = g_bcnt[w][seg * 32 + lane];
            int s = v;
#pragma unroll
            for (int d = 1; d < 32; d <<= 1) {
                int t = __shfl_up_sync(0xffffffffu, s, d);
                if (lane >= d) s += t;
            }
            g_base[w][seg * 32 + lane] = acc + s - v;
            acc += __shfl_sync(0xffffffffu, s, 31);
        }
        if (lane == 0) tot[w] = acc;
    }
    __syncthreads();
    if (threadIdx.x == 0) {
        int a = 0;
        for (int c = 0; c < CN_; c++) { g_off[c] = a; g_cnt[c] = tot[c]; a += tot[c]; }
    }
}

// ---------------- kernel 3: scatter + transform + bf16 hi/lo split copy --------
__global__ void k_scattercopy(const float* __restrict__ neis,
                              const int*   __restrict__ nei_labels) {
    __shared__ int s_cur[CN_];
    __shared__ int s_pos[256];
    int tid = threadIdx.x;
    int blk = blockIdx.x;
    if (tid < CN_) s_cur[tid] = g_off[tid] + g_base[tid][blk];
    __syncthreads();

    int row = blk * 256 + tid;
    int c   = nei_labels[row];
    int pos = atomicAdd(&s_cur[c], 1);
    s_pos[tid]  = pos;
    g_perm[pos] = row;
    __syncthreads();

#pragma unroll
    for (int it = 0; it < 12; it++) {
        int idx = it * 256 + tid;
        int r = idx / 12, q = idx % 12;       // q: float4 chunk 0..11
        float4 v = *(const float4*)(neis + ((size_t)blk * 256 + r) * DNEI_ + q * 4);
        v.x = (v.x >= 0.f) ? 1.f / (v.x + EPSF) : 1.f / (v.x - EPSF);
        v.y = (v.y >= 0.f) ? 1.f / (v.y + EPSF) : 1.f / (v.y - EPSF);
        v.z = (v.z >= 0.f) ? 1.f / (v.z + EPSF) : 1.f / (v.z - EPSF);
        v.w = (v.w >= 0.f) ? 1.f / (v.w + EPSF) : 1.f / (v.w - EPSF);

        __nv_bfloat16 hx = __float2bfloat16(v.x), hy = __float2bfloat16(v.y);
        __nv_bfloat16 hz = __float2bfloat16(v.z), hw = __float2bfloat16(v.w);
        __nv_bfloat16 lx = __float2bfloat16(v.x - __bfloat162float(hx));
        __nv_bfloat16 ly = __float2bfloat16(v.y - __bfloat162float(hy));
        __nv_bfloat16 lz = __float2bfloat16(v.z - __bfloat162float(hz));
        __nv_bfloat16 lw = __float2bfloat16(v.w - __bfloat162float(hw));

        uint32_t h01 = ((uint32_t)__bfloat16_as_ushort(hy) << 16) | __bfloat16_as_ushort(hx);
        uint32_t h23 = ((uint32_t)__bfloat16_as_ushort(hw) << 16) | __bfloat16_as_ushort(hz);
        uint32_t l01 = ((uint32_t)__bfloat16_as_ushort(ly) << 16) | __bfloat16_as_ushort(lx);
        uint32_t l23 = ((uint32_t)__bfloat16_as_ushort(lw) << 16) | __bfloat16_as_ushort(lz);

        char* rb = (char*)g_Ab + (size_t)s_pos[r] * ROWB_;
        *(uint2*)(rb + q * 8)        = make_uint2(h01, h23);   // seg0: hi (k 0..47)
        *(uint2*)(rb + 96 + q * 8)   = make_uint2(l01, l23);   // seg1: lo (k 48..95)
        *(uint2*)(rb + 192 + q * 8)  = make_uint2(h01, h23);   // seg2: hi (k 96..143)
    }
}

// ================= mma.sync / cp.async helpers =================
__device__ __forceinline__ uint32_t smem_u32(const void* p) {
    uint32_t a;
    asm("{ .reg .u64 t; cvta.to.shared.u64 t, %1; cvt.u32.u64 %0, t; }" : "=r"(a) : "l"(p));
    return a;
}
__device__ __forceinline__ void cp_async16(uint32_t dst, const void* src, int src_size) {
    asm volatile("cp.async.cg.shared.global [%0], [%1], 16, %2;"
                 :: "r"(dst), "l"(src), "r"(src_size) : "memory");
}
__device__ __forceinline__ void cp_commit() {
    asm volatile("cp.async.commit_group;" ::: "memory");
}
__device__ __forceinline__ void cp_wait_all() {
    asm volatile("cp.async.wait_group 0;" ::: "memory");
}
__device__ __forceinline__ void ldsm_x4(uint32_t& r0, uint32_t& r1, uint32_t& r2, uint32_t& r3,
                                        uint32_t addr) {
    asm volatile("ldmatrix.sync.aligned.m8n8.x4.shared.b16 {%0,%1,%2,%3}, [%4];"
                 : "=r"(r0), "=r"(r1), "=r"(r2), "=r"(r3) : "r"(addr));
}
__device__ __forceinline__ void mma16816(float* c, const uint32_t* a, uint32_t b0, uint32_t b1) {
    asm volatile("mma.sync.aligned.m16n8k16.row.col.f32.bf16.bf16.f32 "
                 "{%0,%1,%2,%3}, {%4,%5,%6,%7}, {%8,%9}, {%0,%1,%2,%3};"
                 : "+f"(c[0]), "+f"(c[1]), "+f"(c[2]), "+f"(c[3])
                 : "r"(a[0]), "r"(a[1]), "r"(a[2]), "r"(a[3]), "r"(b0), "r"(b1));
}

// ---------------- kernel 4: persistent pipelined grouped GEMM (mma.sync bf16) ----
// 128x128 tile, K'=144 resident. 256 threads = 8 warps (2x4), warp = 64x32.
// Each CTA: one n-tile, JOBS_ contiguous m-tiles, double-buffered cp.async prefetch.
#define MT 128
#define NT 128
#define GEMM_MAX_MTILES ((RTOT_ / MT) + CN_)   // 1031
#define JOBS_ 7
#define GEMM_CHUNKS ((GEMM_MAX_MTILES + JOBS_ - 1) / JOBS_)  // 148
#define GEMM_GRID (GEMM_CHUNKS * 4)            // 592
#define STRIDE_B 304                           // padded row stride — LDSM conflict-free
#define TILE_B   (128 * STRIDE_B)              // 38912 bytes
#define SMEM_HDR 1024                          // s_perm(512) + s_bias(512)
#define SMEM_BYTES (SMEM_HDR + 4 * TILE_B)     // 156672

__global__ void __launch_bounds__(256, 1)
k_gemm_mma(const float* __restrict__ b_nei,
           float*       __restrict__ out_nei) {
    int nt    = blockIdx.x & 3;
    int chunk = blockIdx.x >> 2;
    int mid0  = chunk * JOBS_;

    int cnts[CN_], offs[CN_];
#pragma unroll
    for (int cc = 0; cc < CN_; cc++) { cnts[cc] = g_cnt[cc]; offs[cc] = g_off[cc]; }

    extern __shared__ char smem[];
    int*   s_perm = (int*)smem;                  // [128]
    float* s_bias = (float*)(smem + 512);        // [128]
    char*  a_smb  = smem + SMEM_HDR;             // 2 x TILE_B
    char*  b_smb  = smem + SMEM_HDR + 2 * TILE_B;// 2 x TILE_B

    int tid  = threadIdx.x;
    int lane = tid & 31;
    int wid  = tid >> 5;
    int wm   = wid & 1;          // 2 warp rows (64 rows each)
    int wn   = wid >> 1;         // 4 warp cols (32 cols each)

    // per-thread cp.async geometry: row tid>>1, 16B chunks h..h+8
    int pr = tid >> 1;
    int ph = (tid & 1) * 9;

    // job -> (class, m-tile) mapping
    auto map_job = [&](int mid, int& c, int& mt) -> bool {
        int acc = 0;
#pragma unroll
        for (int cc = 0; cc < CN_; cc++) {
            int t = (cnts[cc] + MT - 1) >> 7;
            if (mid < acc + t) { c = cc; mt = mid - acc; return true; }
            acc += t;
        }
        return false;
    };

    auto prefetch_A = [&](int buf, int c, int mt) {
        int m0  = mt * MT;
        int ok  = (m0 + pr < cnts[c]) ? 16 : 0;
        const char* src = (const char*)g_Ab
                        + (size_t)(ok ? (offs[c] + m0 + pr) : 0) * ROWB_;
        uint32_t dst = smem_u32(a_smb + buf * TILE_B)
                     + (uint32_t)pr * STRIDE_B + (uint32_t)ph * 16;
#pragma unroll
        for (int i = 0; i < 9; i++)
            cp_async16(dst + i * 16, src + (ph + i) * 16, ok);
    };
    auto prefetch_B = [&](int buf, int c) {
        const char* src = (const char*)g_Wb
                        + ((size_t)c * E_ + nt * NT + pr) * ROWB_;
        uint32_t dst = smem_u32(b_smb + buf * TILE_B)
                     + (uint32_t)pr * STRIDE_B + (uint32_t)ph * 16;
#pragma unroll
        for (int i = 0; i < 9; i++)
            cp_async16(dst + i * 16, src + (ph + i) * 16, 16);
    };

    // prologue: fetch job 0
    int c0, mt0;
    if (!map_job(mid0, c0, mt0)) return;
    prefetch_A(0, c0, mt0);
    prefetch_B(0, c0);
    cp_commit();

    int cur = 0, bcur = 0;

    for (int j = 0; j < JOBS_; j++) {
        int mid = mid0 + j;
        int c, mt;
        if (!map_job(mid, c, mt)) break;

        cp_wait_all();          // job j data ready
        __syncthreads();        // all warps done with j-1 compute/epilogue

        // prefetch job j+1 into alternate buffers (overlaps compute of j)
        int bnext = bcur;
        if (j + 1 < JOBS_) {
            int cn, mtn;
            if (map_job(mid + 1, cn, mtn)) {
                prefetch_A(cur ^ 1, cn, mtn);
                if (cn != c) { bnext = bcur ^ 1; prefetch_B(bnext, cn); }
                cp_commit();
            }
        }

        // stage perm + bias for job j
        if (tid < 128) {
            int r = mt * MT + tid;
            s_perm[tid] = (r < cnts[c]) ? g_perm[offs[c] + r] : -1;
            s_bias[tid] = b_nei[(size_t)c * E_ + nt * NT + tid];
        }
        __syncthreads();

        // ---- compute ----
        uint32_t a_u32 = smem_u32(a_smb + cur  * TILE_B);
        uint32_t b_u32 = smem_u32(b_smb + bcur * TILE_B);
        uint32_t a_base = a_u32 + (uint32_t)(wm * 64 + (lane & 15)) * STRIDE_B
                                + ((lane >> 4) << 4);
        uint32_t b_base = b_u32 + (uint32_t)(wn * 32 + ((lane >> 4) << 3) + (lane & 7)) * STRIDE_B
                                + (((lane >> 3) & 1) << 4);

        float acc[4][4][4];
#pragma unroll
        for (int i = 0; i < 4; i++)
#pragma unroll
            for (int jj = 0; jj < 4; jj++)
#pragma unroll
                for (int q = 0; q < 4; q++) acc[i][jj][q] = 0.f;

#pragma unroll
        for (int kc = 0; kc < 9; kc++) {       // K' = 144 = 9 x 16
            uint32_t kb = kc * 32;
            uint32_t B0[4], B1[4];
            ldsm_x4(B0[0], B0[1], B0[2], B0[3], b_base + kb);                 // ntiles 0,1
            ldsm_x4(B1[0], B1[1], B1[2], B1[3], b_base + 16 * STRIDE_B + kb); // ntiles 2,3
#pragma unroll
            for (int mi = 0; mi < 4; mi++) {
                uint32_t A[4];
                ldsm_x4(A[0], A[1], A[2], A[3], a_base + (uint32_t)mi * 16 * STRIDE_B + kb);
                mma16816(acc[mi][0], A, B0[0], B0[1]);
                mma16816(acc[mi][1], A, B0[2], B0[3]);
                mma16816(acc[mi][2], A, B1[0], B1[1]);
                mma16816(acc[mi][3], A, B1[2], B1[3]);
            }
        }

        // ---- epilogue ----
        int g = lane >> 2, t4 = lane & 3;
#pragma unroll
        for (int mi = 0; mi < 4; mi++) {
#pragma unroll
            for (int half = 0; half < 2; half++) {
                int rloc = wm * 64 + mi * 16 + g + half * 8;
                int rg   = s_perm[rloc];
                if (rg >= 0) {
                    float* orow = out_nei + (size_t)rg * E_ + nt * NT + wn * 32;
#pragma unroll
                    for (int ni = 0; ni < 4; ni++) {
                        int colo = ni * 8 + t4 * 2;
                        float2 v = make_float2(
                            acc[mi][ni][half * 2 + 0] + s_bias[wn * 32 + colo],
                            acc[mi][ni][half * 2 + 1] + s_bias[wn * 32 + colo + 1]);
                        *(float2*)(orow + colo) = v;
                    }
                }
            }
        }

        cur ^= 1;
        bcur = bnext;
    }
}

// ---------------- kernel 5: anchor ----------------
__global__ void k_anchor(const float* __restrict__ init_trajs,
                         const float* __restrict__ W_self,
                         const float* __restrict__ b_self) {
    int c  = blockIdx.x / K_;
    int kk = blockIdx.x % K_;
    __shared__ float tr[PRED_ * IN_];
    if (threadIdx.x < PRED_ * IN_)
        tr[threadIdx.x] = init_trajs[((size_t)c * K_ + kk) * (PRED_ * IN_) + threadIdx.x];
    __syncthreads();

    int col = threadIdx.x * 4;
    const float* bb = b_self + (size_t)c * E_ + col;
    float4 acc = *(const float4*)bb;
    const float* W = W_self + ((size_t)c * DSELF_ + DNEI_) * E_ + col;
#pragma unroll 8
    for (int j = 0; j < PRED_ * IN_; j++) {
        float  t = tr[j];
        float4 w = *(const float4*)(W + (size_t)j * E_);
        acc.x += t * w.x; acc.y += t * w.y; acc.z += t * w.z; acc.w += t * w.w;
    }
    *(float4*)(g_anchor + ((size_t)c * K_ + kk) * E_ + col) = acc;
}

// ---------------- kernel 6: x path ----------------
__global__ void k_x(const float* __restrict__ obs,
                    const float* __restrict__ W_self,
                    const int*   __restrict__ self_labels,
                    float*       __restrict__ out_x) {
    int b = blockIdx.x;
    __shared__ float ob[DNEI_];
    if (threadIdx.x < DNEI_)
        ob[threadIdx.x] = obs[(size_t)b * DNEI_ + threadIdx.x];
    __syncthreads();

    int c   = self_labels[b];
    int col = threadIdx.x * 4;
    const float* W = W_self + (size_t)c * DSELF_ * E_ + col;
    float4 acc = make_float4(0.f, 0.f, 0.f, 0.f);
#pragma unroll 8
    for (int j = 0; j < DNEI_; j++) {
        float  t = ob[j];
        float4 w = *(const float4*)(W + (size_t)j * E_);
        acc.x += t * w.x; acc.y += t * w.y; acc.z += t * w.z; acc.w += t * w.w;
    }
#pragma unroll
    for (int kk = 0; kk < K_; kk++) {
        float4 an = *(const float4*)(g_anchor + ((size_t)c * K_ + kk) * E_ + col);
        float4 v  = make_float4(acc.x + an.x, acc.y + an.y, acc.z + an.z, acc.w + an.w);
        *(float4*)(out_x + ((size_t)b * K_ + kk) * E_ + col) = v;
    }
}

// ---------------- launcher ----------------
#define WPREP_BLKS ((CN_ * E_ + 255) / 256)    // 14

extern "C" void kernel_launch(void* const* d_in, const int* in_sizes, int n_in,
                              void* d_out, int out_size) {
    const float* obs         = (const float*)d_in[0];
    const float* neis        = (const float*)d_in[1];
    const float* init_trajs  = (const float*)d_in[2];
    const float* W_self      = (const float*)d_in[3];
    const float* b_self      = (const float*)d_in[4];
    const float* W_nei       = (const float*)d_in[5];
    const float* b_nei       = (const float*)d_in[6];
    const int*   self_labels = (const int*)d_in[7];
    const int*   nei_labels  = (const int*)d_in[8];

    float* out_x   = (float*)d_out;
    float* out_nei = (float*)d_out + X_ELEMS;

    cudaFuncSetAttribute(k_gemm_mma, cudaFuncAttributeMaxDynamicSharedMemorySize, SMEM_BYTES);

    // nei_feats path (GEMM is launch #4 -> lands in the ncu capture slot)
    k_count_wprep<<<NBLK_ + WPREP_BLKS, 256>>>(nei_labels, W_nei);
    k_prefix<<<1, 256>>>();
    k_scattercopy<<<NBLK_, 256>>>(neis, nei_labels);
    k_gemm_mma<<<GEMM_GRID, 256, SMEM_BYTES>>>(b_nei, out_nei);

    // x path
    k_anchor<<<C_ * K_, 128>>>(init_trajs, W_self, b_self);
    k_x<<<B_, 128>>>(obs, W_self, self_labels, out_x);
}

// round 8
// speedup vs baseline: 1.0843x; 1.0583x over previous
#include <cuda_runtime.h>
#include <cuda_bf16.h>
#include <cstdint>

typedef unsigned long long u64;

// Problem constants
#define B_      2048
#define N_      64
#define OBS_    8
#define PRED_   12
#define IN_     6
#define E_      512
#define C_      6
#define CN_     7          // C + 1
#define K_      20
#define DSELF_  120        // IN*(OBS+PRED)
#define DNEI_   48         // IN*OBS
#define RTOT_   (B_ * N_)  // 131072
#define NBLK_   (RTOT_ / 256)   // 512
#define EPSF    1e-4f

#define KP_     144        // split-K: [hi(48) | lo(48) | hi(48)]
#define ROWB_   (KP_ * 2)  // 288 bytes per packed row
#define X_ELEMS ((size_t)B_ * K_ * E_)   // 20,971,520

// ---------------- scratch (__device__ globals; no allocation) ----------------
__device__ __nv_bfloat16 g_Ab[(size_t)RTOT_ * KP_];      // packed split-A rows (~38 MB)
__device__ __nv_bfloat16 g_Wb[(size_t)CN_ * E_ * KP_];   // split weights (~1 MB)
__device__ int   g_perm[RTOT_];
__device__ int   g_bcnt[CN_][NBLK_];
__device__ int   g_base[CN_][NBLK_];
__device__ int   g_cnt[CN_];
__device__ int   g_off[CN_];
__device__ float g_anchor[(size_t)C_ * K_ * E_];
// x-path binning
__device__ int   g_xperm[B_];
__device__ int   g_xcnt[C_];
__device__ int   g_xoff[C_];

// ---------------- kernel 1: per-block class histograms + (folded) weight split ----
__global__ void k_count_wprep(const int* __restrict__ nei_labels,
                              const float* __restrict__ W_nei) {
    if (blockIdx.x < NBLK_) {
        __shared__ int sc[CN_];
        if (threadIdx.x < CN_) sc[threadIdx.x] = 0;
        __syncthreads();
        int i = blockIdx.x * 256 + threadIdx.x;
        atomicAdd(&sc[nei_labels[i]], 1);
        __syncthreads();
        if (threadIdx.x < CN_) g_bcnt[threadIdx.x][blockIdx.x] = sc[threadIdx.x];
    } else {
        int g = (blockIdx.x - NBLK_) * 256 + threadIdx.x;   // (c, n)
        if (g >= CN_ * E_) return;
        int c = g / E_, n = g % E_;
        char* rb = (char*)g_Wb + (size_t)g * ROWB_;
        const float* W = W_nei + (size_t)c * DNEI_ * E_ + n;
#pragma unroll 8
        for (int k = 0; k < DNEI_; k++) {
            float w = W[(size_t)k * E_];
            __nv_bfloat16 h = __float2bfloat16(w);
            __nv_bfloat16 l = __float2bfloat16(w - __bfloat162float(h));
            *(__nv_bfloat16*)(rb + k * 2)       = h;   // seg0 (pairs A hi)
            *(__nv_bfloat16*)(rb + 96 + k * 2)  = h;   // seg1 (pairs A lo)
            *(__nv_bfloat16*)(rb + 192 + k * 2) = l;   // seg2 (pairs A hi)
        }
    }
}

// ---------------- kernel 2: per-class scan over blocks ----------------
__global__ void k_prefix() {
    int w    = threadIdx.x >> 5;
    int lane = threadIdx.x & 31;
    __shared__ int tot[CN_];
    if (w < CN_) {
        int acc = 0;
#pragma unroll
        for (int seg = 0; seg < NBLK_ / 32; seg++) {
            int v = g_bcnt[w][seg * 32 + lane];
            int s = v;
#pragma unroll
            for (int d = 1; d < 32; d <<= 1) {
                int t = __shfl_up_sync(0xffffffffu, s, d);
                if (lane >= d) s += t;
            }
            g_base[w][seg * 32 + lane] = acc + s - v;
            acc += __shfl_sync(0xffffffffu, s, 31);
        }
        if (lane == 0) tot[w] = acc;
    }
    __syncthreads();
    if (threadIdx.x == 0) {
        int a = 0;
        for (int c = 0; c < CN_; c++) { g_off[c] = a; g_cnt[c] = tot[c]; a += tot[c]; }
    }
}

// ---------------- kernel 3: scatter + transform + bf16 hi/lo split copy --------
__global__ void k_scattercopy(const float* __restrict__ neis,
                              const int*   __restrict__ nei_labels) {
    __shared__ int s_cur[CN_];
    __shared__ int s_pos[256];
    int tid = threadIdx.x;
    int blk = blockIdx.x;
    if (tid < CN_) s_cur[tid] = g_off[tid] + g_base[tid][blk];
    __syncthreads();

    int row = blk * 256 + tid;
    int c   = nei_labels[row];
    int pos = atomicAdd(&s_cur[c], 1);
    s_pos[tid]  = pos;
    g_perm[pos] = row;
    __syncthreads();

#pragma unroll
    for (int it = 0; it < 12; it++) {
        int idx = it * 256 + tid;
        int r = idx / 12, q = idx % 12;       // q: float4 chunk 0..11
        float4 v = *(const float4*)(neis + ((size_t)blk * 256 + r) * DNEI_ + q * 4);
        v.x = (v.x >= 0.f) ? 1.f / (v.x + EPSF) : 1.f / (v.x - EPSF);
        v.y = (v.y >= 0.f) ? 1.f / (v.y + EPSF) : 1.f / (v.y - EPSF);
        v.z = (v.z >= 0.f) ? 1.f / (v.z + EPSF) : 1.f / (v.z - EPSF);
        v.w = (v.w >= 0.f) ? 1.f / (v.w + EPSF) : 1.f / (v.w - EPSF);

        __nv_bfloat16 hx = __float2bfloat16(v.x), hy = __float2bfloat16(v.y);
        __nv_bfloat16 hz = __float2bfloat16(v.z), hw = __float2bfloat16(v.w);
        __nv_bfloat16 lx = __float2bfloat16(v.x - __bfloat162float(hx));
        __nv_bfloat16 ly = __float2bfloat16(v.y - __bfloat162float(hy));
        __nv_bfloat16 lz = __float2bfloat16(v.z - __bfloat162float(hz));
        __nv_bfloat16 lw = __float2bfloat16(v.w - __bfloat162float(hw));

        uint32_t h01 = ((uint32_t)__bfloat16_as_ushort(hy) << 16) | __bfloat16_as_ushort(hx);
        uint32_t h23 = ((uint32_t)__bfloat16_as_ushort(hw) << 16) | __bfloat16_as_ushort(hz);
        uint32_t l01 = ((uint32_t)__bfloat16_as_ushort(ly) << 16) | __bfloat16_as_ushort(lx);
        uint32_t l23 = ((uint32_t)__bfloat16_as_ushort(lw) << 16) | __bfloat16_as_ushort(lz);

        char* rb = (char*)g_Ab + (size_t)s_pos[r] * ROWB_;
        *(uint2*)(rb + q * 8)        = make_uint2(h01, h23);   // seg0: hi (k 0..47)
        *(uint2*)(rb + 96 + q * 8)   = make_uint2(l01, l23);   // seg1: lo (k 48..95)
        *(uint2*)(rb + 192 + q * 8)  = make_uint2(h01, h23);   // seg2: hi (k 96..143)
    }
}

// ================= mma.sync / cp.async helpers =================
__device__ __forceinline__ uint32_t smem_u32(const void* p) {
    uint32_t a;
    asm("{ .reg .u64 t; cvta.to.shared.u64 t, %1; cvt.u32.u64 %0, t; }" : "=r"(a) : "l"(p));
    return a;
}
__device__ __forceinline__ void cp_async16(uint32_t dst, const void* src, int src_size) {
    asm volatile("cp.async.cg.shared.global [%0], [%1], 16, %2;"
                 :: "r"(dst), "l"(src), "r"(src_size) : "memory");
}
__device__ __forceinline__ void cp_commit() {
    asm volatile("cp.async.commit_group;" ::: "memory");
}
__device__ __forceinline__ void cp_wait_all() {
    asm volatile("cp.async.wait_group 0;" ::: "memory");
}
__device__ __forceinline__ void ldsm_x4(uint32_t& r0, uint32_t& r1, uint32_t& r2, uint32_t& r3,
                                        uint32_t addr) {
    asm volatile("ldmatrix.sync.aligned.m8n8.x4.shared.b16 {%0,%1,%2,%3}, [%4];"
                 : "=r"(r0), "=r"(r1), "=r"(r2), "=r"(r3) : "r"(addr));
}
__device__ __forceinline__ void mma16816(float* c, const uint32_t* a, uint32_t b0, uint32_t b1) {
    asm volatile("mma.sync.aligned.m16n8k16.row.col.f32.bf16.bf16.f32 "
                 "{%0,%1,%2,%3}, {%4,%5,%6,%7}, {%8,%9}, {%0,%1,%2,%3};"
                 : "+f"(c[0]), "+f"(c[1]), "+f"(c[2]), "+f"(c[3])
                 : "r"(a[0]), "r"(a[1]), "r"(a[2]), "r"(a[3]), "r"(b0), "r"(b1));
}

// ---------------- kernel 4: persistent pipelined grouped GEMM (mma.sync bf16) ----
// 128x128 tile, K'=144 resident. 256 threads = 8 warps (2x4), warp = 64x32.
// occ 2 (regs capped at 128, smem 115712 <= 114KB). A double-buffered (stride 304,
// conflict-free), B single-buffered (stride 288, reload on class change only).
#define MT 128
#define NT 128
#define GEMM_MAX_MTILES ((RTOT_ / MT) + CN_)   // 1031
#define JOBS_ 14
#define GEMM_CHUNKS ((GEMM_MAX_MTILES + JOBS_ - 1) / JOBS_)  // 74
#define GEMM_GRID (GEMM_CHUNKS * 4)            // 296 = 148 SMs x occ 2
#define STRIDE_A 304                           // conflict-free LDSM stride
#define STRIDE_BB 288                          // compact stride (2-way LDSM conflict, B only)
#define TILE_A   (128 * STRIDE_A)              // 38912
#define TILE_BB  (128 * STRIDE_BB)             // 36864
#define SMEM_HDR 1024                          // s_perm(512) + s_bias(512)
#define SMEM_BYTES (SMEM_HDR + 2 * TILE_A + TILE_BB)   // 115712

__global__ void __launch_bounds__(256, 2)
k_gemm_mma(const float* __restrict__ b_nei,
           float*       __restrict__ out_nei) {
    int nt    = blockIdx.x & 3;
    int chunk = blockIdx.x >> 2;
    int mid0  = chunk * JOBS_;

    int cnts[CN_], offs[CN_];
#pragma unroll
    for (int cc = 0; cc < CN_; cc++) { cnts[cc] = g_cnt[cc]; offs[cc] = g_off[cc]; }

    extern __shared__ char smem[];
    int*   s_perm = (int*)smem;                  // [128]
    float* s_bias = (float*)(smem + 512);        // [128]
    char*  a_smb  = smem + SMEM_HDR;             // 2 x TILE_A
    char*  b_sm   = smem + SMEM_HDR + 2 * TILE_A;// 1 x TILE_BB

    int tid  = threadIdx.x;
    int lane = tid & 31;
    int wid  = tid >> 5;
    int wm   = wid & 1;          // 2 warp rows (64 rows each)
    int wn   = wid >> 1;         // 4 warp cols (32 cols each)

    // per-thread cp.async geometry: row tid>>1, 16B chunks h..h+8
    int pr = tid >> 1;
    int ph = (tid & 1) * 9;

    auto map_job = [&](int mid, int& c, int& mt) -> bool {
        int acc = 0;
#pragma unroll
        for (int cc = 0; cc < CN_; cc++) {
            int t = (cnts[cc] + MT - 1) >> 7;
            if (mid < acc + t) { c = cc; mt = mid - acc; return true; }
            acc += t;
        }
        return false;
    };

    auto prefetch_A = [&](int buf, int c, int mt) {
        int m0  = mt * MT;
        int ok  = (m0 + pr < cnts[c]) ? 16 : 0;
        const char* src = (const char*)g_Ab
                        + (size_t)(ok ? (offs[c] + m0 + pr) : 0) * ROWB_;
        uint32_t dst = smem_u32(a_smb + buf * TILE_A)
                     + (uint32_t)pr * STRIDE_A + (uint32_t)ph * 16;
#pragma unroll
        for (int i = 0; i < 9; i++)
            cp_async16(dst + i * 16, src + (ph + i) * 16, ok);
    };
    auto prefetch_B = [&](int c) {
        const char* src = (const char*)g_Wb
                        + ((size_t)c * E_ + nt * NT + pr) * ROWB_;
        uint32_t dst = smem_u32(b_sm)
                     + (uint32_t)pr * STRIDE_BB + (uint32_t)ph * 16;
#pragma unroll
        for (int i = 0; i < 9; i++)
            cp_async16(dst + i * 16, src + (ph + i) * 16, 16);
    };

    // prologue: fetch job 0's A
    int c0, mt0;
    if (!map_job(mid0, c0, mt0)) return;
    prefetch_A(0, c0, mt0);
    cp_commit();

    int cur = 0, bclass = -1;

    for (int j = 0; j < JOBS_; j++) {
        int mid = mid0 + j;
        int c, mt;
        if (!map_job(mid, c, mt)) break;

        cp_wait_all();          // job j A (and any pending) ready
        __syncthreads();        // all warps done with j-1 compute/epilogue

        // B reload on class change (rare; exposed but cheap)
        if (c != bclass) {
            prefetch_B(c);
            cp_commit();
            cp_wait_all();
            bclass = c;
        }

        // prefetch job j+1's A into alternate buffer (overlaps compute of j)
        if (j + 1 < JOBS_) {
            int cn, mtn;
            if (map_job(mid + 1, cn, mtn)) {
                prefetch_A(cur ^ 1, cn, mtn);
                cp_commit();
            }
        }

        // stage perm + bias for job j
        if (tid < 128) {
            int r = mt * MT + tid;
            s_perm[tid] = (r < cnts[c]) ? g_perm[offs[c] + r] : -1;
            s_bias[tid] = b_nei[(size_t)c * E_ + nt * NT + tid];
        }
        __syncthreads();

        // ---- compute ----
        uint32_t a_u32 = smem_u32(a_smb + cur * TILE_A);
        uint32_t b_u32 = smem_u32(b_sm);
        uint32_t a_base = a_u32 + (uint32_t)(wm * 64 + (lane & 15)) * STRIDE_A
                                + ((lane >> 4) << 4);
        uint32_t b_base = b_u32 + (uint32_t)(wn * 32 + ((lane >> 4) << 3) + (lane & 7)) * STRIDE_BB
                                + (((lane >> 3) & 1) << 4);

        float acc[4][4][4];
#pragma unroll
        for (int i = 0; i < 4; i++)
#pragma unroll
            for (int jj = 0; jj < 4; jj++)
#pragma unroll
                for (int q = 0; q < 4; q++) acc[i][jj][q] = 0.f;

#pragma unroll
        for (int kc = 0; kc < 9; kc++) {       // K' = 144 = 9 x 16
            uint32_t kb = kc * 32;
            uint32_t B0[4], B1[4];
            ldsm_x4(B0[0], B0[1], B0[2], B0[3], b_base + kb);                  // ntiles 0,1
            ldsm_x4(B1[0], B1[1], B1[2], B1[3], b_base + 16 * STRIDE_BB + kb); // ntiles 2,3
#pragma unroll
            for (int mi = 0; mi < 4; mi++) {
                uint32_t A[4];
                ldsm_x4(A[0], A[1], A[2], A[3], a_base + (uint32_t)mi * 16 * STRIDE_A + kb);
                mma16816(acc[mi][0], A, B0[0], B0[1]);
                mma16816(acc[mi][1], A, B0[2], B0[3]);
                mma16816(acc[mi][2], A, B1[0], B1[1]);
                mma16816(acc[mi][3], A, B1[2], B1[3]);
            }
        }

        // ---- epilogue ----
        int g = lane >> 2, t4 = lane & 3;
#pragma unroll
        for (int mi = 0; mi < 4; mi++) {
#pragma unroll
            for (int half = 0; half < 2; half++) {
                int rloc = wm * 64 + mi * 16 + g + half * 8;
                int rg   = s_perm[rloc];
                if (rg >= 0) {
                    float* orow = out_nei + (size_t)rg * E_ + nt * NT + wn * 32;
#pragma unroll
                    for (int ni = 0; ni < 4; ni++) {
                        int colo = ni * 8 + t4 * 2;
                        float2 v = make_float2(
                            acc[mi][ni][half * 2 + 0] + s_bias[wn * 32 + colo],
                            acc[mi][ni][half * 2 + 1] + s_bias[wn * 32 + colo + 1]);
                        *(float2*)(orow + colo) = v;
                    }
                }
            }
        }

        cur ^= 1;
    }
}

// ---------------- kernel 5: anchor ----------------
__global__ void k_anchor(const float* __restrict__ init_trajs,
                         const float* __restrict__ W_self,
                         const float* __restrict__ b_self) {
    int c  = blockIdx.x / K_;
    int kk = blockIdx.x % K_;
    __shared__ float tr[PRED_ * IN_];
    if (threadIdx.x < PRED_ * IN_)
        tr[threadIdx.x] = init_trajs[((size_t)c * K_ + kk) * (PRED_ * IN_) + threadIdx.x];
    __syncthreads();

    int col = threadIdx.x * 4;
    const float* bb = b_self + (size_t)c * E_ + col;
    float4 acc = *(const float4*)bb;
    const float* W = W_self + ((size_t)c * DSELF_ + DNEI_) * E_ + col;
#pragma unroll 8
    for (int j = 0; j < PRED_ * IN_; j++) {
        float  t = tr[j];
        float4 w = *(const float4*)(W + (size_t)j * E_);
        acc.x += t * w.x; acc.y += t * w.y; acc.z += t * w.z; acc.w += t * w.w;
    }
    *(float4*)(g_anchor + ((size_t)c * K_ + kk) * E_ + col) = acc;
}

// ---------------- kernel 6: bin self_labels (single block, deterministic) --------
__global__ void k_xbin(const int* __restrict__ self_labels) {
    __shared__ int sc[C_][256];
    __shared__ int s_tot[C_];
    __shared__ int s_off[C_];
    int tid = threadIdx.x;
    int base = tid * 8;                       // 256 threads x 8 labels = 2048

#pragma unroll
    for (int c = 0; c < C_; c++) {
        int n = 0;
#pragma unroll
        for (int i = 0; i < 8; i++) n += (self_labels[base + i] == c);
        sc[c][tid] = n;
    }
    __syncthreads();

    // warps 0..5: exclusive scan of sc[w][0..255]
    int w = tid >> 5, lane = tid & 31;
    if (w < C_) {
        int acc = 0;
#pragma unroll
        for (int seg = 0; seg < 8; seg++) {
            int v = sc[w][seg * 32 + lane];
            int s = v;
#pragma unroll
            for (int d = 1; d < 32; d <<= 1) {
                int t = __shfl_up_sync(0xffffffffu, s, d);
                if (lane >= d) s += t;
            }
            sc[w][seg * 32 + lane] = acc + s - v;
            acc += __shfl_sync(0xffffffffu, s, 31);
        }
        if (lane == 0) s_tot[w] = acc;
    }
    __syncthreads();
    if (tid == 0) {
        int a = 0;
        for (int c = 0; c < C_; c++) {
            s_off[c] = a; g_xoff[c] = a; g_xcnt[c] = s_tot[c]; a += s_tot[c];
        }
    }
    __syncthreads();

#pragma unroll
    for (int c = 0; c < C_; c++) {
        int p = s_off[c] + sc[c][tid];
#pragma unroll
        for (int i = 0; i < 8; i++)
            if (self_labels[base + i] == c) g_xperm[p++] = base + i;
    }
}

// ---------------- kernel 7: x path, 8 same-class samples per block --------------
#define XGRP 8
#define X2_GRID (B_ / XGRP + C_)     // 262

__global__ void __launch_bounds__(128)
k_x2(const float* __restrict__ obs,
     const float* __restrict__ W_self,
     float*       __restrict__ out_x) {
    // map block -> (class, group)
    int mid = blockIdx.x;
    int c = -1, gt = 0, acc_t = 0;
#pragma unroll
    for (int cc = 0; cc < C_; cc++) {
        int t = (g_xcnt[cc] + XGRP - 1) / XGRP;
        if (c < 0 && mid < acc_t + t) { c = cc; gt = mid - acc_t; }
        acc_t += t;
    }
    if (c < 0) return;
    int cnt = g_xcnt[c];
    int xo  = g_xoff[c];
    int s0  = gt * XGRP;
    int m   = min(XGRP, cnt - s0);

    __shared__ int   s_rows[XGRP];
    __shared__ float s_obs[XGRP][DNEI_];
    int tid = threadIdx.x;

    if (tid < XGRP)
        s_rows[tid] = (tid < m) ? g_xperm[xo + s0 + tid] : -1;
    __syncthreads();
    // load obs rows: 8 x 12 float4 = 96 float4
    if (tid < 96) {
        int s = tid / 12, q = tid % 12;
        int rb = s_rows[s];
        float4 v = make_float4(0.f, 0.f, 0.f, 0.f);
        if (rb >= 0) v = *(const float4*)(obs + (size_t)rb * DNEI_ + q * 4);
        *(float4*)(&s_obs[s][q * 4]) = v;
    }
    __syncthreads();

    int col = tid * 4;          // 128 threads x 4 cols
    const float* W = W_self + (size_t)c * DSELF_ * E_ + col;
    float4 a0 = make_float4(0,0,0,0), a1 = a0, a2 = a0, a3 = a0;
    float4 a4 = a0, a5 = a0, a6 = a0, a7 = a0;
#pragma unroll 4
    for (int j = 0; j < DNEI_; j++) {
        float4 w4 = *(const float4*)(W + (size_t)j * E_);
        float t0 = s_obs[0][j], t1 = s_obs[1][j], t2 = s_obs[2][j], t3 = s_obs[3][j];
        float t4 = s_obs[4][j], t5 = s_obs[5][j], t6 = s_obs[6][j], t7 = s_obs[7][j];
        a0.x += t0*w4.x; a0.y += t0*w4.y; a0.z += t0*w4.z; a0.w += t0*w4.w;
        a1.x += t1*w4.x; a1.y += t1*w4.y; a1.z += t1*w4.z; a1.w += t1*w4.w;
        a2.x += t2*w4.x; a2.y += t2*w4.y; a2.z += t2*w4.z; a2.w += t2*w4.w;
        a3.x += t3*w4.x; a3.y += t3*w4.y; a3.z += t3*w4.z; a3.w += t3*w4.w;
        a4.x += t4*w4.x; a4.y += t4*w4.y; a4.z += t4*w4.z; a4.w += t4*w4.w;
        a5.x += t5*w4.x; a5.y += t5*w4.y; a5.z += t5*w4.z; a5.w += t5*w4.w;
        a6.x += t6*w4.x; a6.y += t6*w4.y; a6.z += t6*w4.z; a6.w += t6*w4.w;
        a7.x += t7*w4.x; a7.y += t7*w4.y; a7.z += t7*w4.z; a7.w += t7*w4.w;
    }

    float4 av[XGRP] = {a0, a1, a2, a3, a4, a5, a6, a7};
#pragma unroll
    for (int kk = 0; kk < K_; kk++) {
        float4 an = *(const float4*)(g_anchor + ((size_t)c * K_ + kk) * E_ + col);
#pragma unroll
        for (int s = 0; s < XGRP; s++) {
            int rb = s_rows[s];
            if (rb >= 0) {
                float4 v = make_float4(av[s].x + an.x, av[s].y + an.y,
                                       av[s].z + an.z, av[s].w + an.w);
                *(float4*)(out_x + ((size_t)rb * K_ + kk) * E_ + col) = v;
            }
        }
    }
}

// ---------------- launcher ----------------
#define WPREP_BLKS ((CN_ * E_ + 255) / 256)    // 14

extern "C" void kernel_launch(void* const* d_in, const int* in_sizes, int n_in,
                              void* d_out, int out_size) {
    const float* obs         = (const float*)d_in[0];
    const float* neis        = (const float*)d_in[1];
    const float* init_trajs  = (const float*)d_in[2];
    const float* W_self      = (const float*)d_in[3];
    const float* b_self      = (const float*)d_in[4];
    const float* W_nei       = (const float*)d_in[5];
    const float* b_nei       = (const float*)d_in[6];
    const int*   self_labels = (const int*)d_in[7];
    const int*   nei_labels  = (const int*)d_in[8];

    float* out_x   = (float*)d_out;
    float* out_nei = (float*)d_out + X_ELEMS;

    cudaFuncSetAttribute(k_gemm_mma, cudaFuncAttributeMaxDynamicSharedMemorySize, SMEM_BYTES);

    // nei_feats path (GEMM is launch #4 -> lands in the ncu capture slot)
    k_count_wprep<<<NBLK_ + WPREP_BLKS, 256>>>(nei_labels, W_nei);
    k_prefix<<<1, 256>>>();
    k_scattercopy<<<NBLK_, 256>>>(neis, nei_labels);
    k_gemm_mma<<<GEMM_GRID, 256, SMEM_BYTES>>>(b_nei, out_nei);

    // x path
    k_anchor<<<C_ * K_, 128>>>(init_trajs, W_self, b_self);
    k_xbin<<<1, 256>>>(self_labels);
    k_x2<<<X2_GRID, 128>>>(obs, W_self, out_x);
}

// round 11
// speedup vs baseline: 1.5329x; 1.4138x over previous
#include <cuda_runtime.h>
#include <cuda_bf16.h>
#include <cstdint>

typedef unsigned long long u64;

// Problem constants
#define B_      2048
#define N_      64
#define OBS_    8
#define PRED_   12
#define IN_     6
#define E_      512
#define C_      6
#define CN_     7          // C + 1
#define K_      20
#define DSELF_  120        // IN*(OBS+PRED)
#define DNEI_   48         // IN*OBS
#define RTOT_   (B_ * N_)  // 131072
#define NBLK_   (RTOT_ / 256)   // 512
#define EPSF    1e-4f

#define KP2_    96         // packed row: [hi(48) | lo(48)] bf16
#define ROW2_   (KP2_ * 2) // 192 bytes per packed row
#define RPAD_   (RTOT_ + CN_ * 128)   // class-aligned padding slack
#define X_ELEMS ((size_t)B_ * K_ * E_)   // 20,971,520

// ---------------- scratch (__device__ globals; no allocation) ----------------
// 256B alignment: required for 16B cp.async sources.
__device__ __align__(256) __nv_bfloat16 g_Ab[(size_t)RPAD_ * KP2_];
__device__ __align__(256) __nv_bfloat16 g_Wb[(size_t)CN_ * E_ * KP2_];
__device__ __align__(256) int   g_perm[RPAD_ + 128];
__device__ __align__(256) int   g_bcnt[CN_][NBLK_];
__device__ __align__(256) int   g_base[CN_][NBLK_];
__device__ __align__(256) int   g_cnt[CN_];
__device__ __align__(256) int   g_off[CN_];    // class starts, padded to 128 rows
__device__ __align__(256) float g_anchor[(size_t)C_ * K_ * E_];
// x-path binning
__device__ __align__(256) int   g_xperm[B_];
__device__ __align__(256) int   g_xcnt[C_];
__device__ __align__(256) int   g_xoff[C_];

// ---------------- kernel 1: per-block class histograms + (folded) weight split ----
__global__ void k_count_wprep(const int* __restrict__ nei_labels,
                              const float* __restrict__ W_nei) {
    if (blockIdx.x < NBLK_) {
        __shared__ int sc[CN_];
        if (threadIdx.x < CN_) sc[threadIdx.x] = 0;
        __syncthreads();
        int i = blockIdx.x * 256 + threadIdx.x;
        atomicAdd(&sc[nei_labels[i]], 1);
        __syncthreads();
        if (threadIdx.x < CN_) g_bcnt[threadIdx.x][blockIdx.x] = sc[threadIdx.x];
    } else {
        int g = (blockIdx.x - NBLK_) * 256 + threadIdx.x;   // (c, n)
        if (g >= CN_ * E_) return;
        int c = g / E_, n = g % E_;
        char* rb = (char*)g_Wb + (size_t)g * ROW2_;
        const float* W = W_nei + (size_t)c * DNEI_ * E_ + n;
#pragma unroll 8
        for (int k = 0; k < DNEI_; k++) {
            float w = W[(size_t)k * E_];
            __nv_bfloat16 h = __float2bfloat16(w);
            __nv_bfloat16 l = __float2bfloat16(w - __bfloat162float(h));
            *(__nv_bfloat16*)(rb + k * 2)      = h;   // Whi
            *(__nv_bfloat16*)(rb + 96 + k * 2) = l;   // Wlo
        }
    }
}

// ---------------- kernel 2: per-class scan over blocks ----------------
// Class segment starts are padded to multiples of 128 rows (cp.async alignment
// + tile alignment). Padding rows are never computed on (guards vs g_cnt).
__global__ void k_prefix() {
    int w    = threadIdx.x >> 5;
    int lane = threadIdx.x & 31;
    __shared__ int tot[CN_];
    if (w < CN_) {
        int acc = 0;
#pragma unroll
        for (int seg = 0; seg < NBLK_ / 32; seg++) {
            int v = g_bcnt[w][seg * 32 + lane];
            int s = v;
#pragma unroll
            for (int d = 1; d < 32; d <<= 1) {
                int t = __shfl_up_sync(0xffffffffu, s, d);
                if (lane >= d) s += t;
            }
            g_base[w][seg * 32 + lane] = acc + s - v;
            acc += __shfl_sync(0xffffffffu, s, 31);
        }
        if (lane == 0) tot[w] = acc;
    }
    __syncthreads();
    if (threadIdx.x == 0) {
        int a = 0;
        for (int c = 0; c < CN_; c++) {
            g_off[c] = a; g_cnt[c] = tot[c];
            a = (a + tot[c] + 127) & ~127;      // align next class start
        }
    }
}

// ---------------- kernel 3: scatter + transform + bf16 hi/lo split copy --------
__global__ void k_scattercopy(const float* __restrict__ neis,
                              const int*   __restrict__ nei_labels) {
    __shared__ int s_cur[CN_];
    __shared__ int s_pos[256];
    int tid = threadIdx.x;
    int blk = blockIdx.x;
    if (tid < CN_) s_cur[tid] = g_off[tid] + g_base[tid][blk];
    __syncthreads();

    int row = blk * 256 + tid;
    int c   = nei_labels[row];
    int pos = atomicAdd(&s_cur[c], 1);
    s_pos[tid]  = pos;
    g_perm[pos] = row;
    __syncthreads();

#pragma unroll
    for (int it = 0; it < 12; it++) {
        int idx = it * 256 + tid;
        int r = idx / 12, q = idx % 12;       // q: float4 chunk 0..11
        float4 v = *(const float4*)(neis + ((size_t)blk * 256 + r) * DNEI_ + q * 4);
        v.x = (v.x >= 0.f) ? 1.f / (v.x + EPSF) : 1.f / (v.x - EPSF);
        v.y = (v.y >= 0.f) ? 1.f / (v.y + EPSF) : 1.f / (v.y - EPSF);
        v.z = (v.z >= 0.f) ? 1.f / (v.z + EPSF) : 1.f / (v.z - EPSF);
        v.w = (v.w >= 0.f) ? 1.f / (v.w + EPSF) : 1.f / (v.w - EPSF);

        __nv_bfloat16 hx = __float2bfloat16(v.x), hy = __float2bfloat16(v.y);
        __nv_bfloat16 hz = __float2bfloat16(v.z), hw = __float2bfloat16(v.w);
        __nv_bfloat16 lx = __float2bfloat16(v.x - __bfloat162float(hx));
        __nv_bfloat16 ly = __float2bfloat16(v.y - __bfloat162float(hy));
        __nv_bfloat16 lz = __float2bfloat16(v.z - __bfloat162float(hz));
        __nv_bfloat16 lw = __float2bfloat16(v.w - __bfloat162float(hw));

        uint32_t h01 = ((uint32_t)__bfloat16_as_ushort(hy) << 16) | __bfloat16_as_ushort(hx);
        uint32_t h23 = ((uint32_t)__bfloat16_as_ushort(hw) << 16) | __bfloat16_as_ushort(hz);
        uint32_t l01 = ((uint32_t)__bfloat16_as_ushort(ly) << 16) | __bfloat16_as_ushort(lx);
        uint32_t l23 = ((uint32_t)__bfloat16_as_ushort(lw) << 16) | __bfloat16_as_ushort(lz);

        char* rb = (char*)g_Ab + (size_t)s_pos[r] * ROW2_;
        *(uint2*)(rb + q * 8)       = make_uint2(h01, h23);   // hi (k 0..47)
        *(uint2*)(rb + 96 + q * 8)  = make_uint2(l01, l23);   // lo
    }
}

// ================= mma.sync / cp.async helpers =================
__device__ __forceinline__ uint32_t smem_u32(const void* p) {
    uint32_t a;
    asm("{ .reg .u64 t; cvta.to.shared.u64 t, %1; cvt.u32.u64 %0, t; }" : "=r"(a) : "l"(p));
    return a;
}
__device__ __forceinline__ void cp_async16(uint32_t dst, const void* src, int src_size) {
    asm volatile("cp.async.cg.shared.global [%0], [%1], 16, %2;"
                 :: "r"(dst), "l"(src), "r"(src_size) : "memory");
}
__device__ __forceinline__ void cp_commit() {
    asm volatile("cp.async.commit_group;" ::: "memory");
}
__device__ __forceinline__ void cp_wait_all() {
    asm volatile("cp.async.wait_group 0;" ::: "memory");
}
__device__ __forceinline__ void ldsm_x4(uint32_t* r, uint32_t addr) {
    asm volatile("ldmatrix.sync.aligned.m8n8.x4.shared.b16 {%0,%1,%2,%3}, [%4];"
                 : "=r"(r[0]), "=r"(r[1]), "=r"(r[2]), "=r"(r[3]) : "r"(addr));
}
__device__ __forceinline__ void mma16816(float* c, const uint32_t* a, uint32_t b0, uint32_t b1) {
    asm volatile("mma.sync.aligned.m16n8k16.row.col.f32.bf16.bf16.f32 "
                 "{%0,%1,%2,%3}, {%4,%5,%6,%7}, {%8,%9}, {%0,%1,%2,%3};"
                 : "+f"(c[0]), "+f"(c[1]), "+f"(c[2]), "+f"(c[3])
                 : "r"(a[0]), "r"(a[1]), "r"(a[2]), "r"(a[3]), "r"(b0), "r"(b1));
}

// ---------------- kernel 4: persistent pipelined grouped GEMM (mma.sync bf16) ----
// 128x128 tile. A rows [hi|lo] 192B; 3-term split via fragment recombination:
// acc += A_hi*B_hi + A_lo*B_hi + A_hi*B_lo. 256 threads = 8 warps (2x4).
#define MT 128
#define NT 128
#define GEMM_MAX_MTILES ((RTOT_ / MT) + CN_)   // 1031
#define JOBS_ 14
#define GEMM_CHUNKS ((GEMM_MAX_MTILES + JOBS_ - 1) / JOBS_)  // 74
#define GEMM_GRID (GEMM_CHUNKS * 4)            // 296 = 148 SMs x occ 2
#define STRIDE 208                             // conflict-free LDSM stride (192B rows + pad)
#define TILE_SB (128 * STRIDE)                 // 26624
#define HDR_B 1024                             // per buffer: perm 512 + bias 512
#define SMEM_BYTES (2 * HDR_B + 2 * TILE_SB + TILE_SB)   // 81920

__global__ void __launch_bounds__(256, 2)
k_gemm_mma(const float* __restrict__ b_nei,
           float*       __restrict__ out_nei) {
    int nt    = blockIdx.x & 3;
    int chunk = blockIdx.x >> 2;
    int mid0  = chunk * JOBS_;

    int cnts[CN_], offs[CN_];
#pragma unroll
    for (int cc = 0; cc < CN_; cc++) { cnts[cc] = g_cnt[cc]; offs[cc] = g_off[cc]; }

    extern __shared__ char smem[];
    char* hdrb  = smem;                          // 2 x HDR_B
    char* a_smb = smem + 2 * HDR_B;              // 2 x TILE_SB
    char* b_sm  = smem + 2 * HDR_B + 2 * TILE_SB;

    int tid  = threadIdx.x;
    int lane = tid & 31;
    int wid  = tid >> 5;
    int wm   = wid & 1;          // 2 warp rows (64 rows each)
    int wn   = wid >> 1;         // 4 warp cols (32 cols each)

    // per-thread cp.async geometry: row tid>>1, 16B chunks h..h+5
    int pr = tid >> 1;
    int ph = (tid & 1) * 6;

    auto map_job = [&](int mid, int& c, int& mt) -> bool {
        int acc = 0;
#pragma unroll
        for (int cc = 0; cc < CN_; cc++) {
            int t = (cnts[cc] + MT - 1) >> 7;
            if (mid < acc + t) { c = cc; mt = mid - acc; return true; }
            acc += t;
        }
        return false;
    };

    auto prefetch_A = [&](int buf, int c, int mt) {
        int m0 = mt * MT;
        int ok = (m0 + pr < cnts[c]) ? 16 : 0;
        const char* src = (const char*)g_Ab
                        + (size_t)(ok ? (offs[c] + m0 + pr) : 0) * ROW2_;
        uint32_t dst = smem_u32(a_smb + buf * TILE_SB)
                     + (uint32_t)pr * STRIDE + (uint32_t)ph * 16;
#pragma unroll
        for (int i = 0; i < 6; i++)
            cp_async16(dst + i * 16, src + (ph + i) * 16, ok);
    };
    auto prefetch_hdr = [&](int buf, int c, int mt) {
        if (tid < 32) {
            // offs[c] and mt*MT are multiples of 128 -> byte offset multiple of 512
            const char* src = (const char*)g_perm + ((size_t)offs[c] + mt * MT) * 4 + tid * 16;
            cp_async16(smem_u32(hdrb + buf * HDR_B) + tid * 16, src, 16);
        } else if (tid < 64) {
            int l = tid - 32;
            const char* src = (const char*)b_nei + ((size_t)c * E_ + nt * NT) * 4 + l * 16;
            cp_async16(smem_u32(hdrb + buf * HDR_B) + 512 + l * 16, src, 16);
        }
    };
    auto prefetch_B = [&](int c) {
        const char* src = (const char*)g_Wb + ((size_t)c * E_ + nt * NT + pr) * ROW2_;
        uint32_t dst = smem_u32(b_sm) + (uint32_t)pr * STRIDE + (uint32_t)ph * 16;
#pragma unroll
        for (int i = 0; i < 6; i++)
            cp_async16(dst + i * 16, src + (ph + i) * 16, 16);
    };

    // prologue
    int c0, mt0;
    if (!map_job(mid0, c0, mt0)) return;
    prefetch_A(0, c0, mt0);
    prefetch_hdr(0, c0, mt0);
    prefetch_B(c0);
    cp_commit();

    int cur = 0, bclass = c0;

    for (int j = 0; j < JOBS_; j++) {
        int mid = mid0 + j;
        int c, mt;
        if (!map_job(mid, c, mt)) break;
        int cnt = cnts[c];

        cp_wait_all();          // this thread's copies for job j done
        __syncthreads();        // all threads' copies done + prev compute finished

        // B reload on class change (rare; exposed but cheap, L2-hot).
        // NOTE: cp.async wait_group is PER-THREAD — the __syncthreads() after the
        // wait is required so every thread sees the complete B tile (race fixed).
        if (c != bclass) {      // uniform branch (c, bclass are CTA-uniform)
            prefetch_B(c);
            cp_commit();
            cp_wait_all();
            __syncthreads();
            bclass = c;
        }

        // prefetch job j+1 (A + hdr) into alternate buffers — overlaps compute
        if (j + 1 < JOBS_) {
            int cn, mtn;
            if (map_job(mid + 1, cn, mtn)) {
                prefetch_A(cur ^ 1, cn, mtn);
                prefetch_hdr(cur ^ 1, cn, mtn);
                cp_commit();
            }
        }

        const int*   s_perm = (const int*)(hdrb + cur * HDR_B);
        const float* s_bias = (const float*)(hdrb + cur * HDR_B + 512);

        // ---- compute ----
        uint32_t a_u32 = smem_u32(a_smb + cur * TILE_SB);
        uint32_t b_u32 = smem_u32(b_sm);
        uint32_t a_base = a_u32 + (uint32_t)(wm * 64 + (lane & 15)) * STRIDE
                                + ((lane >> 4) << 4);
        uint32_t b_base = b_u32 + (uint32_t)(wn * 32 + ((lane >> 4) << 3) + (lane & 7)) * STRIDE
                                + (((lane >> 3) & 1) << 4);

        float acc[4][4][4];
#pragma unroll
        for (int i = 0; i < 4; i++)
#pragma unroll
            for (int jj = 0; jj < 4; jj++)
#pragma unroll
                for (int q = 0; q < 4; q++) acc[i][jj][q] = 0.f;

#pragma unroll
        for (int kc = 0; kc < 3; kc++) {       // 48 = 3 x 16
            uint32_t kb = kc * 32;
            uint32_t Bh0[4], Bh1[4], Bl0[4], Bl1[4];
            ldsm_x4(Bh0, b_base + kb);                       // Whi, ntiles 0,1
            ldsm_x4(Bh1, b_base + 16 * STRIDE + kb);         // Whi, ntiles 2,3
            ldsm_x4(Bl0, b_base + 96 + kb);                  // Wlo, ntiles 0,1
            ldsm_x4(Bl1, b_base + 16 * STRIDE + 96 + kb);    // Wlo, ntiles 2,3
#pragma unroll
            for (int mi = 0; mi < 4; mi++) {
                uint32_t Ah[4], Al[4];
                ldsm_x4(Ah, a_base + (uint32_t)mi * 16 * STRIDE + kb);
                ldsm_x4(Al, a_base + (uint32_t)mi * 16 * STRIDE + 96 + kb);
                // hi*hi
                mma16816(acc[mi][0], Ah, Bh0[0], Bh0[1]);
                mma16816(acc[mi][1], Ah, Bh0[2], Bh0[3]);
                mma16816(acc[mi][2], Ah, Bh1[0], Bh1[1]);
                mma16816(acc[mi][3], Ah, Bh1[2], Bh1[3]);
                // lo*hi
                mma16816(acc[mi][0], Al, Bh0[0], Bh0[1]);
                mma16816(acc[mi][1], Al, Bh0[2], Bh0[3]);
                mma16816(acc[mi][2], Al, Bh1[0], Bh1[1]);
                mma16816(acc[mi][3], Al, Bh1[2], Bh1[3]);
                // hi*lo
                mma16816(acc[mi][0], Ah, Bl0[0], Bl0[1]);
                mma16816(acc[mi][1], Ah, Bl0[2], Bl0[3]);
                mma16816(acc[mi][2], Ah, Bl1[0], Bl1[1]);
                mma16816(acc[mi][3], Ah, Bl1[2], Bl1[3]);
            }
        }

        // ---- epilogue ----
        int g = lane >> 2, t4 = lane & 3;
        int m0 = mt * MT;
#pragma unroll
        for (int mi = 0; mi < 4; mi++) {
#pragma unroll
            for (int half = 0; half < 2; half++) {
                int rloc = wm * 64 + mi * 16 + g + half * 8;
                if (m0 + rloc < cnt) {
                    int rg = s_perm[rloc];
                    float* orow = out_nei + (size_t)rg * E_ + nt * NT + wn * 32;
#pragma unroll
                    for (int ni = 0; ni < 4; ni++) {
                        int colo = ni * 8 + t4 * 2;
                        float2 v = make_float2(
                            acc[mi][ni][half * 2 + 0] + s_bias[wn * 32 + colo],
                            acc[mi][ni][half * 2 + 1] + s_bias[wn * 32 + colo + 1]);
                        *(float2*)(orow + colo) = v;
                    }
                }
            }
        }

        cur ^= 1;
    }
}

// ---------------- kernel 5: anchor ----------------
__global__ void k_anchor(const float* __restrict__ init_trajs,
                         const float* __restrict__ W_self,
                         const float* __restrict__ b_self) {
    int c  = blockIdx.x / K_;
    int kk = blockIdx.x % K_;
    __shared__ float tr[PRED_ * IN_];
    if (threadIdx.x < PRED_ * IN_)
        tr[threadIdx.x] = init_trajs[((size_t)c * K_ + kk) * (PRED_ * IN_) + threadIdx.x];
    __syncthreads();

    int col = threadIdx.x * 4;
    const float* bb = b_self + (size_t)c * E_ + col;
    float4 acc = *(const float4*)bb;
    const float* W = W_self + ((size_t)c * DSELF_ + DNEI_) * E_ + col;
#pragma unroll 8
    for (int j = 0; j < PRED_ * IN_; j++) {
        float  t = tr[j];
        float4 w = *(const float4*)(W + (size_t)j * E_);
        acc.x += t * w.x; acc.y += t * w.y; acc.z += t * w.z; acc.w += t * w.w;
    }
    *(float4*)(g_anchor + ((size_t)c * K_ + kk) * E_ + col) = acc;
}

// ---------------- kernel 6: bin self_labels (single block, deterministic) --------
__global__ void k_xbin(const int* __restrict__ self_labels) {
    __shared__ int sc[C_][256];
    __shared__ int s_tot[C_];
    __shared__ int s_off[C_];
    int tid = threadIdx.x;
    int base = tid * 8;                       // 256 threads x 8 labels = 2048

#pragma unroll
    for (int c = 0; c < C_; c++) {
        int n = 0;
#pragma unroll
        for (int i = 0; i < 8; i++) n += (self_labels[base + i] == c);
        sc[c][tid] = n;
    }
    __syncthreads();

    int w = tid >> 5, lane = tid & 31;
    if (w < C_) {
        int acc = 0;
#pragma unroll
        for (int seg = 0; seg < 8; seg++) {
            int v = sc[w][seg * 32 + lane];
            int s = v;
#pragma unroll
            for (int d = 1; d < 32; d <<= 1) {
                int t = __shfl_up_sync(0xffffffffu, s, d);
                if (lane >= d) s += t;
            }
            sc[w][seg * 32 + lane] = acc + s - v;
            acc += __shfl_sync(0xffffffffu, s, 31);
        }
        if (lane == 0) s_tot[w] = acc;
    }
    __syncthreads();
    if (tid == 0) {
        int a = 0;
        for (int c = 0; c < C_; c++) {
            s_off[c] = a; g_xoff[c] = a; g_xcnt[c] = s_tot[c]; a += s_tot[c];
        }
    }
    __syncthreads();

#pragma unroll
    for (int c = 0; c < C_; c++) {
        int p = s_off[c] + sc[c][tid];
#pragma unroll
        for (int i = 0; i < 8; i++)
            if (self_labels[base + i] == c) g_xperm[p++] = base + i;
    }
}

// ---------------- kernel 7: x path, 8 same-class samples per block --------------
#define XGRP 8
#define X2_GRID (B_ / XGRP + C_)     // 262

__global__ void __launch_bounds__(128)
k_x2(const float* __restrict__ obs,
     const float* __restrict__ W_self,
     float*       __restrict__ out_x) {
    int mid = blockIdx.x;
    int c = -1, gt = 0, acc_t = 0;
#pragma unroll
    for (int cc = 0; cc < C_; cc++) {
        int t = (g_xcnt[cc] + XGRP - 1) / XGRP;
        if (c < 0 && mid < acc_t + t) { c = cc; gt = mid - acc_t; }
        acc_t += t;
    }
    if (c < 0) return;
    int cnt = g_xcnt[c];
    int xo  = g_xoff[c];
    int s0  = gt * XGRP;
    int m   = min(XGRP, cnt - s0);

    __shared__ int   s_rows[XGRP];
    __shared__ float s_obs[XGRP][DNEI_];
    int tid = threadIdx.x;

    if (tid < XGRP)
        s_rows[tid] = (tid < m) ? g_xperm[xo + s0 + tid] : -1;
    __syncthreads();
    if (tid < 96) {
        int s = tid / 12, q = tid % 12;
        int rb = s_rows[s];
        float4 v = make_float4(0.f, 0.f, 0.f, 0.f);
        if (rb >= 0) v = *(const float4*)(obs + (size_t)rb * DNEI_ + q * 4);
        *(float4*)(&s_obs[s][q * 4]) = v;
    }
    __syncthreads();

    int col = tid * 4;
    const float* W = W_self + (size_t)c * DSELF_ * E_ + col;
    float4 a0 = make_float4(0,0,0,0), a1 = a0, a2 = a0, a3 = a0;
    float4 a4 = a0, a5 = a0, a6 = a0, a7 = a0;
#pragma unroll 4
    for (int j = 0; j < DNEI_; j++) {
        float4 w4 = *(const float4*)(W + (size_t)j * E_);
        float t0 = s_obs[0][j], t1 = s_obs[1][j], t2 = s_obs[2][j], t3 = s_obs[3][j];
        float t4 = s_obs[4][j], t5 = s_obs[5][j], t6 = s_obs[6][j], t7 = s_obs[7][j];
        a0.x += t0*w4.x; a0.y += t0*w4.y; a0.z += t0*w4.z; a0.w += t0*w4.w;
        a1.x += t1*w4.x; a1.y += t1*w4.y; a1.z += t1*w4.z; a1.w += t1*w4.w;
        a2.x += t2*w4.x; a2.y += t2*w4.y; a2.z += t2*w4.z; a2.w += t2*w4.w;
        a3.x += t3*w4.x; a3.y += t3*w4.y; a3.z += t3*w4.z; a3.w += t3*w4.w;
        a4.x += t4*w4.x; a4.y += t4*w4.y; a4.z += t4*w4.z; a4.w += t4*w4.w;
        a5.x += t5*w4.x; a5.y += t5*w4.y; a5.z += t5*w4.z; a5.w += t5*w4.w;
        a6.x += t6*w4.x; a6.y += t6*w4.y; a6.z += t6*w4.z; a6.w += t6*w4.w;
        a7.x += t7*w4.x; a7.y += t7*w4.y; a7.z += t7*w4.z; a7.w += t7*w4.w;
    }

    float4 av[XGRP] = {a0, a1, a2, a3, a4, a5, a6, a7};
#pragma unroll
    for (int kk = 0; kk < K_; kk++) {
        float4 an = *(const float4*)(g_anchor + ((size_t)c * K_ + kk) * E_ + col);
#pragma unroll
        for (int s = 0; s < XGRP; s++) {
            int rb = s_rows[s];
            if (rb >= 0) {
                float4 v = make_float4(av[s].x + an.x, av[s].y + an.y,
                                       av[s].z + an.z, av[s].w + an.w);
                *(float4*)(out_x + ((size_t)rb * K_ + kk) * E_ + col) = v;
            }
        }
    }
}

// ---------------- launcher ----------------
#define WPREP_BLKS ((CN_ * E_ + 255) / 256)    // 14

extern "C" void kernel_launch(void* const* d_in, const int* in_sizes, int n_in,
                              void* d_out, int out_size) {
    const float* obs         = (const float*)d_in[0];
    const float* neis        = (const float*)d_in[1];
    const float* init_trajs  = (const float*)d_in[2];
    const float* W_self      = (const float*)d_in[3];
    const float* b_self      = (const float*)d_in[4];
    const float* W_nei       = (const float*)d_in[5];
    const float* b_nei       = (const float*)d_in[6];
    const int*   self_labels = (const int*)d_in[7];
    const int*   nei_labels  = (const int*)d_in[8];

    float* out_x   = (float*)d_out;
    float* out_nei = (float*)d_out + X_ELEMS;

    cudaFuncSetAttribute(k_gemm_mma, cudaFuncAttributeMaxDynamicSharedMemorySize, SMEM_BYTES);

    // nei_feats path (GEMM is launch #4 -> lands in the ncu capture slot)
    k_count_wprep<<<NBLK_ + WPREP_BLKS, 256>>>(nei_labels, W_nei);
    k_prefix<<<1, 256>>>();
    k_scattercopy<<<NBLK_, 256>>>(neis, nei_labels);
    k_gemm_mma<<<GEMM_GRID, 256, SMEM_BYTES>>>(b_nei, out_nei);

    // x path
    k_anchor<<<C_ * K_, 128>>>(init_trajs, W_self, b_self);
    k_xbin<<<1, 256>>>(self_labels);
    k_x2<<<X2_GRID, 128>>>(obs, W_self, out_x);
}

// round 12
// speedup vs baseline: 1.7628x; 1.1499x over previous
#include <cuda_runtime.h>
#include <cuda_bf16.h>
#include <cstdint>

typedef unsigned long long u64;

// Problem constants
#define B_      2048
#define N_      64
#define OBS_    8
#define PRED_   12
#define IN_     6
#define E_      512
#define C_      6
#define CN_     7          // C + 1
#define K_      20
#define DSELF_  120        // IN*(OBS+PRED)
#define DNEI_   48         // IN*OBS
#define RTOT_   (B_ * N_)  // 131072
#define NBLK_   (RTOT_ / 256)   // 512
#define EPSF    1e-4f

#define KP2_    96         // packed row: [hi(48) | lo(48)] bf16
#define ROW2_   (KP2_ * 2) // 192 bytes per packed row
#define RPAD_   (RTOT_ + CN_ * 128)   // class-aligned padding slack
#define X_ELEMS ((size_t)B_ * K_ * E_)   // 20,971,520

// ---------------- scratch (__device__ globals; no allocation) ----------------
// 256B alignment: required for 16B cp.async sources.
__device__ __align__(256) __nv_bfloat16 g_Ab[(size_t)RPAD_ * KP2_];
__device__ __align__(256) __nv_bfloat16 g_Wb[(size_t)CN_ * E_ * KP2_];
__device__ __align__(256) int   g_perm[RPAD_ + 128];
__device__ __align__(256) int   g_bcnt[CN_][NBLK_];
__device__ __align__(256) int   g_base[CN_][NBLK_];
__device__ __align__(256) int   g_cnt[CN_];
__device__ __align__(256) int   g_off[CN_];    // class starts, padded to 128 rows
__device__ __align__(256) float g_anchor[(size_t)C_ * K_ * E_];
// x-path binning
__device__ __align__(256) int   g_xperm[B_];
__device__ __align__(256) int   g_xcnt[C_];
__device__ __align__(256) int   g_xoff[C_];

// ---------------- kernel 1: histograms + weight split + anchor + xbin (fused) ----
#define WPREP_BLKS ((CN_ * E_ + 255) / 256)    // 14
#define ANCH_BLKS  (C_ * K_)                   // 120
#define K1_GRID    (NBLK_ + WPREP_BLKS + ANCH_BLKS + 1)

__global__ void k_prep(const int* __restrict__ nei_labels,
                       const float* __restrict__ W_nei,
                       const float* __restrict__ init_trajs,
                       const float* __restrict__ W_self,
                       const float* __restrict__ b_self,
                       const int*   __restrict__ self_labels) {
    int tid = threadIdx.x;
    if (blockIdx.x < NBLK_) {
        // ---- per-block class histogram ----
        __shared__ int sc[CN_];
        if (tid < CN_) sc[tid] = 0;
        __syncthreads();
        int i = blockIdx.x * 256 + tid;
        atomicAdd(&sc[nei_labels[i]], 1);
        __syncthreads();
        if (tid < CN_) g_bcnt[tid][blockIdx.x] = sc[tid];
    } else if (blockIdx.x < NBLK_ + WPREP_BLKS) {
        // ---- weight hi/lo split ----
        int g = (blockIdx.x - NBLK_) * 256 + tid;   // (c, n)
        if (g >= CN_ * E_) return;
        int c = g / E_, n = g % E_;
        char* rb = (char*)g_Wb + (size_t)g * ROW2_;
        const float* W = W_nei + (size_t)c * DNEI_ * E_ + n;
#pragma unroll 8
        for (int k = 0; k < DNEI_; k++) {
            float w = W[(size_t)k * E_];
            __nv_bfloat16 h = __float2bfloat16(w);
            __nv_bfloat16 l = __float2bfloat16(w - __bfloat162float(h));
            *(__nv_bfloat16*)(rb + k * 2)      = h;   // Whi
            *(__nv_bfloat16*)(rb + 96 + k * 2) = l;   // Wlo
        }
    } else if (blockIdx.x < NBLK_ + WPREP_BLKS + ANCH_BLKS) {
        // ---- anchor: anchor[c,k,:] = it[c,k] @ W_self[c][48:] + b_self[c] ----
        int bid = blockIdx.x - NBLK_ - WPREP_BLKS;
        int c  = bid / K_;
        int kk = bid % K_;
        __shared__ float tr[PRED_ * IN_];   // 72
        if (tid < PRED_ * IN_)
            tr[tid] = init_trajs[((size_t)c * K_ + kk) * (PRED_ * IN_) + tid];
        __syncthreads();
        if (tid < 128) {
            int col = tid * 4;
            const float* bb = b_self + (size_t)c * E_ + col;
            float4 acc = *(const float4*)bb;
            const float* W = W_self + ((size_t)c * DSELF_ + DNEI_) * E_ + col;
#pragma unroll 8
            for (int j = 0; j < PRED_ * IN_; j++) {
                float  t = tr[j];
                float4 w = *(const float4*)(W + (size_t)j * E_);
                acc.x += t * w.x; acc.y += t * w.y; acc.z += t * w.z; acc.w += t * w.w;
            }
            *(float4*)(g_anchor + ((size_t)c * K_ + kk) * E_ + col) = acc;
        }
    } else {
        // ---- xbin: bin self_labels (single block, deterministic) ----
        __shared__ int sc2[C_][256];
        __shared__ int s_tot[C_];
        __shared__ int s_off[C_];
        int base = tid * 8;                       // 256 x 8 = 2048
#pragma unroll
        for (int c = 0; c < C_; c++) {
            int n = 0;
#pragma unroll
            for (int i = 0; i < 8; i++) n += (self_labels[base + i] == c);
            sc2[c][tid] = n;
        }
        __syncthreads();
        int w = tid >> 5, lane = tid & 31;
        if (w < C_) {
            int acc = 0;
#pragma unroll
            for (int seg = 0; seg < 8; seg++) {
                int v = sc2[w][seg * 32 + lane];
                int s = v;
#pragma unroll
                for (int d = 1; d < 32; d <<= 1) {
                    int t = __shfl_up_sync(0xffffffffu, s, d);
                    if (lane >= d) s += t;
                }
                sc2[w][seg * 32 + lane] = acc + s - v;
                acc += __shfl_sync(0xffffffffu, s, 31);
            }
            if (lane == 0) s_tot[w] = acc;
        }
        __syncthreads();
        if (tid == 0) {
            int a = 0;
            for (int c = 0; c < C_; c++) {
                s_off[c] = a; g_xoff[c] = a; g_xcnt[c] = s_tot[c]; a += s_tot[c];
            }
        }
        __syncthreads();
#pragma unroll
        for (int c = 0; c < C_; c++) {
            int p = s_off[c] + sc2[c][tid];
#pragma unroll
            for (int i = 0; i < 8; i++)
                if (self_labels[base + i] == c) g_xperm[p++] = base + i;
        }
    }
}

// ---------------- kernel 2: per-class scan over blocks ----------------
__global__ void k_prefix() {
    int w    = threadIdx.x >> 5;
    int lane = threadIdx.x & 31;
    __shared__ int tot[CN_];
    if (w < CN_) {
        int acc = 0;
#pragma unroll
        for (int seg = 0; seg < NBLK_ / 32; seg++) {
            int v = g_bcnt[w][seg * 32 + lane];
            int s = v;
#pragma unroll
            for (int d = 1; d < 32; d <<= 1) {
                int t = __shfl_up_sync(0xffffffffu, s, d);
                if (lane >= d) s += t;
            }
            g_base[w][seg * 32 + lane] = acc + s - v;
            acc += __shfl_sync(0xffffffffu, s, 31);
        }
        if (lane == 0) tot[w] = acc;
    }
    __syncthreads();
    if (threadIdx.x == 0) {
        int a = 0;
        for (int c = 0; c < CN_; c++) {
            g_off[c] = a; g_cnt[c] = tot[c];
            a = (a + tot[c] + 127) & ~127;      // align next class start
        }
    }
}

// ---------------- kernel 3: scatter + transform + bf16 hi/lo split copy --------
__global__ void k_scattercopy(const float* __restrict__ neis,
                              const int*   __restrict__ nei_labels) {
    __shared__ int s_cur[CN_];
    __shared__ int s_pos[256];
    int tid = threadIdx.x;
    int blk = blockIdx.x;
    if (tid < CN_) s_cur[tid] = g_off[tid] + g_base[tid][blk];
    __syncthreads();

    int row = blk * 256 + tid;
    int c   = nei_labels[row];
    int pos = atomicAdd(&s_cur[c], 1);
    s_pos[tid]  = pos;
    g_perm[pos] = row;
    __syncthreads();

#pragma unroll
    for (int it = 0; it < 12; it++) {
        int idx = it * 256 + tid;
        int r = idx / 12, q = idx % 12;       // q: float4 chunk 0..11
        float4 v = *(const float4*)(neis + ((size_t)blk * 256 + r) * DNEI_ + q * 4);
        v.x = (v.x >= 0.f) ? 1.f / (v.x + EPSF) : 1.f / (v.x - EPSF);
        v.y = (v.y >= 0.f) ? 1.f / (v.y + EPSF) : 1.f / (v.y - EPSF);
        v.z = (v.z >= 0.f) ? 1.f / (v.z + EPSF) : 1.f / (v.z - EPSF);
        v.w = (v.w >= 0.f) ? 1.f / (v.w + EPSF) : 1.f / (v.w - EPSF);

        __nv_bfloat16 hx = __float2bfloat16(v.x), hy = __float2bfloat16(v.y);
        __nv_bfloat16 hz = __float2bfloat16(v.z), hw = __float2bfloat16(v.w);
        __nv_bfloat16 lx = __float2bfloat16(v.x - __bfloat162float(hx));
        __nv_bfloat16 ly = __float2bfloat16(v.y - __bfloat162float(hy));
        __nv_bfloat16 lz = __float2bfloat16(v.z - __bfloat162float(hz));
        __nv_bfloat16 lw = __float2bfloat16(v.w - __bfloat162float(hw));

        uint32_t h01 = ((uint32_t)__bfloat16_as_ushort(hy) << 16) | __bfloat16_as_ushort(hx);
        uint32_t h23 = ((uint32_t)__bfloat16_as_ushort(hw) << 16) | __bfloat16_as_ushort(hz);
        uint32_t l01 = ((uint32_t)__bfloat16_as_ushort(ly) << 16) | __bfloat16_as_ushort(lx);
        uint32_t l23 = ((uint32_t)__bfloat16_as_ushort(lw) << 16) | __bfloat16_as_ushort(lz);

        char* rb = (char*)g_Ab + (size_t)s_pos[r] * ROW2_;
        *(uint2*)(rb + q * 8)       = make_uint2(h01, h23);   // hi (k 0..47)
        *(uint2*)(rb + 96 + q * 8)  = make_uint2(l01, l23);   // lo
    }
}

// ================= mma.sync / cp.async helpers =================
__device__ __forceinline__ uint32_t smem_u32(const void* p) {
    uint32_t a;
    asm("{ .reg .u64 t; cvta.to.shared.u64 t, %1; cvt.u32.u64 %0, t; }" : "=r"(a) : "l"(p));
    return a;
}
__device__ __forceinline__ void cp_async16(uint32_t dst, const void* src, int src_size) {
    asm volatile("cp.async.cg.shared.global [%0], [%1], 16, %2;"
                 :: "r"(dst), "l"(src), "r"(src_size) : "memory");
}
__device__ __forceinline__ void cp_commit() {
    asm volatile("cp.async.commit_group;" ::: "memory");
}
__device__ __forceinline__ void cp_wait_all() {
    asm volatile("cp.async.wait_group 0;" ::: "memory");
}
__device__ __forceinline__ void ldsm_x4(uint32_t* r, uint32_t addr) {
    asm volatile("ldmatrix.sync.aligned.m8n8.x4.shared.b16 {%0,%1,%2,%3}, [%4];"
                 : "=r"(r[0]), "=r"(r[1]), "=r"(r[2]), "=r"(r[3]) : "r"(addr));
}
__device__ __forceinline__ void mma16816(float* c, const uint32_t* a, uint32_t b0, uint32_t b1) {
    asm volatile("mma.sync.aligned.m16n8k16.row.col.f32.bf16.bf16.f32 "
                 "{%0,%1,%2,%3}, {%4,%5,%6,%7}, {%8,%9}, {%0,%1,%2,%3};"
                 : "+f"(c[0]), "+f"(c[1]), "+f"(c[2]), "+f"(c[3])
                 : "r"(a[0]), "r"(a[1]), "r"(a[2]), "r"(a[3]), "r"(b0), "r"(b1));
}

// ---------------- kernel 4: persistent GEMM + fused x-path tail ----------------
// 128x128 tile. A rows [hi|lo] 192B; 3-term split via fragment recombination.
// After its 14 jobs, each CTA processes one 8-sample x-group (overlaps with
// other CTAs' GEMM work, using spare DRAM bandwidth).
#define MT 128
#define NT 128
#define GEMM_MAX_MTILES ((RTOT_ / MT) + CN_)   // 1031
#define JOBS_ 14
#define GEMM_CHUNKS ((GEMM_MAX_MTILES + JOBS_ - 1) / JOBS_)  // 74
#define GEMM_GRID (GEMM_CHUNKS * 4)            // 296 = 148 SMs x occ 2
#define STRIDE 208                             // conflict-free LDSM stride
#define TILE_SB (128 * STRIDE)                 // 26624
#define HDR_B 1024                             // per buffer: perm 512 + bias 512
#define SMEM_BYTES (2 * HDR_B + 2 * TILE_SB + TILE_SB)   // 81920
#define XGRP 8

__global__ void __launch_bounds__(256, 2)
k_gemm_mma(const float* __restrict__ b_nei,
           const float* __restrict__ obs,
           const float* __restrict__ W_self,
           float*       __restrict__ out_nei,
           float*       __restrict__ out_x) {
    int nt    = blockIdx.x & 3;
    int chunk = blockIdx.x >> 2;
    int mid0  = chunk * JOBS_;

    int cnts[CN_], offs[CN_];
#pragma unroll
    for (int cc = 0; cc < CN_; cc++) { cnts[cc] = g_cnt[cc]; offs[cc] = g_off[cc]; }

    extern __shared__ char smem[];
    char* hdrb  = smem;                          // 2 x HDR_B
    char* a_smb = smem + 2 * HDR_B;              // 2 x TILE_SB
    char* b_sm  = smem + 2 * HDR_B + 2 * TILE_SB;

    int tid  = threadIdx.x;
    int lane = tid & 31;
    int wid  = tid >> 5;
    int wm   = wid & 1;          // 2 warp rows (64 rows each)
    int wn   = wid >> 1;         // 4 warp cols (32 cols each)

    // per-thread cp.async geometry: row tid>>1, 16B chunks h..h+5
    int pr = tid >> 1;
    int ph = (tid & 1) * 6;

    auto map_job = [&](int mid, int& c, int& mt) -> bool {
        int acc = 0;
#pragma unroll
        for (int cc = 0; cc < CN_; cc++) {
            int t = (cnts[cc] + MT - 1) >> 7;
            if (mid < acc + t) { c = cc; mt = mid - acc; return true; }
            acc += t;
        }
        return false;
    };

    auto prefetch_A = [&](int buf, int c, int mt) {
        int m0 = mt * MT;
        int ok = (m0 + pr < cnts[c]) ? 16 : 0;
        const char* src = (const char*)g_Ab
                        + (size_t)(ok ? (offs[c] + m0 + pr) : 0) * ROW2_;
        uint32_t dst = smem_u32(a_smb + buf * TILE_SB)
                     + (uint32_t)pr * STRIDE + (uint32_t)ph * 16;
#pragma unroll
        for (int i = 0; i < 6; i++)
            cp_async16(dst + i * 16, src + (ph + i) * 16, ok);
    };
    auto prefetch_hdr = [&](int buf, int c, int mt) {
        if (tid < 32) {
            const char* src = (const char*)g_perm + ((size_t)offs[c] + mt * MT) * 4 + tid * 16;
            cp_async16(smem_u32(hdrb + buf * HDR_B) + tid * 16, src, 16);
        } else if (tid < 64) {
            int l = tid - 32;
            const char* src = (const char*)b_nei + ((size_t)c * E_ + nt * NT) * 4 + l * 16;
            cp_async16(smem_u32(hdrb + buf * HDR_B) + 512 + l * 16, src, 16);
        }
    };
    auto prefetch_B = [&](int c) {
        const char* src = (const char*)g_Wb + ((size_t)c * E_ + nt * NT + pr) * ROW2_;
        uint32_t dst = smem_u32(b_sm) + (uint32_t)pr * STRIDE + (uint32_t)ph * 16;
#pragma unroll
        for (int i = 0; i < 6; i++)
            cp_async16(dst + i * 16, src + (ph + i) * 16, 16);
    };

    // prologue
    int c0, mt0;
    if (map_job(mid0, c0, mt0)) {
        prefetch_A(0, c0, mt0);
        prefetch_hdr(0, c0, mt0);
        prefetch_B(c0);
        cp_commit();

        int cur = 0, bclass = c0;

        for (int j = 0; j < JOBS_; j++) {
            int mid = mid0 + j;
            int c, mt;
            if (!map_job(mid, c, mt)) break;
            int cnt = cnts[c];

            cp_wait_all();          // this thread's copies for job j done
            __syncthreads();        // all threads' copies + prev compute done

            // B reload on class change (uniform branch; per-thread wait_group
            // needs the trailing __syncthreads for cross-thread visibility)
            if (c != bclass) {
                prefetch_B(c);
                cp_commit();
                cp_wait_all();
                __syncthreads();
                bclass = c;
            }

            // prefetch job j+1 into alternate buffers — overlaps compute
            if (j + 1 < JOBS_) {
                int cn, mtn;
                if (map_job(mid + 1, cn, mtn)) {
                    prefetch_A(cur ^ 1, cn, mtn);
                    prefetch_hdr(cur ^ 1, cn, mtn);
                    cp_commit();
                }
            }

            const int*   s_perm = (const int*)(hdrb + cur * HDR_B);
            const float* s_bias = (const float*)(hdrb + cur * HDR_B + 512);

            // ---- compute ----
            uint32_t a_u32 = smem_u32(a_smb + cur * TILE_SB);
            uint32_t b_u32 = smem_u32(b_sm);
            uint32_t a_base = a_u32 + (uint32_t)(wm * 64 + (lane & 15)) * STRIDE
                                    + ((lane >> 4) << 4);
            uint32_t b_base = b_u32 + (uint32_t)(wn * 32 + ((lane >> 4) << 3) + (lane & 7)) * STRIDE
                                    + (((lane >> 3) & 1) << 4);

            float acc[4][4][4];
#pragma unroll
            for (int i = 0; i < 4; i++)
#pragma unroll
                for (int jj = 0; jj < 4; jj++)
#pragma unroll
                    for (int q = 0; q < 4; q++) acc[i][jj][q] = 0.f;

#pragma unroll
            for (int kc = 0; kc < 3; kc++) {       // 48 = 3 x 16
                uint32_t kb = kc * 32;
                uint32_t Bh0[4], Bh1[4], Bl0[4], Bl1[4];
                ldsm_x4(Bh0, b_base + kb);                       // Whi, ntiles 0,1
                ldsm_x4(Bh1, b_base + 16 * STRIDE + kb);         // Whi, ntiles 2,3
                ldsm_x4(Bl0, b_base + 96 + kb);                  // Wlo, ntiles 0,1
                ldsm_x4(Bl1, b_base + 16 * STRIDE + 96 + kb);    // Wlo, ntiles 2,3
#pragma unroll
                for (int mi = 0; mi < 4; mi++) {
                    uint32_t Ah[4], Al[4];
                    ldsm_x4(Ah, a_base + (uint32_t)mi * 16 * STRIDE + kb);
                    ldsm_x4(Al, a_base + (uint32_t)mi * 16 * STRIDE + 96 + kb);
                    // hi*hi
                    mma16816(acc[mi][0], Ah, Bh0[0], Bh0[1]);
                    mma16816(acc[mi][1], Ah, Bh0[2], Bh0[3]);
                    mma16816(acc[mi][2], Ah, Bh1[0], Bh1[1]);
                    mma16816(acc[mi][3], Ah, Bh1[2], Bh1[3]);
                    // lo*hi
                    mma16816(acc[mi][0], Al, Bh0[0], Bh0[1]);
                    mma16816(acc[mi][1], Al, Bh0[2], Bh0[3]);
                    mma16816(acc[mi][2], Al, Bh1[0], Bh1[1]);
                    mma16816(acc[mi][3], Al, Bh1[2], Bh1[3]);
                    // hi*lo
                    mma16816(acc[mi][0], Ah, Bl0[0], Bl0[1]);
                    mma16816(acc[mi][1], Ah, Bl0[2], Bl0[3]);
                    mma16816(acc[mi][2], Ah, Bl1[0], Bl1[1]);
                    mma16816(acc[mi][3], Ah, Bl1[2], Bl1[3]);
                }
            }

            // ---- epilogue ----
            int g = lane >> 2, t4 = lane & 3;
            int m0 = mt * MT;
#pragma unroll
            for (int mi = 0; mi < 4; mi++) {
#pragma unroll
                for (int half = 0; half < 2; half++) {
                    int rloc = wm * 64 + mi * 16 + g + half * 8;
                    if (m0 + rloc < cnt) {
                        int rg = s_perm[rloc];
                        float* orow = out_nei + (size_t)rg * E_ + nt * NT + wn * 32;
#pragma unroll
                        for (int ni = 0; ni < 4; ni++) {
                            int colo = ni * 8 + t4 * 2;
                            float2 v = make_float2(
                                acc[mi][ni][half * 2 + 0] + s_bias[wn * 32 + colo],
                                acc[mi][ni][half * 2 + 1] + s_bias[wn * 32 + colo + 1]);
                            *(float2*)(orow + colo) = v;
                        }
                    }
                }
            }

            cur ^= 1;
        }
    }

    // ================== fused x-path tail ==================
    // map blockIdx.x -> (class, 8-sample group) over g_xcnt bins
    {
        int mid = blockIdx.x;
        int c = -1, gt = 0, acc_t = 0;
#pragma unroll
        for (int cc = 0; cc < C_; cc++) {
            int t = (g_xcnt[cc] + XGRP - 1) / XGRP;
            if (c < 0 && mid < acc_t + t) { c = cc; gt = mid - acc_t; }
            acc_t += t;
        }
        if (c < 0) return;
        int cnt = g_xcnt[c];
        int xo  = g_xoff[c];
        int s0  = gt * XGRP;
        int m   = min(XGRP, cnt - s0);

        __syncthreads();                      // done with GEMM smem
        int*   s_rows = (int*)smem;           // [8]
        float (*s_obs)[DNEI_] = (float(*)[DNEI_])(smem + 32);

        if (tid < XGRP)
            s_rows[tid] = (tid < m) ? g_xperm[xo + s0 + tid] : -1;
        __syncthreads();
        if (tid < 96) {
            int s = tid / 12, q = tid % 12;
            int rb = s_rows[s];
            float4 v = make_float4(0.f, 0.f, 0.f, 0.f);
            if (rb >= 0) v = *(const float4*)(obs + (size_t)rb * DNEI_ + q * 4);
            *(float4*)(&s_obs[s][q * 4]) = v;
        }
        __syncthreads();

        // 256 threads: col thread (tid&127) x kk-half (tid>>7); the 48-dot is
        // computed redundantly per pair (cheap), store loop split across halves.
        int ct   = tid & 127;
        int half = tid >> 7;
        int col  = ct * 4;
        const float* W = W_self + (size_t)c * DSELF_ * E_ + col;
        float4 a0 = make_float4(0,0,0,0), a1 = a0, a2 = a0, a3 = a0;
        float4 a4 = a0, a5 = a0, a6 = a0, a7 = a0;
#pragma unroll 4
        for (int j = 0; j < DNEI_; j++) {
            float4 w4 = *(const float4*)(W + (size_t)j * E_);
            float t0 = s_obs[0][j], t1 = s_obs[1][j], t2 = s_obs[2][j], t3 = s_obs[3][j];
            float t4 = s_obs[4][j], t5 = s_obs[5][j], t6 = s_obs[6][j], t7 = s_obs[7][j];
            a0.x += t0*w4.x; a0.y += t0*w4.y; a0.z += t0*w4.z; a0.w += t0*w4.w;
            a1.x += t1*w4.x; a1.y += t1*w4.y; a1.z += t1*w4.z; a1.w += t1*w4.w;
            a2.x += t2*w4.x; a2.y += t2*w4.y; a2.z += t2*w4.z; a2.w += t2*w4.w;
            a3.x += t3*w4.x; a3.y += t3*w4.y; a3.z += t3*w4.z; a3.w += t3*w4.w;
            a4.x += t4*w4.x; a4.y += t4*w4.y; a4.z += t4*w4.z; a4.w += t4*w4.w;
            a5.x += t5*w4.x; a5.y += t5*w4.y; a5.z += t5*w4.z; a5.w += t5*w4.w;
            a6.x += t6*w4.x; a6.y += t6*w4.y; a6.z += t6*w4.z; a6.w += t6*w4.w;
            a7.x += t7*w4.x; a7.y += t7*w4.y; a7.z += t7*w4.z; a7.w += t7*w4.w;
        }

        float4 av[XGRP] = {a0, a1, a2, a3, a4, a5, a6, a7};
        int kk0 = half * (K_ / 2), kk1 = kk0 + (K_ / 2);
#pragma unroll
        for (int kk = kk0; kk < kk1; kk++) {
            float4 an = *(const float4*)(g_anchor + ((size_t)c * K_ + kk) * E_ + col);
#pragma unroll
            for (int s = 0; s < XGRP; s++) {
                int rb = s_rows[s];
                if (rb >= 0) {
                    float4 v = make_float4(av[s].x + an.x, av[s].y + an.y,
                                           av[s].z + an.z, av[s].w + an.w);
                    *(float4*)(out_x + ((size_t)rb * K_ + kk) * E_ + col) = v;
                }
            }
        }
    }
}

// ---------------- launcher ----------------
extern "C" void kernel_launch(void* const* d_in, const int* in_sizes, int n_in,
                              void* d_out, int out_size) {
    const float* obs         = (const float*)d_in[0];
    const float* neis        = (const float*)d_in[1];
    const float* init_trajs  = (const float*)d_in[2];
    const float* W_self      = (const float*)d_in[3];
    const float* b_self      = (const float*)d_in[4];
    const float* W_nei       = (const float*)d_in[5];
    const float* b_nei       = (const float*)d_in[6];
    const int*   self_labels = (const int*)d_in[7];
    const int*   nei_labels  = (const int*)d_in[8];

    float* out_x   = (float*)d_out;
    float* out_nei = (float*)d_out + X_ELEMS;

    cudaFuncSetAttribute(k_gemm_mma, cudaFuncAttributeMaxDynamicSharedMemorySize, SMEM_BYTES);

    k_prep<<<K1_GRID, 256>>>(nei_labels, W_nei, init_trajs, W_self, b_self, self_labels);
    k_prefix<<<1, 256>>>();
    k_scattercopy<<<NBLK_, 256>>>(neis, nei_labels);
    k_gemm_mma<<<GEMM_GRID, 256, SMEM_BYTES>>>(b_nei, obs, W_self, out_nei, out_x);
}

// round 13
// speedup vs baseline: 1.9318x; 1.0959x over previous
#include <cuda_runtime.h>
#include <cuda_bf16.h>
#include <cstdint>

typedef unsigned long long u64;

// Problem constants
#define B_      2048
#define N_      64
#define OBS_    8
#define PRED_   12
#define IN_     6
#define E_      512
#define C_      6
#define CN_     7          // C + 1
#define K_      20
#define DSELF_  120        // IN*(OBS+PRED)
#define DNEI_   48         // IN*OBS
#define RTOT_   (B_ * N_)  // 131072
#define NBLK_   (RTOT_ / 256)   // 512
#define EPSF    1e-4f

#define KP2_    96         // packed row: [hi(48) | lo(48)] bf16
#define ROW2_   (KP2_ * 2) // 192 bytes per packed row
#define X_ELEMS ((size_t)B_ * K_ * E_)   // 20,971,520

// Fixed per-class segments: class c owns rows [c*RTOT_, c*RTOT_+cnt_c).
// Packing order within a class is non-deterministic (block-level atomics), but
// every row's output is computed identically regardless of packed position and
// scattered back via perm -> outputs are bitwise deterministic.
#define CSEG_ROWS ((size_t)CN_ * RTOT_)   // 917504 rows

// ---------------- scratch (__device__ globals; no allocation) ----------------
// 256B alignment: required for 16B cp.async sources.
__device__ __align__(256) __nv_bfloat16 g_Ab[CSEG_ROWS * KP2_];     // ~176 MB
__device__ __align__(256) __nv_bfloat16 g_Wb[(size_t)CN_ * E_ * KP2_];
__device__ __align__(256) int   g_perm[CSEG_ROWS + 128];
__device__ __align__(256) int   g_cur[CN_];    // running per-class counts (= totals after scatter)
__device__ __align__(256) float g_anchor[(size_t)C_ * K_ * E_];
// x-path binning
__device__ __align__(256) int   g_xperm[B_];
__device__ __align__(256) int   g_xcnt[C_];
__device__ __align__(256) int   g_xoff[C_];

// ---------------- kernel 0: zero the class counters ----------------
__global__ void k_init() {
    if (threadIdx.x < CN_) g_cur[threadIdx.x] = 0;
}

// ---------------- kernel 1 (fused): scatter+split | weight split | anchor | xbin ----
#define WPREP_BLKS ((CN_ * E_ + 255) / 256)    // 14
#define ANCH_BLKS  (C_ * K_)                   // 120
#define K1_GRID    (NBLK_ + WPREP_BLKS + ANCH_BLKS + 1)

__global__ void k_fused(const float* __restrict__ neis,
                        const int*   __restrict__ nei_labels,
                        const float* __restrict__ W_nei,
                        const float* __restrict__ init_trajs,
                        const float* __restrict__ W_self,
                        const float* __restrict__ b_self,
                        const int*   __restrict__ self_labels) {
    int tid = threadIdx.x;
    if (blockIdx.x < NBLK_) {
        // ---- scatter + transform + bf16 hi/lo split copy ----
        __shared__ int s_hist[CN_], s_cur[CN_];
        __shared__ int s_pos[256];
        int blk = blockIdx.x;
        if (tid < CN_) s_hist[tid] = 0;
        __syncthreads();
        int row = blk * 256 + tid;
        int c   = nei_labels[row];
        atomicAdd(&s_hist[c], 1);
        __syncthreads();
        if (tid < CN_)
            s_cur[tid] = s_hist[tid] ? atomicAdd(&g_cur[tid], s_hist[tid]) : 0;
        __syncthreads();
        int pos = c * RTOT_ + atomicAdd(&s_cur[c], 1);
        s_pos[tid]  = pos;
        g_perm[pos] = row;
        __syncthreads();

#pragma unroll
        for (int it = 0; it < 12; it++) {
            int idx = it * 256 + tid;
            int r = idx / 12, q = idx % 12;       // q: float4 chunk 0..11
            float4 v = *(const float4*)(neis + ((size_t)blk * 256 + r) * DNEI_ + q * 4);
            v.x = (v.x >= 0.f) ? 1.f / (v.x + EPSF) : 1.f / (v.x - EPSF);
            v.y = (v.y >= 0.f) ? 1.f / (v.y + EPSF) : 1.f / (v.y - EPSF);
            v.z = (v.z >= 0.f) ? 1.f / (v.z + EPSF) : 1.f / (v.z - EPSF);
            v.w = (v.w >= 0.f) ? 1.f / (v.w + EPSF) : 1.f / (v.w - EPSF);

            __nv_bfloat16 hx = __float2bfloat16(v.x), hy = __float2bfloat16(v.y);
            __nv_bfloat16 hz = __float2bfloat16(v.z), hw = __float2bfloat16(v.w);
            __nv_bfloat16 lx = __float2bfloat16(v.x - __bfloat162float(hx));
            __nv_bfloat16 ly = __float2bfloat16(v.y - __bfloat162float(hy));
            __nv_bfloat16 lz = __float2bfloat16(v.z - __bfloat162float(hz));
            __nv_bfloat16 lw = __float2bfloat16(v.w - __bfloat162float(hw));

            uint32_t h01 = ((uint32_t)__bfloat16_as_ushort(hy) << 16) | __bfloat16_as_ushort(hx);
            uint32_t h23 = ((uint32_t)__bfloat16_as_ushort(hw) << 16) | __bfloat16_as_ushort(hz);
            uint32_t l01 = ((uint32_t)__bfloat16_as_ushort(ly) << 16) | __bfloat16_as_ushort(lx);
            uint32_t l23 = ((uint32_t)__bfloat16_as_ushort(lw) << 16) | __bfloat16_as_ushort(lz);

            char* rb = (char*)g_Ab + (size_t)s_pos[r] * ROW2_;
            *(uint2*)(rb + q * 8)       = make_uint2(h01, h23);   // hi (k 0..47)
            *(uint2*)(rb + 96 + q * 8)  = make_uint2(l01, l23);   // lo
        }
    } else if (blockIdx.x < NBLK_ + WPREP_BLKS) {
        // ---- weight hi/lo split ----
        int g = (blockIdx.x - NBLK_) * 256 + tid;   // (c, n)
        if (g >= CN_ * E_) return;
        int c = g / E_, n = g % E_;
        char* rb = (char*)g_Wb + (size_t)g * ROW2_;
        const float* W = W_nei + (size_t)c * DNEI_ * E_ + n;
#pragma unroll 8
        for (int k = 0; k < DNEI_; k++) {
            float w = W[(size_t)k * E_];
            __nv_bfloat16 h = __float2bfloat16(w);
            __nv_bfloat16 l = __float2bfloat16(w - __bfloat162float(h));
            *(__nv_bfloat16*)(rb + k * 2)      = h;   // Whi
            *(__nv_bfloat16*)(rb + 96 + k * 2) = l;   // Wlo
        }
    } else if (blockIdx.x < NBLK_ + WPREP_BLKS + ANCH_BLKS) {
        // ---- anchor: anchor[c,k,:] = it[c,k] @ W_self[c][48:] + b_self[c] ----
        int bid = blockIdx.x - NBLK_ - WPREP_BLKS;
        int c  = bid / K_;
        int kk = bid % K_;
        __shared__ float tr[PRED_ * IN_];   // 72
        if (tid < PRED_ * IN_)
            tr[tid] = init_trajs[((size_t)c * K_ + kk) * (PRED_ * IN_) + tid];
        __syncthreads();
        if (tid < 128) {
            int col = tid * 4;
            const float* bb = b_self + (size_t)c * E_ + col;
            float4 acc = *(const float4*)bb;
            const float* W = W_self + ((size_t)c * DSELF_ + DNEI_) * E_ + col;
#pragma unroll 8
            for (int j = 0; j < PRED_ * IN_; j++) {
                float  t = tr[j];
                float4 w = *(const float4*)(W + (size_t)j * E_);
                acc.x += t * w.x; acc.y += t * w.y; acc.z += t * w.z; acc.w += t * w.w;
            }
            *(float4*)(g_anchor + ((size_t)c * K_ + kk) * E_ + col) = acc;
        }
    } else {
        // ---- xbin: bin self_labels (single block, deterministic) ----
        __shared__ int sc2[C_][256];
        __shared__ int s_tot[C_];
        __shared__ int s_off[C_];
        int base = tid * 8;                       // 256 x 8 = 2048
#pragma unroll
        for (int c = 0; c < C_; c++) {
            int n = 0;
#pragma unroll
            for (int i = 0; i < 8; i++) n += (self_labels[base + i] == c);
            sc2[c][tid] = n;
        }
        __syncthreads();
        int w = tid >> 5, lane = tid & 31;
        if (w < C_) {
            int acc = 0;
#pragma unroll
            for (int seg = 0; seg < 8; seg++) {
                int v = sc2[w][seg * 32 + lane];
                int s = v;
#pragma unroll
                for (int d = 1; d < 32; d <<= 1) {
                    int t = __shfl_up_sync(0xffffffffu, s, d);
                    if (lane >= d) s += t;
                }
                sc2[w][seg * 32 + lane] = acc + s - v;
                acc += __shfl_sync(0xffffffffu, s, 31);
            }
            if (lane == 0) s_tot[w] = acc;
        }
        __syncthreads();
        if (tid == 0) {
            int a = 0;
            for (int c = 0; c < C_; c++) {
                s_off[c] = a; g_xoff[c] = a; g_xcnt[c] = s_tot[c]; a += s_tot[c];
            }
        }
        __syncthreads();
#pragma unroll
        for (int c = 0; c < C_; c++) {
            int p = s_off[c] + sc2[c][tid];
#pragma unroll
            for (int i = 0; i < 8; i++)
                if (self_labels[base + i] == c) g_xperm[p++] = base + i;
        }
    }
}

// ================= mma.sync / cp.async helpers =================
__device__ __forceinline__ uint32_t smem_u32(const void* p) {
    uint32_t a;
    asm("{ .reg .u64 t; cvta.to.shared.u64 t, %1; cvt.u32.u64 %0, t; }" : "=r"(a) : "l"(p));
    return a;
}
__device__ __forceinline__ void cp_async16(uint32_t dst, const void* src, int src_size) {
    asm volatile("cp.async.cg.shared.global [%0], [%1], 16, %2;"
                 :: "r"(dst), "l"(src), "r"(src_size) : "memory");
}
__device__ __forceinline__ void cp_commit() {
    asm volatile("cp.async.commit_group;" ::: "memory");
}
__device__ __forceinline__ void cp_wait_all() {
    asm volatile("cp.async.wait_group 0;" ::: "memory");
}
__device__ __forceinline__ void ldsm_x4(uint32_t* r, uint32_t addr) {
    asm volatile("ldmatrix.sync.aligned.m8n8.x4.shared.b16 {%0,%1,%2,%3}, [%4];"
                 : "=r"(r[0]), "=r"(r[1]), "=r"(r[2]), "=r"(r[3]) : "r"(addr));
}
__device__ __forceinline__ void mma16816(float* c, const uint32_t* a, uint32_t b0, uint32_t b1) {
    asm volatile("mma.sync.aligned.m16n8k16.row.col.f32.bf16.bf16.f32 "
                 "{%0,%1,%2,%3}, {%4,%5,%6,%7}, {%8,%9}, {%0,%1,%2,%3};"
                 : "+f"(c[0]), "+f"(c[1]), "+f"(c[2]), "+f"(c[3])
                 : "r"(a[0]), "r"(a[1]), "r"(a[2]), "r"(a[3]), "r"(b0), "r"(b1));
}

// ---------------- kernel 2: persistent GEMM + fused x-path tail ----------------
#define MT 128
#define NT 128
#define GEMM_MAX_MTILES ((RTOT_ / MT) + CN_)   // 1031
#define JOBS_ 14
#define GEMM_CHUNKS ((GEMM_MAX_MTILES + JOBS_ - 1) / JOBS_)  // 74
#define GEMM_GRID (GEMM_CHUNKS * 4)            // 296 = 148 SMs x occ 2
#define STRIDE 208                             // conflict-free LDSM stride
#define TILE_SB (128 * STRIDE)                 // 26624
#define HDR_B 1024                             // per buffer: perm 512 + bias 512
#define SMEM_BYTES (2 * HDR_B + 2 * TILE_SB + TILE_SB)   // 81920
#define XGRP 8

__global__ void __launch_bounds__(256, 2)
k_gemm_mma(const float* __restrict__ b_nei,
           const float* __restrict__ obs,
           const float* __restrict__ W_self,
           float*       __restrict__ out_nei,
           float*       __restrict__ out_x) {
    int nt    = blockIdx.x & 3;
    int chunk = blockIdx.x >> 2;
    int mid0  = chunk * JOBS_;

    int cnts[CN_];
#pragma unroll
    for (int cc = 0; cc < CN_; cc++) cnts[cc] = g_cur[cc];

    extern __shared__ char smem[];
    char* hdrb  = smem;                          // 2 x HDR_B
    char* a_smb = smem + 2 * HDR_B;              // 2 x TILE_SB
    char* b_sm  = smem + 2 * HDR_B + 2 * TILE_SB;

    int tid  = threadIdx.x;
    int lane = tid & 31;
    int wid  = tid >> 5;
    int wm   = wid & 1;          // 2 warp rows (64 rows each)
    int wn   = wid >> 1;         // 4 warp cols (32 cols each)

    // per-thread cp.async geometry: row tid>>1, 16B chunks h..h+5
    int pr = tid >> 1;
    int ph = (tid & 1) * 6;

    auto map_job = [&](int mid, int& c, int& mt) -> bool {
        int acc = 0;
#pragma unroll
        for (int cc = 0; cc < CN_; cc++) {
            int t = (cnts[cc] + MT - 1) >> 7;
            if (mid < acc + t) { c = cc; mt = mid - acc; return true; }
            acc += t;
        }
        return false;
    };

    auto prefetch_A = [&](int buf, int c, int mt) {
        int m0 = mt * MT;
        int ok = (m0 + pr < cnts[c]) ? 16 : 0;
        const char* src = (const char*)g_Ab
                        + (size_t)(ok ? (c * RTOT_ + m0 + pr) : 0) * ROW2_;
        uint32_t dst = smem_u32(a_smb + buf * TILE_SB)
                     + (uint32_t)pr * STRIDE + (uint32_t)ph * 16;
#pragma unroll
        for (int i = 0; i < 6; i++)
            cp_async16(dst + i * 16, src + (ph + i) * 16, ok);
    };
    auto prefetch_hdr = [&](int buf, int c, int mt) {
        if (tid < 32) {
            // c*RTOT_ and mt*MT are multiples of 128 -> source 512B aligned
            const char* src = (const char*)g_perm + ((size_t)c * RTOT_ + mt * MT) * 4 + tid * 16;
            cp_async16(smem_u32(hdrb + buf * HDR_B) + tid * 16, src, 16);
        } else if (tid < 64) {
            int l = tid - 32;
            const char* src = (const char*)b_nei + ((size_t)c * E_ + nt * NT) * 4 + l * 16;
            cp_async16(smem_u32(hdrb + buf * HDR_B) + 512 + l * 16, src, 16);
        }
    };
    auto prefetch_B = [&](int c) {
        const char* src = (const char*)g_Wb + ((size_t)c * E_ + nt * NT + pr) * ROW2_;
        uint32_t dst = smem_u32(b_sm) + (uint32_t)pr * STRIDE + (uint32_t)ph * 16;
#pragma unroll
        for (int i = 0; i < 6; i++)
            cp_async16(dst + i * 16, src + (ph + i) * 16, 16);
    };

    // prologue
    int c0, mt0;
    if (map_job(mid0, c0, mt0)) {
        prefetch_A(0, c0, mt0);
        prefetch_hdr(0, c0, mt0);
        prefetch_B(c0);
        cp_commit();

        int cur = 0, bclass = c0;

        for (int j = 0; j < JOBS_; j++) {
            int mid = mid0 + j;
            int c, mt;
            if (!map_job(mid, c, mt)) break;
            int cnt = cnts[c];

            cp_wait_all();          // this thread's copies for job j done
            __syncthreads();        // all threads' copies + prev compute done

            // B reload on class change (uniform branch; per-thread wait_group
            // needs the trailing __syncthreads for cross-thread visibility)
            if (c != bclass) {
                prefetch_B(c);
                cp_commit();
                cp_wait_all();
                __syncthreads();
                bclass = c;
            }

            // prefetch job j+1 into alternate buffers — overlaps compute
            if (j + 1 < JOBS_) {
                int cn, mtn;
                if (map_job(mid + 1, cn, mtn)) {
                    prefetch_A(cur ^ 1, cn, mtn);
                    prefetch_hdr(cur ^ 1, cn, mtn);
                    cp_commit();
                }
            }

            const int*   s_perm = (const int*)(hdrb + cur * HDR_B);
            const float* s_bias = (const float*)(hdrb + cur * HDR_B + 512);

            // ---- compute ----
            uint32_t a_u32 = smem_u32(a_smb + cur * TILE_SB);
            uint32_t b_u32 = smem_u32(b_sm);
            uint32_t a_base = a_u32 + (uint32_t)(wm * 64 + (lane & 15)) * STRIDE
                                    + ((lane >> 4) << 4);
            uint32_t b_base = b_u32 + (uint32_t)(wn * 32 + ((lane >> 4) << 3) + (lane & 7)) * STRIDE
                                    + (((lane >> 3) & 1) << 4);

            float acc[4][4][4];
#pragma unroll
            for (int i = 0; i < 4; i++)
#pragma unroll
                for (int jj = 0; jj < 4; jj++)
#pragma unroll
                    for (int q = 0; q < 4; q++) acc[i][jj][q] = 0.f;

#pragma unroll
            for (int kc = 0; kc < 3; kc++) {       // 48 = 3 x 16
                uint32_t kb = kc * 32;
                uint32_t Bh0[4], Bh1[4], Bl0[4], Bl1[4];
                ldsm_x4(Bh0, b_base + kb);                       // Whi, ntiles 0,1
                ldsm_x4(Bh1, b_base + 16 * STRIDE + kb);         // Whi, ntiles 2,3
                ldsm_x4(Bl0, b_base + 96 + kb);                  // Wlo, ntiles 0,1
                ldsm_x4(Bl1, b_base + 16 * STRIDE + 96 + kb);    // Wlo, ntiles 2,3
#pragma unroll
                for (int mi = 0; mi < 4; mi++) {
                    uint32_t Ah[4], Al[4];
                    ldsm_x4(Ah, a_base + (uint32_t)mi * 16 * STRIDE + kb);
                    ldsm_x4(Al, a_base + (uint32_t)mi * 16 * STRIDE + 96 + kb);
                    // hi*hi
                    mma16816(acc[mi][0], Ah, Bh0[0], Bh0[1]);
                    mma16816(acc[mi][1], Ah, Bh0[2], Bh0[3]);
                    mma16816(acc[mi][2], Ah, Bh1[0], Bh1[1]);
                    mma16816(acc[mi][3], Ah, Bh1[2], Bh1[3]);
                    // lo*hi
                    mma16816(acc[mi][0], Al, Bh0[0], Bh0[1]);
                    mma16816(acc[mi][1], Al, Bh0[2], Bh0[3]);
                    mma16816(acc[mi][2], Al, Bh1[0], Bh1[1]);
                    mma16816(acc[mi][3], Al, Bh1[2], Bh1[3]);
                    // hi*lo
                    mma16816(acc[mi][0], Ah, Bl0[0], Bl0[1]);
                    mma16816(acc[mi][1], Ah, Bl0[2], Bl0[3]);
                    mma16816(acc[mi][2], Ah, Bl1[0], Bl1[1]);
                    mma16816(acc[mi][3], Ah, Bl1[2], Bl1[3]);
                }
            }

            // ---- epilogue ----
            int g = lane >> 2, t4 = lane & 3;
            int m0 = mt * MT;
#pragma unroll
            for (int mi = 0; mi < 4; mi++) {
#pragma unroll
                for (int half = 0; half < 2; half++) {
                    int rloc = wm * 64 + mi * 16 + g + half * 8;
                    if (m0 + rloc < cnt) {
                        int rg = s_perm[rloc];
                        float* orow = out_nei + (size_t)rg * E_ + nt * NT + wn * 32;
#pragma unroll
                        for (int ni = 0; ni < 4; ni++) {
                            int colo = ni * 8 + t4 * 2;
                            float2 v = make_float2(
                                acc[mi][ni][half * 2 + 0] + s_bias[wn * 32 + colo],
                                acc[mi][ni][half * 2 + 1] + s_bias[wn * 32 + colo + 1]);
                            *(float2*)(orow + colo) = v;
                        }
                    }
                }
            }

            cur ^= 1;
        }
    }

    // ================== fused x-path tail ==================
    {
        int mid = blockIdx.x;
        int c = -1, gt = 0, acc_t = 0;
#pragma unroll
        for (int cc = 0; cc < C_; cc++) {
            int t = (g_xcnt[cc] + XGRP - 1) / XGRP;
            if (c < 0 && mid < acc_t + t) { c = cc; gt = mid - acc_t; }
            acc_t += t;
        }
        if (c < 0) return;
        int cnt = g_xcnt[c];
        int xo  = g_xoff[c];
        int s0  = gt * XGRP;
        int m   = min(XGRP, cnt - s0);

        __syncthreads();                      // done with GEMM smem
        int*   s_rows = (int*)smem;           // [8]
        float (*s_obs)[DNEI_] = (float(*)[DNEI_])(smem + 32);

        if (tid < XGRP)
            s_rows[tid] = (tid < m) ? g_xperm[xo + s0 + tid] : -1;
        __syncthreads();
        if (tid < 96) {
            int s = tid / 12, q = tid % 12;
            int rb = s_rows[s];
            float4 v = make_float4(0.f, 0.f, 0.f, 0.f);
            if (rb >= 0) v = *(const float4*)(obs + (size_t)rb * DNEI_ + q * 4);
            *(float4*)(&s_obs[s][q * 4]) = v;
        }
        __syncthreads();

        int ct   = tid & 127;
        int half = tid >> 7;
        int col  = ct * 4;
        const float* W = W_self + (size_t)c * DSELF_ * E_ + col;
        float4 a0 = make_float4(0,0,0,0), a1 = a0, a2 = a0, a3 = a0;
        float4 a4 = a0, a5 = a0, a6 = a0, a7 = a0;
#pragma unroll 4
        for (int j = 0; j < DNEI_; j++) {
            float4 w4 = *(const float4*)(W + (size_t)j * E_);
            float t0 = s_obs[0][j], t1 = s_obs[1][j], t2 = s_obs[2][j], t3 = s_obs[3][j];
            float t4 = s_obs[4][j], t5 = s_obs[5][j], t6 = s_obs[6][j], t7 = s_obs[7][j];
            a0.x += t0*w4.x; a0.y += t0*w4.y; a0.z += t0*w4.z; a0.w += t0*w4.w;
            a1.x += t1*w4.x; a1.y += t1*w4.y; a1.z += t1*w4.z; a1.w += t1*w4.w;
            a2.x += t2*w4.x; a2.y += t2*w4.y; a2.z += t2*w4.z; a2.w += t2*w4.w;
            a3.x += t3*w4.x; a3.y += t3*w4.y; a3.z += t3*w4.z; a3.w += t3*w4.w;
            a4.x += t4*w4.x; a4.y += t4*w4.y; a4.z += t4*w4.z; a4.w += t4*w4.w;
            a5.x += t5*w4.x; a5.y += t5*w4.y; a5.z += t5*w4.z; a5.w += t5*w4.w;
            a6.x += t6*w4.x; a6.y += t6*w4.y; a6.z += t6*w4.z; a6.w += t6*w4.w;
            a7.x += t7*w4.x; a7.y += t7*w4.y; a7.z += t7*w4.z; a7.w += t7*w4.w;
        }

        float4 av[XGRP] = {a0, a1, a2, a3, a4, a5, a6, a7};
        int kk0 = half * (K_ / 2), kk1 = kk0 + (K_ / 2);
#pragma unroll
        for (int kk = kk0; kk < kk1; kk++) {
            float4 an = *(const float4*)(g_anchor + ((size_t)c * K_ + kk) * E_ + col);
#pragma unroll
            for (int s = 0; s < XGRP; s++) {
                int rb = s_rows[s];
                if (rb >= 0) {
                    float4 v = make_float4(av[s].x + an.x, av[s].y + an.y,
                                           av[s].z + an.z, av[s].w + an.w);
                    *(float4*)(out_x + ((size_t)rb * K_ + kk) * E_ + col) = v;
                }
            }
        }
    }
}

// ---------------- launcher ----------------
extern "C" void kernel_launch(void* const* d_in, const int* in_sizes, int n_in,
                              void* d_out, int out_size) {
    const float* obs         = (const float*)d_in[0];
    const float* neis        = (const float*)d_in[1];
    const float* init_trajs  = (const float*)d_in[2];
    const float* W_self      = (const float*)d_in[3];
    const float* b_self      = (const float*)d_in[4];
    const float* W_nei       = (const float*)d_in[5];
    const float* b_nei       = (const float*)d_in[6];
    const int*   self_labels = (const int*)d_in[7];
    const int*   nei_labels  = (const int*)d_in[8];

    float* out_x   = (float*)d_out;
    float* out_nei = (float*)d_out + X_ELEMS;

    cudaFuncSetAttribute(k_gemm_mma, cudaFuncAttributeMaxDynamicSharedMemorySize, SMEM_BYTES);

    k_init<<<1, 32>>>();
    k_fused<<<K1_GRID, 256>>>(neis, nei_labels, W_nei, init_trajs,
                              W_self, b_self, self_labels);
    k_gemm_mma<<<GEMM_GRID, 256, SMEM_BYTES>>>(b_nei, obs, W_self, out_nei, out_x);
}

// round 14
// speedup vs baseline: 2.0645x; 1.0687x over previous
#include <cuda_runtime.h>
#include <cuda_fp16.h>
#include <cstdint>

typedef unsigned long long u64;

// Problem constants
#define B_      2048
#define N_      64
#define OBS_    8
#define PRED_   12
#define IN_     6
#define E_      512
#define C_      6
#define CN_     7          // C + 1
#define K_      20
#define DSELF_  120        // IN*(OBS+PRED)
#define DNEI_   48         // IN*OBS
#define RTOT_   (B_ * N_)  // 131072
#define NBLK_   (RTOT_ / 256)   // 512
#define EPSF    1e-4f

#define KP2_    96         // packed A row: [hi(48) | lo(48)] fp16
#define ROW2_   (KP2_ * 2) // 192 bytes per packed A row
#define WROW_   96         // packed W row: [hi(48)] fp16 = 96 bytes
#define X_ELEMS ((size_t)B_ * K_ * E_)   // 20,971,520

// Fixed per-class segments: class c owns rows [c*RTOT_, c*RTOT_+cnt_c).
#define CSEG_ROWS ((size_t)CN_ * RTOT_)   // 917504 rows

// ---------------- scratch (__device__ globals; no allocation) ----------------
__device__ __align__(256) __half g_Ab[CSEG_ROWS * KP2_];            // ~176 MB
__device__ __align__(256) __half g_Wb[(size_t)CN_ * E_ * (WROW_/2)];
__device__ __align__(256) int    g_perm[CSEG_ROWS + 128];
__device__ __align__(256) int    g_cur[CN_];   // zero at launch; reset by GEMM block 0
__device__ __align__(256) float  g_anchor[(size_t)C_ * K_ * E_];
// x-path binning
__device__ __align__(256) int    g_xperm[B_];
__device__ __align__(256) int    g_xcnt[C_];
__device__ __align__(256) int    g_xoff[C_];

// ---------------- kernel 1 (fused): scatter+split | weight split | anchor | xbin ----
#define WPREP_BLKS ((CN_ * E_ + 255) / 256)    // 14
#define ANCH_BLKS  (C_ * K_)                   // 120
#define K1_GRID    (NBLK_ + WPREP_BLKS + ANCH_BLKS + 1)

__global__ void k_fused(const float* __restrict__ neis,
                        const int*   __restrict__ nei_labels,
                        const float* __restrict__ W_nei,
                        const float* __restrict__ init_trajs,
                        const float* __restrict__ W_self,
                        const float* __restrict__ b_self,
                        const int*   __restrict__ self_labels) {
    int tid = threadIdx.x;
    if (blockIdx.x < NBLK_) {
        // ---- scatter + transform + fp16 hi/lo split copy ----
        __shared__ int s_hist[CN_], s_cur[CN_];
        __shared__ int s_pos[256];
        int blk = blockIdx.x;
        if (tid < CN_) s_hist[tid] = 0;
        __syncthreads();
        int row = blk * 256 + tid;
        int c   = nei_labels[row];
        atomicAdd(&s_hist[c], 1);
        __syncthreads();
        if (tid < CN_)
            s_cur[tid] = s_hist[tid] ? atomicAdd(&g_cur[tid], s_hist[tid]) : 0;
        __syncthreads();
        int pos = c * RTOT_ + atomicAdd(&s_cur[c], 1);
        s_pos[tid]  = pos;
        g_perm[pos] = row;
        __syncthreads();

#pragma unroll
        for (int it = 0; it < 12; it++) {
            int idx = it * 256 + tid;
            int r = idx / 12, q = idx % 12;       // q: float4 chunk 0..11
            float4 v = *(const float4*)(neis + ((size_t)blk * 256 + r) * DNEI_ + q * 4);
            v.x = (v.x >= 0.f) ? 1.f / (v.x + EPSF) : 1.f / (v.x - EPSF);
            v.y = (v.y >= 0.f) ? 1.f / (v.y + EPSF) : 1.f / (v.y - EPSF);
            v.z = (v.z >= 0.f) ? 1.f / (v.z + EPSF) : 1.f / (v.z - EPSF);
            v.w = (v.w >= 0.f) ? 1.f / (v.w + EPSF) : 1.f / (v.w - EPSF);

            __half hx = __float2half_rn(v.x), hy = __float2half_rn(v.y);
            __half hz = __float2half_rn(v.z), hw = __float2half_rn(v.w);
            __half lx = __float2half_rn(v.x - __half2float(hx));
            __half ly = __float2half_rn(v.y - __half2float(hy));
            __half lz = __float2half_rn(v.z - __half2float(hz));
            __half lw = __float2half_rn(v.w - __half2float(hw));

            uint32_t h01 = ((uint32_t)__half_as_ushort(hy) << 16) | __half_as_ushort(hx);
            uint32_t h23 = ((uint32_t)__half_as_ushort(hw) << 16) | __half_as_ushort(hz);
            uint32_t l01 = ((uint32_t)__half_as_ushort(ly) << 16) | __half_as_ushort(lx);
            uint32_t l23 = ((uint32_t)__half_as_ushort(lw) << 16) | __half_as_ushort(lz);

            char* rb = (char*)g_Ab + (size_t)s_pos[r] * ROW2_;
            *(uint2*)(rb + q * 8)       = make_uint2(h01, h23);   // hi (k 0..47)
            *(uint2*)(rb + 96 + q * 8)  = make_uint2(l01, l23);   // lo
        }
    } else if (blockIdx.x < NBLK_ + WPREP_BLKS) {
        // ---- weight fp16 hi (only hi needed for the 2-term split) ----
        int g = (blockIdx.x - NBLK_) * 256 + tid;   // (c, n)
        if (g >= CN_ * E_) return;
        int c = g / E_, n = g % E_;
        char* rb = (char*)g_Wb + (size_t)g * WROW_;
        const float* W = W_nei + (size_t)c * DNEI_ * E_ + n;
#pragma unroll 8
        for (int k = 0; k < DNEI_; k++)
            *(__half*)(rb + k * 2) = __float2half_rn(W[(size_t)k * E_]);
    } else if (blockIdx.x < NBLK_ + WPREP_BLKS + ANCH_BLKS) {
        // ---- anchor: anchor[c,k,:] = it[c,k] @ W_self[c][48:] + b_self[c] ----
        int bid = blockIdx.x - NBLK_ - WPREP_BLKS;
        int c  = bid / K_;
        int kk = bid % K_;
        __shared__ float tr[PRED_ * IN_];   // 72
        if (tid < PRED_ * IN_)
            tr[tid] = init_trajs[((size_t)c * K_ + kk) * (PRED_ * IN_) + tid];
        __syncthreads();
        if (tid < 128) {
            int col = tid * 4;
            const float* bb = b_self + (size_t)c * E_ + col;
            float4 acc = *(const float4*)bb;
            const float* W = W_self + ((size_t)c * DSELF_ + DNEI_) * E_ + col;
#pragma unroll 8
            for (int j = 0; j < PRED_ * IN_; j++) {
                float  t = tr[j];
                float4 w = *(const float4*)(W + (size_t)j * E_);
                acc.x += t * w.x; acc.y += t * w.y; acc.z += t * w.z; acc.w += t * w.w;
            }
            *(float4*)(g_anchor + ((size_t)c * K_ + kk) * E_ + col) = acc;
        }
    } else {
        // ---- xbin: bin self_labels (single block, deterministic) ----
        __shared__ int sc2[C_][256];
        __shared__ int s_tot[C_];
        __shared__ int s_off[C_];
        int base = tid * 8;                       // 256 x 8 = 2048
#pragma unroll
        for (int c = 0; c < C_; c++) {
            int n = 0;
#pragma unroll
            for (int i = 0; i < 8; i++) n += (self_labels[base + i] == c);
            sc2[c][tid] = n;
        }
        __syncthreads();
        int w = tid >> 5, lane = tid & 31;
        if (w < C_) {
            int acc = 0;
#pragma unroll
            for (int seg = 0; seg < 8; seg++) {
                int v = sc2[w][seg * 32 + lane];
                int s = v;
#pragma unroll
                for (int d = 1; d < 32; d <<= 1) {
                    int t = __shfl_up_sync(0xffffffffu, s, d);
                    if (lane >= d) s += t;
                }
                sc2[w][seg * 32 + lane] = acc + s - v;
                acc += __shfl_sync(0xffffffffu, s, 31);
            }
            if (lane == 0) s_tot[w] = acc;
        }
        __syncthreads();
        if (tid == 0) {
            int a = 0;
            for (int c = 0; c < C_; c++) {
                s_off[c] = a; g_xoff[c] = a; g_xcnt[c] = s_tot[c]; a += s_tot[c];
            }
        }
        __syncthreads();
#pragma unroll
        for (int c = 0; c < C_; c++) {
            int p = s_off[c] + sc2[c][tid];
#pragma unroll
            for (int i = 0; i < 8; i++)
                if (self_labels[base + i] == c) g_xperm[p++] = base + i;
        }
    }
}

// ================= mma.sync / cp.async helpers =================
__device__ __forceinline__ uint32_t smem_u32(const void* p) {
    uint32_t a;
    asm("{ .reg .u64 t; cvta.to.shared.u64 t, %1; cvt.u32.u64 %0, t; }" : "=r"(a) : "l"(p));
    return a;
}
__device__ __forceinline__ void cp_async16(uint32_t dst, const void* src, int src_size) {
    asm volatile("cp.async.cg.shared.global [%0], [%1], 16, %2;"
                 :: "r"(dst), "l"(src), "r"(src_size) : "memory");
}
__device__ __forceinline__ void cp_commit() {
    asm volatile("cp.async.commit_group;" ::: "memory");
}
__device__ __forceinline__ void cp_wait_all() {
    asm volatile("cp.async.wait_group 0;" ::: "memory");
}
__device__ __forceinline__ void ldsm_x4(uint32_t* r, uint32_t addr) {
    asm volatile("ldmatrix.sync.aligned.m8n8.x4.shared.b16 {%0,%1,%2,%3}, [%4];"
                 : "=r"(r[0]), "=r"(r[1]), "=r"(r[2]), "=r"(r[3]) : "r"(addr));
}
__device__ __forceinline__ void mma16816h(float* c, const uint32_t* a, uint32_t b0, uint32_t b1) {
    asm volatile("mma.sync.aligned.m16n8k16.row.col.f32.f16.f16.f32 "
                 "{%0,%1,%2,%3}, {%4,%5,%6,%7}, {%8,%9}, {%0,%1,%2,%3};"
                 : "+f"(c[0]), "+f"(c[1]), "+f"(c[2]), "+f"(c[3])
                 : "r"(a[0]), "r"(a[1]), "r"(a[2]), "r"(a[3]), "r"(b0), "r"(b1));
}

// ---------------- kernel 2: persistent GEMM (fp16 2-term) + fused x-path tail ----
// acc += A_hi*B_hi + A_lo*B_hi  (dropped a_hi*b_lo ~ a*b*2^-12 — within tolerance)
#define MT 128
#define NT 128
#define GEMM_MAX_MTILES ((RTOT_ / MT) + CN_)   // 1031
#define JOBS_ 14
#define GEMM_CHUNKS ((GEMM_MAX_MTILES + JOBS_ - 1) / JOBS_)  // 74
#define GEMM_GRID (GEMM_CHUNKS * 4)            // 296 = 148 SMs x occ 2
#define STRIDE_A 208                           // conflict-free LDSM stride (A, 192B rows)
#define STRIDE_B 112                           // conflict-free LDSM stride (B, 96B rows)
#define TILE_A   (128 * STRIDE_A)              // 26624
#define TILE_BB  (128 * STRIDE_B)              // 14336
#define HDR_B 1024                             // per buffer: perm 512 + bias 512
#define SMEM_BYTES (2 * HDR_B + 2 * TILE_A + TILE_BB)   // 69632
#define XGRP 8

__global__ void __launch_bounds__(256, 2)
k_gemm_mma(const float* __restrict__ b_nei,
           const float* __restrict__ obs,
           const float* __restrict__ W_self,
           float*       __restrict__ out_nei,
           float*       __restrict__ out_x) {
    int nt    = blockIdx.x & 3;
    int chunk = blockIdx.x >> 2;
    int mid0  = chunk * JOBS_;

    int cnts[CN_];
#pragma unroll
    for (int cc = 0; cc < CN_; cc++) cnts[cc] = g_cur[cc];

    extern __shared__ char smem[];
    char* hdrb  = smem;                          // 2 x HDR_B
    char* a_smb = smem + 2 * HDR_B;              // 2 x TILE_A
    char* b_sm  = smem + 2 * HDR_B + 2 * TILE_A; // 1 x TILE_BB

    int tid  = threadIdx.x;
    int lane = tid & 31;
    int wid  = tid >> 5;
    int wm   = wid & 1;          // 2 warp rows (64 rows each)
    int wn   = wid >> 1;         // 4 warp cols (32 cols each)

    // per-thread cp.async geometry: row tid>>1
    int pr = tid >> 1;
    int phA = (tid & 1) * 6;     // A: 12 chunks/row, 6 per thread
    int phB = (tid & 1) * 3;     // B: 6 chunks/row, 3 per thread

    auto map_job = [&](int mid, int& c, int& mt) -> bool {
        int acc = 0;
#pragma unroll
        for (int cc = 0; cc < CN_; cc++) {
            int t = (cnts[cc] + MT - 1) >> 7;
            if (mid < acc + t) { c = cc; mt = mid - acc; return true; }
            acc += t;
        }
        return false;
    };

    auto prefetch_A = [&](int buf, int c, int mt) {
        int m0 = mt * MT;
        int ok = (m0 + pr < cnts[c]) ? 16 : 0;
        const char* src = (const char*)g_Ab
                        + (size_t)(ok ? (c * RTOT_ + m0 + pr) : 0) * ROW2_;
        uint32_t dst = smem_u32(a_smb + buf * TILE_A)
                     + (uint32_t)pr * STRIDE_A + (uint32_t)phA * 16;
#pragma unroll
        for (int i = 0; i < 6; i++)
            cp_async16(dst + i * 16, src + (phA + i) * 16, ok);
    };
    auto prefetch_hdr = [&](int buf, int c, int mt) {
        if (tid < 32) {
            // c*RTOT_ and mt*MT are multiples of 128 -> source 512B aligned
            const char* src = (const char*)g_perm + ((size_t)c * RTOT_ + mt * MT) * 4 + tid * 16;
            cp_async16(smem_u32(hdrb + buf * HDR_B) + tid * 16, src, 16);
        } else if (tid < 64) {
            int l = tid - 32;
            const char* src = (const char*)b_nei + ((size_t)c * E_ + nt * NT) * 4 + l * 16;
            cp_async16(smem_u32(hdrb + buf * HDR_B) + 512 + l * 16, src, 16);
        }
    };
    auto prefetch_B = [&](int c) {
        const char* src = (const char*)g_Wb + ((size_t)c * E_ + nt * NT + pr) * WROW_;
        uint32_t dst = smem_u32(b_sm) + (uint32_t)pr * STRIDE_B + (uint32_t)phB * 16;
#pragma unroll
        for (int i = 0; i < 3; i++)
            cp_async16(dst + i * 16, src + (phB + i) * 16, 16);
    };

    // prologue
    int c0, mt0;
    if (map_job(mid0, c0, mt0)) {
        prefetch_A(0, c0, mt0);
        prefetch_hdr(0, c0, mt0);
        prefetch_B(c0);
        cp_commit();

        int cur = 0, bclass = c0;

        for (int j = 0; j < JOBS_; j++) {
            int mid = mid0 + j;
            int c, mt;
            if (!map_job(mid, c, mt)) break;
            int cnt = cnts[c];

            cp_wait_all();          // this thread's copies for job j done
            __syncthreads();        // all threads' copies + prev compute done

            // B reload on class change (uniform branch; per-thread wait_group
            // needs the trailing __syncthreads for cross-thread visibility)
            if (c != bclass) {
                prefetch_B(c);
                cp_commit();
                cp_wait_all();
                __syncthreads();
                bclass = c;
            }

            // prefetch job j+1 into alternate buffers — overlaps compute
            if (j + 1 < JOBS_) {
                int cn, mtn;
                if (map_job(mid + 1, cn, mtn)) {
                    prefetch_A(cur ^ 1, cn, mtn);
                    prefetch_hdr(cur ^ 1, cn, mtn);
                    cp_commit();
                }
            }

            const int*   s_perm = (const int*)(hdrb + cur * HDR_B);
            const float* s_bias = (const float*)(hdrb + cur * HDR_B + 512);

            // ---- compute ----
            uint32_t a_u32 = smem_u32(a_smb + cur * TILE_A);
            uint32_t b_u32 = smem_u32(b_sm);
            uint32_t a_base = a_u32 + (uint32_t)(wm * 64 + (lane & 15)) * STRIDE_A
                                    + ((lane >> 4) << 4);
            uint32_t b_base = b_u32 + (uint32_t)(wn * 32 + ((lane >> 4) << 3) + (lane & 7)) * STRIDE_B
                                    + (((lane >> 3) & 1) << 4);

            float acc[4][4][4];
#pragma unroll
            for (int i = 0; i < 4; i++)
#pragma unroll
                for (int jj = 0; jj < 4; jj++)
#pragma unroll
                    for (int q = 0; q < 4; q++) acc[i][jj][q] = 0.f;

#pragma unroll
            for (int kc = 0; kc < 3; kc++) {       // 48 = 3 x 16
                uint32_t kb = kc * 32;
                uint32_t Bh0[4], Bh1[4];
                ldsm_x4(Bh0, b_base + kb);                       // Whi, ntiles 0,1
                ldsm_x4(Bh1, b_base + 16 * STRIDE_B + kb);       // Whi, ntiles 2,3
#pragma unroll
                for (int mi = 0; mi < 4; mi++) {
                    uint32_t Ah[4], Al[4];
                    ldsm_x4(Ah, a_base + (uint32_t)mi * 16 * STRIDE_A + kb);
                    ldsm_x4(Al, a_base + (uint32_t)mi * 16 * STRIDE_A + 96 + kb);
                    // hi*hi
                    mma16816h(acc[mi][0], Ah, Bh0[0], Bh0[1]);
                    mma16816h(acc[mi][1], Ah, Bh0[2], Bh0[3]);
                    mma16816h(acc[mi][2], Ah, Bh1[0], Bh1[1]);
                    mma16816h(acc[mi][3], Ah, Bh1[2], Bh1[3]);
                    // lo*hi
                    mma16816h(acc[mi][0], Al, Bh0[0], Bh0[1]);
                    mma16816h(acc[mi][1], Al, Bh0[2], Bh0[3]);
                    mma16816h(acc[mi][2], Al, Bh1[0], Bh1[1]);
                    mma16816h(acc[mi][3], Al, Bh1[2], Bh1[3]);
                }
            }

            // ---- epilogue ----
            int g = lane >> 2, t4 = lane & 3;
            int m0 = mt * MT;
#pragma unroll
            for (int mi = 0; mi < 4; mi++) {
#pragma unroll
                for (int half = 0; half < 2; half++) {
                    int rloc = wm * 64 + mi * 16 + g + half * 8;
                    if (m0 + rloc < cnt) {
                        int rg = s_perm[rloc];
                        float* orow = out_nei + (size_t)rg * E_ + nt * NT + wn * 32;
#pragma unroll
                        for (int ni = 0; ni < 4; ni++) {
                            int colo = ni * 8 + t4 * 2;
                            float2 v = make_float2(
                                acc[mi][ni][half * 2 + 0] + s_bias[wn * 32 + colo],
                                acc[mi][ni][half * 2 + 1] + s_bias[wn * 32 + colo + 1]);
                            *(float2*)(orow + colo) = v;
                        }
                    }
                }
            }

            cur ^= 1;
        }
    }

    // ================== fused x-path tail ==================
    {
        int mid = blockIdx.x;
        int c = -1, gt = 0, acc_t = 0;
#pragma unroll
        for (int cc = 0; cc < C_; cc++) {
            int t = (g_xcnt[cc] + XGRP - 1) / XGRP;
            if (c < 0 && mid < acc_t + t) { c = cc; gt = mid - acc_t; }
            acc_t += t;
        }
        if (c >= 0) {
            int cnt = g_xcnt[c];
            int xo  = g_xoff[c];
            int s0  = gt * XGRP;
            int m   = min(XGRP, cnt - s0);

            __syncthreads();                      // done with GEMM smem
            int*   s_rows = (int*)smem;           // [8]
            float (*s_obs)[DNEI_] = (float(*)[DNEI_])(smem + 32);

            if (tid < XGRP)
                s_rows[tid] = (tid < m) ? g_xperm[xo + s0 + tid] : -1;
            __syncthreads();
            if (tid < 96) {
                int s = tid / 12, q = tid % 12;
                int rb = s_rows[s];
                float4 v = make_float4(0.f, 0.f, 0.f, 0.f);
                if (rb >= 0) v = *(const float4*)(obs + (size_t)rb * DNEI_ + q * 4);
                *(float4*)(&s_obs[s][q * 4]) = v;
            }
            __syncthreads();

            int ct   = tid & 127;
            int half = tid >> 7;
            int col  = ct * 4;
            const float* W = W_self + (size_t)c * DSELF_ * E_ + col;
            float4 a0 = make_float4(0,0,0,0), a1 = a0, a2 = a0, a3 = a0;
            float4 a4 = a0, a5 = a0, a6 = a0, a7 = a0;
#pragma unroll 4
            for (int j = 0; j < DNEI_; j++) {
                float4 w4 = *(const float4*)(W + (size_t)j * E_);
                float t0 = s_obs[0][j], t1 = s_obs[1][j], t2 = s_obs[2][j], t3 = s_obs[3][j];
                float t4 = s_obs[4][j], t5 = s_obs[5][j], t6 = s_obs[6][j], t7 = s_obs[7][j];
                a0.x += t0*w4.x; a0.y += t0*w4.y; a0.z += t0*w4.z; a0.w += t0*w4.w;
                a1.x += t1*w4.x; a1.y += t1*w4.y; a1.z += t1*w4.z; a1.w += t1*w4.w;
                a2.x += t2*w4.x; a2.y += t2*w4.y; a2.z += t2*w4.z; a2.w += t2*w4.w;
                a3.x += t3*w4.x; a3.y += t3*w4.y; a3.z += t3*w4.z; a3.w += t3*w4.w;
                a4.x += t4*w4.x; a4.y += t4*w4.y; a4.z += t4*w4.z; a4.w += t4*w4.w;
                a5.x += t5*w4.x; a5.y += t5*w4.y; a5.z += t5*w4.z; a5.w += t5*w4.w;
                a6.x += t6*w4.x; a6.y += t6*w4.y; a6.z += t6*w4.z; a6.w += t6*w4.w;
                a7.x += t7*w4.x; a7.y += t7*w4.y; a7.z += t7*w4.z; a7.w += t7*w4.w;
            }

            float4 av[XGRP] = {a0, a1, a2, a3, a4, a5, a6, a7};
            int kk0 = half * (K_ / 2), kk1 = kk0 + (K_ / 2);
#pragma unroll
            for (int kk = kk0; kk < kk1; kk++) {
                float4 an = *(const float4*)(g_anchor + ((size_t)c * K_ + kk) * E_ + col);
#pragma unroll
                for (int s = 0; s < XGRP; s++) {
                    int rb = s_rows[s];
                    if (rb >= 0) {
                        float4 v = make_float4(av[s].x + an.x, av[s].y + an.y,
                                               av[s].z + an.z, av[s].w + an.w);
                        *(float4*)(out_x + ((size_t)rb * K_ + kk) * E_ + col) = v;
                    }
                }
            }
        }
    }

    // Reset class counters for the next launch (graph replay). All 296 CTAs are
    // one co-resident wave: every CTA read g_cur within its first microsecond;
    // block 0 resets it at the very end of its (much longer) execution.
    if (blockIdx.x == 0 && tid < CN_) g_cur[tid] = 0;
}

// ---------------- launcher ----------------
extern "C" void kernel_launch(void* const* d_in, const int* in_sizes, int n_in,
                              void* d_out, int out_size) {
    const float* obs         = (const float*)d_in[0];
    const float* neis        = (const float*)d_in[1];
    const float* init_trajs  = (const float*)d_in[2];
    const float* W_self      = (const float*)d_in[3];
    const float* b_self      = (const float*)d_in[4];
    const float* W_nei       = (const float*)d_in[5];
    const float* b_nei       = (const float*)d_in[6];
    const int*   self_labels = (const int*)d_in[7];
    const int*   nei_labels  = (const int*)d_in[8];

    float* out_x   = (float*)d_out;
    float* out_nei = (float*)d_out + X_ELEMS;

    cudaFuncSetAttribute(k_gemm_mma, cudaFuncAttributeMaxDynamicSharedMemorySize, SMEM_BYTES);

    k_fused<<<K1_GRID, 256>>>(neis, nei_labels, W_nei, init_trajs,
                              W_self, b_self, self_labels);
    k_gemm_mma<<<GEMM_GRID, 256, SMEM_BYTES>>>(b_nei, obs, W_self, out_nei, out_x);
}

// round 15
// speedup vs baseline: 2.0769x; 1.0060x over previous
#include <cuda_runtime.h>
#include <cuda_fp16.h>
#include <cstdint>

typedef unsigned long long u64;

// Problem constants
#define B_      2048
#define N_      64
#define OBS_    8
#define PRED_   12
#define IN_     6
#define E_      512
#define C_      6
#define CN_     7          // C + 1
#define K_      20
#define DSELF_  120        // IN*(OBS+PRED)
#define DNEI_   48         // IN*OBS
#define RTOT_   (B_ * N_)  // 131072
#define NBLK_   (RTOT_ / 256)   // 512
#define EPSF    1e-4f

#define KP2_    96         // packed A row: [hi(48) | lo(48)] fp16
#define ROW2_   (KP2_ * 2) // 192 bytes per packed A row
#define WROW_   96         // packed W row: [hi(48)] fp16 = 96 bytes
#define X_ELEMS ((size_t)B_ * K_ * E_)   // 20,971,520

// Fixed per-class segments: class c owns rows [c*RTOT_, c*RTOT_+cnt_c).
#define CSEG_ROWS ((size_t)CN_ * RTOT_)   // 917504 rows

// ---------------- scratch (__device__ globals; no allocation) ----------------
__device__ __align__(256) __half g_Ab[CSEG_ROWS * KP2_];            // ~176 MB
__device__ __align__(256) __half g_Wb[(size_t)CN_ * E_ * (WROW_/2)];
__device__ __align__(256) int    g_perm[CSEG_ROWS + 128];
__device__ __align__(256) int    g_cur[CN_];   // zero at launch; reset by GEMM block 0
__device__ __align__(256) float  g_anchor[(size_t)C_ * K_ * E_];
// x-path binning
__device__ __align__(256) int    g_xperm[B_];
__device__ __align__(256) int    g_xcnt[C_];
__device__ __align__(256) int    g_xoff[C_];

// ---------------- kernel 1 (fused): scatter+split | weight split | anchor | xbin ----
#define WPREP_BLKS ((CN_ * E_ + 255) / 256)    // 14
#define ANCH_BLKS  (C_ * K_)                   // 120
#define K1_GRID    (NBLK_ + WPREP_BLKS + ANCH_BLKS + 1)

__global__ void k_fused(const float* __restrict__ neis,
                        const int*   __restrict__ nei_labels,
                        const float* __restrict__ W_nei,
                        const float* __restrict__ init_trajs,
                        const float* __restrict__ W_self,
                        const float* __restrict__ b_self,
                        const int*   __restrict__ self_labels) {
    int tid = threadIdx.x;
    if (blockIdx.x < NBLK_) {
        // ---- scatter + transform + fp16 hi/lo split copy ----
        __shared__ int s_hist[CN_], s_cur[CN_];
        __shared__ int s_pos[256];
        int blk = blockIdx.x;
        if (tid < CN_) s_hist[tid] = 0;
        __syncthreads();
        int row = blk * 256 + tid;
        int c   = nei_labels[row];
        atomicAdd(&s_hist[c], 1);
        __syncthreads();
        if (tid < CN_)
            s_cur[tid] = s_hist[tid] ? atomicAdd(&g_cur[tid], s_hist[tid]) : 0;
        __syncthreads();
        int pos = c * RTOT_ + atomicAdd(&s_cur[c], 1);
        s_pos[tid]  = pos;
        g_perm[pos] = row;
        __syncthreads();

#pragma unroll
        for (int it = 0; it < 12; it++) {
            int idx = it * 256 + tid;
            int r = idx / 12, q = idx % 12;       // q: float4 chunk 0..11
            float4 v = *(const float4*)(neis + ((size_t)blk * 256 + r) * DNEI_ + q * 4);
            v.x = (v.x >= 0.f) ? 1.f / (v.x + EPSF) : 1.f / (v.x - EPSF);
            v.y = (v.y >= 0.f) ? 1.f / (v.y + EPSF) : 1.f / (v.y - EPSF);
            v.z = (v.z >= 0.f) ? 1.f / (v.z + EPSF) : 1.f / (v.z - EPSF);
            v.w = (v.w >= 0.f) ? 1.f / (v.w + EPSF) : 1.f / (v.w - EPSF);

            __half hx = __float2half_rn(v.x), hy = __float2half_rn(v.y);
            __half hz = __float2half_rn(v.z), hw = __float2half_rn(v.w);
            __half lx = __float2half_rn(v.x - __half2float(hx));
            __half ly = __float2half_rn(v.y - __half2float(hy));
            __half lz = __float2half_rn(v.z - __half2float(hz));
            __half lw = __float2half_rn(v.w - __half2float(hw));

            uint32_t h01 = ((uint32_t)__half_as_ushort(hy) << 16) | __half_as_ushort(hx);
            uint32_t h23 = ((uint32_t)__half_as_ushort(hw) << 16) | __half_as_ushort(hz);
            uint32_t l01 = ((uint32_t)__half_as_ushort(ly) << 16) | __half_as_ushort(lx);
            uint32_t l23 = ((uint32_t)__half_as_ushort(lw) << 16) | __half_as_ushort(lz);

            char* rb = (char*)g_Ab + (size_t)s_pos[r] * ROW2_;
            *(uint2*)(rb + q * 8)       = make_uint2(h01, h23);   // hi (k 0..47)
            *(uint2*)(rb + 96 + q * 8)  = make_uint2(l01, l23);   // lo
        }
    } else if (blockIdx.x < NBLK_ + WPREP_BLKS) {
        // ---- weight fp16 hi (only hi needed for the 2-term split) ----
        int g = (blockIdx.x - NBLK_) * 256 + tid;   // (c, n)
        if (g >= CN_ * E_) return;
        int c = g / E_, n = g % E_;
        char* rb = (char*)g_Wb + (size_t)g * WROW_;
        const float* W = W_nei + (size_t)c * DNEI_ * E_ + n;
#pragma unroll 8
        for (int k = 0; k < DNEI_; k++)
            *(__half*)(rb + k * 2) = __float2half_rn(W[(size_t)k * E_]);
    } else if (blockIdx.x < NBLK_ + WPREP_BLKS + ANCH_BLKS) {
        // ---- anchor: anchor[c,k,:] = it[c,k] @ W_self[c][48:] + b_self[c] ----
        int bid = blockIdx.x - NBLK_ - WPREP_BLKS;
        int c  = bid / K_;
        int kk = bid % K_;
        __shared__ float tr[PRED_ * IN_];   // 72
        if (tid < PRED_ * IN_)
            tr[tid] = init_trajs[((size_t)c * K_ + kk) * (PRED_ * IN_) + tid];
        __syncthreads();
        if (tid < 128) {
            int col = tid * 4;
            const float* bb = b_self + (size_t)c * E_ + col;
            float4 acc = *(const float4*)bb;
            const float* W = W_self + ((size_t)c * DSELF_ + DNEI_) * E_ + col;
#pragma unroll 8
            for (int j = 0; j < PRED_ * IN_; j++) {
                float  t = tr[j];
                float4 w = *(const float4*)(W + (size_t)j * E_);
                acc.x += t * w.x; acc.y += t * w.y; acc.z += t * w.z; acc.w += t * w.w;
            }
            *(float4*)(g_anchor + ((size_t)c * K_ + kk) * E_ + col) = acc;
        }
    } else {
        // ---- xbin: bin self_labels (single block, deterministic) ----
        __shared__ int sc2[C_][256];
        __shared__ int s_tot[C_];
        __shared__ int s_off[C_];
        int base = tid * 8;                       // 256 x 8 = 2048
#pragma unroll
        for (int c = 0; c < C_; c++) {
            int n = 0;
#pragma unroll
            for (int i = 0; i < 8; i++) n += (self_labels[base + i] == c);
            sc2[c][tid] = n;
        }
        __syncthreads();
        int w = tid >> 5, lane = tid & 31;
        if (w < C_) {
            int acc = 0;
#pragma unroll
            for (int seg = 0; seg < 8; seg++) {
                int v = sc2[w][seg * 32 + lane];
                int s = v;
#pragma unroll
                for (int d = 1; d < 32; d <<= 1) {
                    int t = __shfl_up_sync(0xffffffffu, s, d);
                    if (lane >= d) s += t;
                }
                sc2[w][seg * 32 + lane] = acc + s - v;
                acc += __shfl_sync(0xffffffffu, s, 31);
            }
            if (lane == 0) s_tot[w] = acc;
        }
        __syncthreads();
        if (tid == 0) {
            int a = 0;
            for (int c = 0; c < C_; c++) {
                s_off[c] = a; g_xoff[c] = a; g_xcnt[c] = s_tot[c]; a += s_tot[c];
            }
        }
        __syncthreads();
#pragma unroll
        for (int c = 0; c < C_; c++) {
            int p = s_off[c] + sc2[c][tid];
#pragma unroll
            for (int i = 0; i < 8; i++)
                if (self_labels[base + i] == c) g_xperm[p++] = base + i;
        }
    }
}

// ================= mma.sync / cp.async helpers =================
__device__ __forceinline__ uint32_t smem_u32(const void* p) {
    uint32_t a;
    asm("{ .reg .u64 t; cvta.to.shared.u64 t, %1; cvt.u32.u64 %0, t; }" : "=r"(a) : "l"(p));
    return a;
}
__device__ __forceinline__ void cp_async16(uint32_t dst, const void* src, int src_size) {
    asm volatile("cp.async.cg.shared.global [%0], [%1], 16, %2;"
                 :: "r"(dst), "l"(src), "r"(src_size) : "memory");
}
__device__ __forceinline__ void cp_commit() {
    asm volatile("cp.async.commit_group;" ::: "memory");
}
__device__ __forceinline__ void cp_wait_all() {
    asm volatile("cp.async.wait_group 0;" ::: "memory");
}
__device__ __forceinline__ void ldsm_x4(uint32_t* r, uint32_t addr) {
    asm volatile("ldmatrix.sync.aligned.m8n8.x4.shared.b16 {%0,%1,%2,%3}, [%4];"
                 : "=r"(r[0]), "=r"(r[1]), "=r"(r[2]), "=r"(r[3]) : "r"(addr));
}
__device__ __forceinline__ void mma16816h(float* c, const uint32_t* a, uint32_t b0, uint32_t b1) {
    asm volatile("mma.sync.aligned.m16n8k16.row.col.f32.f16.f16.f32 "
                 "{%0,%1,%2,%3}, {%4,%5,%6,%7}, {%8,%9}, {%0,%1,%2,%3};"
                 : "+f"(c[0]), "+f"(c[1]), "+f"(c[2]), "+f"(c[3])
                 : "r"(a[0]), "r"(a[1]), "r"(a[2]), "r"(a[3]), "r"(b0), "r"(b1));
}

// ---------------- kernel 2: persistent GEMM (full-E per CTA) + x-path tail ----
// Each CTA: JOBS_ m-tiles; per m-tile computes ALL 4 n-tiles (E=512) with the
// class's full-width B resident in smem. A staged once per m-tile (was 4x).
#define MT 128
#define NT 128
#define GEMM_MAX_MTILES ((RTOT_ / MT) + CN_)   // 1031
#define JOBS_ 4
#define GEMM_GRID 262                          // >= ceil(1031/4)=258 and >= 262 x-groups
#define STRIDE_A 208                           // conflict-free LDSM stride (A, 192B rows)
#define STRIDE_B 112                           // conflict-free LDSM stride (B, 96B rows)
#define TILE_A   (128 * STRIDE_A)              // 26624
#define TILE_BF  (E_ * STRIDE_B)               // 57344 (full-width B, 512 rows)
// smem: perm 2x512 | bias 2048 | A 2xTILE_A | B TILE_BF
#define OFF_PERM  0
#define OFF_BIAS  1024
#define OFF_A     3072
#define OFF_B     (OFF_A + 2 * TILE_A)         // 56320
#define SMEM_BYTES (OFF_B + TILE_BF)           // 113664
#define XGRP 8

__global__ void __launch_bounds__(256, 2)
k_gemm_mma(const float* __restrict__ b_nei,
           const float* __restrict__ obs,
           const float* __restrict__ W_self,
           float*       __restrict__ out_nei,
           float*       __restrict__ out_x) {
    int mid0 = blockIdx.x * JOBS_;

    int cnts[CN_];
#pragma unroll
    for (int cc = 0; cc < CN_; cc++) cnts[cc] = g_cur[cc];

    extern __shared__ char smem[];
    uint32_t sbase = smem_u32(smem);

    int tid  = threadIdx.x;
    int lane = tid & 31;
    int wid  = tid >> 5;
    int wm   = wid & 1;          // 2 warp rows (64 rows each)
    int wn   = wid >> 1;         // 4 warp cols (32 cols each, within a 128-wide nt)

    // per-thread cp.async geometry
    int pr  = tid >> 1;
    int phA = (tid & 1) * 6;     // A: 12 chunks/row, 6 per thread

    auto map_job = [&](int mid, int& c, int& mt) -> bool {
        int acc = 0;
#pragma unroll
        for (int cc = 0; cc < CN_; cc++) {
            int t = (cnts[cc] + MT - 1) >> 7;
            if (mid < acc + t) { c = cc; mt = mid - acc; return true; }
            acc += t;
        }
        return false;
    };

    auto prefetch_A = [&](int buf, int c, int mt) {
        int m0 = mt * MT;
        int ok = (m0 + pr < cnts[c]) ? 16 : 0;
        const char* src = (const char*)g_Ab
                        + (size_t)(ok ? (c * RTOT_ + m0 + pr) : 0) * ROW2_;
        uint32_t dst = sbase + OFF_A + buf * TILE_A
                     + (uint32_t)pr * STRIDE_A + (uint32_t)phA * 16;
#pragma unroll
        for (int i = 0; i < 6; i++)
            cp_async16(dst + i * 16, src + (phA + i) * 16, ok);
    };
    auto prefetch_perm = [&](int buf, int c, int mt) {
        if (tid < 32) {
            // c*RTOT_ and mt*MT are multiples of 128 -> source 512B aligned
            const char* src = (const char*)g_perm + ((size_t)c * RTOT_ + mt * MT) * 4 + tid * 16;
            cp_async16(sbase + OFF_PERM + buf * 512 + tid * 16, src, 16);
        }
    };
    // full-width B (512 rows x 96B) + full bias (512 floats), once per class
    auto prefetch_Bfull = [&](int c) {
#pragma unroll
        for (int rr = 0; rr < 2; rr++) {
            int row = tid * 2 + rr;
            const char* src = (const char*)g_Wb + ((size_t)c * E_ + row) * WROW_;
            uint32_t dst = sbase + OFF_B + (uint32_t)row * STRIDE_B;
#pragma unroll
            for (int i = 0; i < 6; i++)
                cp_async16(dst + i * 16, src + i * 16, 16);
        }
        if (tid < 128) {
            const char* src = (const char*)b_nei + (size_t)c * E_ * 4 + tid * 16;
            cp_async16(sbase + OFF_BIAS + tid * 16, src, 16);
        }
    };

    // prologue
    int c0, mt0;
    if (map_job(mid0, c0, mt0)) {
        prefetch_A(0, c0, mt0);
        prefetch_perm(0, c0, mt0);
        prefetch_Bfull(c0);
        cp_commit();

        int cur = 0, bclass = c0;

        for (int j = 0; j < JOBS_; j++) {
            int mid = mid0 + j;
            int c, mt;
            if (!map_job(mid, c, mt)) break;
            int cnt = cnts[c];

            cp_wait_all();          // this thread's copies for job j done
            __syncthreads();        // all threads' copies + prev compute done

            // B/bias reload on class change (uniform branch; per-thread
            // wait_group needs trailing __syncthreads for visibility)
            if (c != bclass) {
                prefetch_Bfull(c);
                cp_commit();
                cp_wait_all();
                __syncthreads();
                bclass = c;
            }

            // prefetch job j+1 A+perm into alternate buffer — overlaps compute
            if (j + 1 < JOBS_) {
                int cn, mtn;
                if (map_job(mid + 1, cn, mtn)) {
                    prefetch_A(cur ^ 1, cn, mtn);
                    prefetch_perm(cur ^ 1, cn, mtn);
                    cp_commit();
                }
            }

            const int*   s_perm = (const int*)(smem + OFF_PERM + cur * 512);
            const float* s_bias = (const float*)(smem + OFF_BIAS);

            uint32_t a_u32 = sbase + OFF_A + cur * TILE_A;
            uint32_t a_base = a_u32 + (uint32_t)(wm * 64 + (lane & 15)) * STRIDE_A
                                    + ((lane >> 4) << 4);
            int g = lane >> 2, t4 = lane & 3;
            int m0 = mt * MT;

            // ---- compute all 4 n-tiles with resident B ----
#pragma unroll
            for (int nt = 0; nt < 4; nt++) {
                uint32_t b_base = sbase + OFF_B
                    + (uint32_t)(nt * NT + wn * 32 + ((lane >> 4) << 3) + (lane & 7)) * STRIDE_B
                    + (((lane >> 3) & 1) << 4);

                float acc[4][4][4];
#pragma unroll
                for (int i = 0; i < 4; i++)
#pragma unroll
                    for (int jj = 0; jj < 4; jj++)
#pragma unroll
                        for (int q = 0; q < 4; q++) acc[i][jj][q] = 0.f;

#pragma unroll
                for (int kc = 0; kc < 3; kc++) {       // 48 = 3 x 16
                    uint32_t kb = kc * 32;
                    uint32_t Bh0[4], Bh1[4];
                    ldsm_x4(Bh0, b_base + kb);                   // Whi, subtiles 0,1
                    ldsm_x4(Bh1, b_base + 16 * STRIDE_B + kb);   // Whi, subtiles 2,3
#pragma unroll
                    for (int mi = 0; mi < 4; mi++) {
                        uint32_t Ah[4], Al[4];
                        ldsm_x4(Ah, a_base + (uint32_t)mi * 16 * STRIDE_A + kb);
                        ldsm_x4(Al, a_base + (uint32_t)mi * 16 * STRIDE_A + 96 + kb);
                        // hi*hi
                        mma16816h(acc[mi][0], Ah, Bh0[0], Bh0[1]);
                        mma16816h(acc[mi][1], Ah, Bh0[2], Bh0[3]);
                        mma16816h(acc[mi][2], Ah, Bh1[0], Bh1[1]);
                        mma16816h(acc[mi][3], Ah, Bh1[2], Bh1[3]);
                        // lo*hi
                        mma16816h(acc[mi][0], Al, Bh0[0], Bh0[1]);
                        mma16816h(acc[mi][1], Al, Bh0[2], Bh0[3]);
                        mma16816h(acc[mi][2], Al, Bh1[0], Bh1[1]);
                        mma16816h(acc[mi][3], Al, Bh1[2], Bh1[3]);
                    }
                }

                // ---- epilogue for this nt ----
#pragma unroll
                for (int mi = 0; mi < 4; mi++) {
#pragma unroll
                    for (int half = 0; half < 2; half++) {
                        int rloc = wm * 64 + mi * 16 + g + half * 8;
                        if (m0 + rloc < cnt) {
                            int rg = s_perm[rloc];
                            float* orow = out_nei + (size_t)rg * E_ + nt * NT + wn * 32;
#pragma unroll
                            for (int ni = 0; ni < 4; ni++) {
                                int colo = ni * 8 + t4 * 2;
                                float2 v = make_float2(
                                    acc[mi][ni][half * 2 + 0] + s_bias[nt * NT + wn * 32 + colo],
                                    acc[mi][ni][half * 2 + 1] + s_bias[nt * NT + wn * 32 + colo + 1]);
                                *(float2*)(orow + colo) = v;
                            }
                        }
                    }
                }
            }

            cur ^= 1;
        }
    }

    // ================== fused x-path tail ==================
    {
        int mid = blockIdx.x;
        int c = -1, gt = 0, acc_t = 0;
#pragma unroll
        for (int cc = 0; cc < C_; cc++) {
            int t = (g_xcnt[cc] + XGRP - 1) / XGRP;
            if (c < 0 && mid < acc_t + t) { c = cc; gt = mid - acc_t; }
            acc_t += t;
        }
        if (c >= 0) {
            int cnt = g_xcnt[c];
            int xo  = g_xoff[c];
            int s0  = gt * XGRP;
            int m   = min(XGRP, cnt - s0);

            __syncthreads();                      // done with GEMM smem
            int*   s_rows = (int*)smem;           // [8]
            float (*s_obs)[DNEI_] = (float(*)[DNEI_])(smem + 32);

            if (tid < XGRP)
                s_rows[tid] = (tid < m) ? g_xperm[xo + s0 + tid] : -1;
            __syncthreads();
            if (tid < 96) {
                int s = tid / 12, q = tid % 12;
                int rb = s_rows[s];
                float4 v = make_float4(0.f, 0.f, 0.f, 0.f);
                if (rb >= 0) v = *(const float4*)(obs + (size_t)rb * DNEI_ + q * 4);
                *(float4*)(&s_obs[s][q * 4]) = v;
            }
            __syncthreads();

            int ct   = tid & 127;
            int half = tid >> 7;
            int col  = ct * 4;
            const float* W = W_self + (size_t)c * DSELF_ * E_ + col;
            float4 a0 = make_float4(0,0,0,0), a1 = a0, a2 = a0, a3 = a0;
            float4 a4 = a0, a5 = a0, a6 = a0, a7 = a0;
#pragma unroll 4
            for (int j = 0; j < DNEI_; j++) {
                float4 w4 = *(const float4*)(W + (size_t)j * E_);
                float t0 = s_obs[0][j], t1 = s_obs[1][j], t2 = s_obs[2][j], t3 = s_obs[3][j];
                float t4 = s_obs[4][j], t5 = s_obs[5][j], t6 = s_obs[6][j], t7 = s_obs[7][j];
                a0.x += t0*w4.x; a0.y += t0*w4.y; a0.z += t0*w4.z; a0.w += t0*w4.w;
                a1.x += t1*w4.x; a1.y += t1*w4.y; a1.z += t1*w4.z; a1.w += t1*w4.w;
                a2.x += t2*w4.x; a2.y += t2*w4.y; a2.z += t2*w4.z; a2.w += t2*w4.w;
                a3.x += t3*w4.x; a3.y += t3*w4.y; a3.z += t3*w4.z; a3.w += t3*w4.w;
                a4.x += t4*w4.x; a4.y += t4*w4.y; a4.z += t4*w4.z; a4.w += t4*w4.w;
                a5.x += t5*w4.x; a5.y += t5*w4.y; a5.z += t5*w4.z; a5.w += t5*w4.w;
                a6.x += t6*w4.x; a6.y += t6*w4.y; a6.z += t6*w4.z; a6.w += t6*w4.w;
                a7.x += t7*w4.x; a7.y += t7*w4.y; a7.z += t7*w4.z; a7.w += t7*w4.w;
            }

            float4 av[XGRP] = {a0, a1, a2, a3, a4, a5, a6, a7};
            int kk0 = half * (K_ / 2), kk1 = kk0 + (K_ / 2);
#pragma unroll
            for (int kk = kk0; kk < kk1; kk++) {
                float4 an = *(const float4*)(g_anchor + ((size_t)c * K_ + kk) * E_ + col);
#pragma unroll
                for (int s = 0; s < XGRP; s++) {
                    int rb = s_rows[s];
                    if (rb >= 0) {
                        float4 v = make_float4(av[s].x + an.x, av[s].y + an.y,
                                               av[s].z + an.z, av[s].w + an.w);
                        *(float4*)(out_x + ((size_t)rb * K_ + kk) * E_ + col) = v;
                    }
                }
            }
        }
    }

    // Reset class counters for the next graph replay. All 262 CTAs are one
    // co-resident wave: every CTA read g_cur in its first microsecond; block 0
    // resets at the very end of its (much longer) execution.
    if (blockIdx.x == 0 && tid < CN_) g_cur[tid] = 0;
}

// ---------------- launcher ----------------
extern "C" void kernel_launch(void* const* d_in, const int* in_sizes, int n_in,
                              void* d_out, int out_size) {
    const float* obs         = (const float*)d_in[0];
    const float* neis        = (const float*)d_in[1];
    const float* init_trajs  = (const float*)d_in[2];
    const float* W_self      = (const float*)d_in[3];
    const float* b_self      = (const float*)d_in[4];
    const float* W_nei       = (const float*)d_in[5];
    const float* b_nei       = (const float*)d_in[6];
    const int*   self_labels = (const int*)d_in[7];
    const int*   nei_labels  = (const int*)d_in[8];

    float* out_x   = (float*)d_out;
    float* out_nei = (float*)d_out + X_ELEMS;

    cudaFuncSetAttribute(k_gemm_mma, cudaFuncAttributeMaxDynamicSharedMemorySize, SMEM_BYTES);

    k_fused<<<K1_GRID, 256>>>(neis, nei_labels, W_nei, init_trajs,
                              W_self, b_self, self_labels);
    k_gemm_mma<<<GEMM_GRID, 256, SMEM_BYTES>>>(b_nei, obs, W_self, out_nei, out_x);
}

// round 16
// speedup vs baseline: 2.4777x; 1.1929x over previous
#include <cuda_runtime.h>
#include <cuda_fp16.h>
#include <cstdint>

typedef unsigned long long u64;

// Problem constants
#define B_      2048
#define N_      64
#define OBS_    8
#define PRED_   12
#define IN_     6
#define E_      512
#define C_      6
#define CN_     7          // C + 1
#define K_      20
#define DSELF_  120        // IN*(OBS+PRED)
#define DNEI_   48         // IN*OBS
#define RTOT_   (B_ * N_)  // 131072
#define NBLK_   (RTOT_ / 256)   // 512
#define EPSF    1e-4f

#define KP2_    96         // packed A row: [hi(48) | lo(48)] fp16
#define ROW2_   (KP2_ * 2) // 192 bytes per packed A row
#define WROW_   96         // packed W row: [hi(48)] fp16 = 96 bytes
#define X_ELEMS ((size_t)B_ * K_ * E_)   // 20,971,520

// Fixed per-class segments: class c owns rows [c*RTOT_, c*RTOT_+cnt_c).
#define CSEG_ROWS ((size_t)CN_ * RTOT_)   // 917504 rows

// ---------------- scratch (__device__ globals; no allocation) ----------------
__device__ __align__(256) __half g_Ab[CSEG_ROWS * KP2_];            // ~176 MB
__device__ __align__(256) __half g_Wb[(size_t)CN_ * E_ * (WROW_/2)];
__device__ __align__(256) int    g_perm[CSEG_ROWS + 128];
__device__ __align__(256) int    g_cur[CN_];   // zero at launch; reset by GEMM block 0
__device__ __align__(256) float  g_anchor[(size_t)C_ * K_ * E_];
// x-path binning
__device__ __align__(256) int    g_xperm[B_];
__device__ __align__(256) int    g_xcnt[C_];
__device__ __align__(256) int    g_xoff[C_];

// ---------------- kernel 1 (fused): scatter+split | weight split | anchor | xbin ----
#define WPREP_BLKS ((CN_ * E_ + 255) / 256)    // 14
#define ANCH_BLKS  (C_ * K_)                   // 120
#define K1_GRID    (NBLK_ + WPREP_BLKS + ANCH_BLKS + 1)

__global__ void k_fused(const float* __restrict__ neis,
                        const int*   __restrict__ nei_labels,
                        const float* __restrict__ W_nei,
                        const float* __restrict__ init_trajs,
                        const float* __restrict__ W_self,
                        const float* __restrict__ b_self,
                        const int*   __restrict__ self_labels) {
    int tid = threadIdx.x;
    if (blockIdx.x < NBLK_) {
        // ---- scatter + transform + fp16 hi/lo split copy ----
        __shared__ int s_hist[CN_], s_cur[CN_];
        __shared__ int s_pos[256];
        int blk = blockIdx.x;
        if (tid < CN_) s_hist[tid] = 0;
        __syncthreads();
        int row = blk * 256 + tid;
        int c   = nei_labels[row];
        atomicAdd(&s_hist[c], 1);
        __syncthreads();
        if (tid < CN_)
            s_cur[tid] = s_hist[tid] ? atomicAdd(&g_cur[tid], s_hist[tid]) : 0;
        __syncthreads();
        int pos = c * RTOT_ + atomicAdd(&s_cur[c], 1);
        s_pos[tid]  = pos;
        g_perm[pos] = row;
        __syncthreads();

#pragma unroll
        for (int it = 0; it < 12; it++) {
            int idx = it * 256 + tid;
            int r = idx / 12, q = idx % 12;       // q: float4 chunk 0..11
            float4 v = *(const float4*)(neis + ((size_t)blk * 256 + r) * DNEI_ + q * 4);
            v.x = (v.x >= 0.f) ? 1.f / (v.x + EPSF) : 1.f / (v.x - EPSF);
            v.y = (v.y >= 0.f) ? 1.f / (v.y + EPSF) : 1.f / (v.y - EPSF);
            v.z = (v.z >= 0.f) ? 1.f / (v.z + EPSF) : 1.f / (v.z - EPSF);
            v.w = (v.w >= 0.f) ? 1.f / (v.w + EPSF) : 1.f / (v.w - EPSF);

            __half hx = __float2half_rn(v.x), hy = __float2half_rn(v.y);
            __half hz = __float2half_rn(v.z), hw = __float2half_rn(v.w);
            __half lx = __float2half_rn(v.x - __half2float(hx));
            __half ly = __float2half_rn(v.y - __half2float(hy));
            __half lz = __float2half_rn(v.z - __half2float(hz));
            __half lw = __float2half_rn(v.w - __half2float(hw));

            uint32_t h01 = ((uint32_t)__half_as_ushort(hy) << 16) | __half_as_ushort(hx);
            uint32_t h23 = ((uint32_t)__half_as_ushort(hw) << 16) | __half_as_ushort(hz);
            uint32_t l01 = ((uint32_t)__half_as_ushort(ly) << 16) | __half_as_ushort(lx);
            uint32_t l23 = ((uint32_t)__half_as_ushort(lw) << 16) | __half_as_ushort(lz);

            char* rb = (char*)g_Ab + (size_t)s_pos[r] * ROW2_;
            *(uint2*)(rb + q * 8)       = make_uint2(h01, h23);   // hi (k 0..47)
            *(uint2*)(rb + 96 + q * 8)  = make_uint2(l01, l23);   // lo
        }
    } else if (blockIdx.x < NBLK_ + WPREP_BLKS) {
        // ---- weight fp16 hi (only hi needed for the 2-term split) ----
        int g = (blockIdx.x - NBLK_) * 256 + tid;   // (c, n)
        if (g >= CN_ * E_) return;
        int c = g / E_, n = g % E_;
        char* rb = (char*)g_Wb + (size_t)g * WROW_;
        const float* W = W_nei + (size_t)c * DNEI_ * E_ + n;
#pragma unroll 8
        for (int k = 0; k < DNEI_; k++)
            *(__half*)(rb + k * 2) = __float2half_rn(W[(size_t)k * E_]);
    } else if (blockIdx.x < NBLK_ + WPREP_BLKS + ANCH_BLKS) {
        // ---- anchor: anchor[c,k,:] = it[c,k] @ W_self[c][48:] + b_self[c] ----
        int bid = blockIdx.x - NBLK_ - WPREP_BLKS;
        int c  = bid / K_;
        int kk = bid % K_;
        __shared__ float tr[PRED_ * IN_];   // 72
        if (tid < PRED_ * IN_)
            tr[tid] = init_trajs[((size_t)c * K_ + kk) * (PRED_ * IN_) + tid];
        __syncthreads();
        if (tid < 128) {
            int col = tid * 4;
            const float* bb = b_self + (size_t)c * E_ + col;
            float4 acc = *(const float4*)bb;
            const float* W = W_self + ((size_t)c * DSELF_ + DNEI_) * E_ + col;
#pragma unroll 8
            for (int j = 0; j < PRED_ * IN_; j++) {
                float  t = tr[j];
                float4 w = *(const float4*)(W + (size_t)j * E_);
                acc.x += t * w.x; acc.y += t * w.y; acc.z += t * w.z; acc.w += t * w.w;
            }
            *(float4*)(g_anchor + ((size_t)c * K_ + kk) * E_ + col) = acc;
        }
    } else {
        // ---- xbin: bin self_labels (single block, deterministic) ----
        __shared__ int sc2[C_][256];
        __shared__ int s_tot[C_];
        __shared__ int s_off[C_];
        int base = tid * 8;                       // 256 x 8 = 2048
#pragma unroll
        for (int c = 0; c < C_; c++) {
            int n = 0;
#pragma unroll
            for (int i = 0; i < 8; i++) n += (self_labels[base + i] == c);
            sc2[c][tid] = n;
        }
        __syncthreads();
        int w = tid >> 5, lane = tid & 31;
        if (w < C_) {
            int acc = 0;
#pragma unroll
            for (int seg = 0; seg < 8; seg++) {
                int v = sc2[w][seg * 32 + lane];
                int s = v;
#pragma unroll
                for (int d = 1; d < 32; d <<= 1) {
                    int t = __shfl_up_sync(0xffffffffu, s, d);
                    if (lane >= d) s += t;
                }
                sc2[w][seg * 32 + lane] = acc + s - v;
                acc += __shfl_sync(0xffffffffu, s, 31);
            }
            if (lane == 0) s_tot[w] = acc;
        }
        __syncthreads();
        if (tid == 0) {
            int a = 0;
            for (int c = 0; c < C_; c++) {
                s_off[c] = a; g_xoff[c] = a; g_xcnt[c] = s_tot[c]; a += s_tot[c];
            }
        }
        __syncthreads();
#pragma unroll
        for (int c = 0; c < C_; c++) {
            int p = s_off[c] + sc2[c][tid];
#pragma unroll
            for (int i = 0; i < 8; i++)
                if (self_labels[base + i] == c) g_xperm[p++] = base + i;
        }
    }
}

// ================= mma.sync / cp.async helpers =================
__device__ __forceinline__ uint32_t smem_u32(const void* p) {
    uint32_t a;
    asm("{ .reg .u64 t; cvta.to.shared.u64 t, %1; cvt.u32.u64 %0, t; }" : "=r"(a) : "l"(p));
    return a;
}
__device__ __forceinline__ void cp_async16(uint32_t dst, const void* src, int src_size) {
    asm volatile("cp.async.cg.shared.global [%0], [%1], 16, %2;"
                 :: "r"(dst), "l"(src), "r"(src_size) : "memory");
}
__device__ __forceinline__ void cp_commit() {
    asm volatile("cp.async.commit_group;" ::: "memory");
}
__device__ __forceinline__ void cp_wait_all() {
    asm volatile("cp.async.wait_group 0;" ::: "memory");
}
__device__ __forceinline__ void ldsm_x4(uint32_t* r, uint32_t addr) {
    asm volatile("ldmatrix.sync.aligned.m8n8.x4.shared.b16 {%0,%1,%2,%3}, [%4];"
                 : "=r"(r[0]), "=r"(r[1]), "=r"(r[2]), "=r"(r[3]) : "r"(addr));
}
__device__ __forceinline__ void mma16816h(float* c, const uint32_t* a, uint32_t b0, uint32_t b1) {
    asm volatile("mma.sync.aligned.m16n8k16.row.col.f32.f16.f16.f32 "
                 "{%0,%1,%2,%3}, {%4,%5,%6,%7}, {%8,%9}, {%0,%1,%2,%3};"
                 : "+f"(c[0]), "+f"(c[1]), "+f"(c[2]), "+f"(c[3])
                 : "r"(a[0]), "r"(a[1]), "r"(a[2]), "r"(a[3]), "r"(b0), "r"(b1));
}

// Column permutation within each 16-col group: B-tile logical row r holds the
// weights of physical output column colOf(r). With this, thread t4's four
// C-fragment values for two adjacent n8 blocks are PHYSICALLY consecutive
// columns 4*t4..4*t4+3 -> epilogue uses STG.128 (halves store wavefronts).
//   logical (n8 block j, pos) -> phys x = (pos>>1)*4 + j*2 + (pos&1)
__device__ __forceinline__ int colOf(int row) {
    int g = row & 15, pos = g & 7, j = g >> 3;
    int x = ((pos >> 1) << 2) | (j << 1) | (pos & 1);
    return (row & ~15) | x;
}

// ---------------- kernel 2: persistent GEMM (full-E per CTA) + x-path tail ----
#define MT 128
#define NT 128
#define GEMM_MAX_MTILES ((RTOT_ / MT) + CN_)   // 1031
#define JOBS_ 4
#define GEMM_GRID 262                          // >= ceil(1031/4)=258 and >= 262 x-groups
#define STRIDE_A 208                           // conflict-free LDSM stride (A, 192B rows)
#define STRIDE_B 112                           // conflict-free LDSM stride (B, 96B rows)
#define TILE_A   (128 * STRIDE_A)              // 26624
#define TILE_BF  (E_ * STRIDE_B)               // 57344 (full-width B, 512 rows)
// smem: perm 2x512 | bias 2048 | A 2xTILE_A | B TILE_BF
#define OFF_PERM  0
#define OFF_BIAS  1024
#define OFF_A     3072
#define OFF_B     (OFF_A + 2 * TILE_A)         // 56320
#define SMEM_BYTES (OFF_B + TILE_BF)           // 113664
#define XGRP 8

__global__ void __launch_bounds__(256, 2)
k_gemm_mma(const float* __restrict__ b_nei,
           const float* __restrict__ obs,
           const float* __restrict__ W_self,
           float*       __restrict__ out_nei,
           float*       __restrict__ out_x) {
    int mid0 = blockIdx.x * JOBS_;

    int cnts[CN_];
#pragma unroll
    for (int cc = 0; cc < CN_; cc++) cnts[cc] = g_cur[cc];

    extern __shared__ char smem[];
    uint32_t sbase = smem_u32(smem);

    int tid  = threadIdx.x;
    int lane = tid & 31;
    int wid  = tid >> 5;
    int wm   = wid & 1;          // 2 warp rows (64 rows each)
    int wn   = wid >> 1;         // 4 warp cols (32 cols each, within a 128-wide nt)

    // per-thread cp.async geometry
    int pr  = tid >> 1;
    int phA = (tid & 1) * 6;     // A: 12 chunks/row, 6 per thread

    auto map_job = [&](int mid, int& c, int& mt) -> bool {
        int acc = 0;
#pragma unroll
        for (int cc = 0; cc < CN_; cc++) {
            int t = (cnts[cc] + MT - 1) >> 7;
            if (mid < acc + t) { c = cc; mt = mid - acc; return true; }
            acc += t;
        }
        return false;
    };

    auto prefetch_A = [&](int buf, int c, int mt) {
        int m0 = mt * MT;
        int ok = (m0 + pr < cnts[c]) ? 16 : 0;
        const char* src = (const char*)g_Ab
                        + (size_t)(ok ? (c * RTOT_ + m0 + pr) : 0) * ROW2_;
        uint32_t dst = sbase + OFF_A + buf * TILE_A
                     + (uint32_t)pr * STRIDE_A + (uint32_t)phA * 16;
#pragma unroll
        for (int i = 0; i < 6; i++)
            cp_async16(dst + i * 16, src + (phA + i) * 16, ok);
    };
    auto prefetch_perm = [&](int buf, int c, int mt) {
        if (tid < 32) {
            // c*RTOT_ and mt*MT are multiples of 128 -> source 512B aligned
            const char* src = (const char*)g_perm + ((size_t)c * RTOT_ + mt * MT) * 4 + tid * 16;
            cp_async16(sbase + OFF_PERM + buf * 512 + tid * 16, src, 16);
        }
    };
    // full-width B (512 rows x 96B) + full bias (512 floats), once per class.
    // B-tile row `row` holds weights of physical column colOf(row).
    auto prefetch_Bfull = [&](int c) {
#pragma unroll
        for (int rr = 0; rr < 2; rr++) {
            int row = tid * 2 + rr;
            const char* src = (const char*)g_Wb + ((size_t)c * E_ + colOf(row)) * WROW_;
            uint32_t dst = sbase + OFF_B + (uint32_t)row * STRIDE_B;
#pragma unroll
            for (int i = 0; i < 6; i++)
                cp_async16(dst + i * 16, src + i * 16, 16);
        }
        if (tid < 128) {
            const char* src = (const char*)b_nei + (size_t)c * E_ * 4 + tid * 16;
            cp_async16(sbase + OFF_BIAS + tid * 16, src, 16);
        }
    };

    // prologue
    int c0, mt0;
    if (map_job(mid0, c0, mt0)) {
        prefetch_A(0, c0, mt0);
        prefetch_perm(0, c0, mt0);
        prefetch_Bfull(c0);
        cp_commit();

        int cur = 0, bclass = c0;

        for (int j = 0; j < JOBS_; j++) {
            int mid = mid0 + j;
            int c, mt;
            if (!map_job(mid, c, mt)) break;
            int cnt = cnts[c];

            cp_wait_all();          // this thread's copies for job j done
            __syncthreads();        // all threads' copies + prev compute done

            // B/bias reload on class change (uniform branch; per-thread
            // wait_group needs trailing __syncthreads for visibility)
            if (c != bclass) {
                prefetch_Bfull(c);
                cp_commit();
                cp_wait_all();
                __syncthreads();
                bclass = c;
            }

            // prefetch job j+1 A+perm into alternate buffer — overlaps compute
            if (j + 1 < JOBS_) {
                int cn, mtn;
                if (map_job(mid + 1, cn, mtn)) {
                    prefetch_A(cur ^ 1, cn, mtn);
                    prefetch_perm(cur ^ 1, cn, mtn);
                    cp_commit();
                }
            }

            const int*   s_perm = (const int*)(smem + OFF_PERM + cur * 512);
            const float* s_bias = (const float*)(smem + OFF_BIAS);

            uint32_t a_u32 = sbase + OFF_A + cur * TILE_A;
            uint32_t a_base = a_u32 + (uint32_t)(wm * 64 + (lane & 15)) * STRIDE_A
                                    + ((lane >> 4) << 4);
            int g = lane >> 2, t4 = lane & 3;
            int m0 = mt * MT;

            // bias float4s for this thread's physical columns (row-invariant)
            // loaded per nt below.

            // ---- compute all 4 n-tiles with resident B ----
#pragma unroll
            for (int nt = 0; nt < 4; nt++) {
                uint32_t b_base = sbase + OFF_B
                    + (uint32_t)(nt * NT + wn * 32 + ((lane >> 4) << 3) + (lane & 7)) * STRIDE_B
                    + (((lane >> 3) & 1) << 4);

                float acc[4][4][4];
#pragma unroll
                for (int i = 0; i < 4; i++)
#pragma unroll
                    for (int jj = 0; jj < 4; jj++)
#pragma unroll
                        for (int q = 0; q < 4; q++) acc[i][jj][q] = 0.f;

#pragma unroll
                for (int kc = 0; kc < 3; kc++) {       // 48 = 3 x 16
                    uint32_t kb = kc * 32;
                    uint32_t Bh0[4], Bh1[4];
                    ldsm_x4(Bh0, b_base + kb);                   // subtiles 0,1
                    ldsm_x4(Bh1, b_base + 16 * STRIDE_B + kb);   // subtiles 2,3
#pragma unroll
                    for (int mi = 0; mi < 4; mi++) {
                        uint32_t Ah[4], Al[4];
                        ldsm_x4(Ah, a_base + (uint32_t)mi * 16 * STRIDE_A + kb);
                        ldsm_x4(Al, a_base + (uint32_t)mi * 16 * STRIDE_A + 96 + kb);
                        // hi*hi
                        mma16816h(acc[mi][0], Ah, Bh0[0], Bh0[1]);
                        mma16816h(acc[mi][1], Ah, Bh0[2], Bh0[3]);
                        mma16816h(acc[mi][2], Ah, Bh1[0], Bh1[1]);
                        mma16816h(acc[mi][3], Ah, Bh1[2], Bh1[3]);
                        // lo*hi
                        mma16816h(acc[mi][0], Al, Bh0[0], Bh0[1]);
                        mma16816h(acc[mi][1], Al, Bh0[2], Bh0[3]);
                        mma16816h(acc[mi][2], Al, Bh1[0], Bh1[1]);
                        mma16816h(acc[mi][3], Al, Bh1[2], Bh1[3]);
                    }
                }

                // ---- epilogue for this nt: STG.128 (physically-permuted cols) ----
                int cbase = nt * NT + wn * 32;
                float4 b0 = *(const float4*)(s_bias + cbase + t4 * 4);        // group 0
                float4 b1 = *(const float4*)(s_bias + cbase + 16 + t4 * 4);   // group 1
#pragma unroll
                for (int mi = 0; mi < 4; mi++) {
#pragma unroll
                    for (int half = 0; half < 2; half++) {
                        int rloc = wm * 64 + mi * 16 + g + half * 8;
                        if (m0 + rloc < cnt) {
                            int rg = s_perm[rloc];
                            float* orow = out_nei + (size_t)rg * E_ + cbase;
                            int h2 = half * 2;
                            float4 v0 = make_float4(
                                acc[mi][0][h2]     + b0.x,
                                acc[mi][0][h2 + 1] + b0.y,
                                acc[mi][1][h2]     + b0.z,
                                acc[mi][1][h2 + 1] + b0.w);
                            float4 v1 = make_float4(
                                acc[mi][2][h2]     + b1.x,
                                acc[mi][2][h2 + 1] + b1.y,
                                acc[mi][3][h2]     + b1.z,
                                acc[mi][3][h2 + 1] + b1.w);
                            *(float4*)(orow + t4 * 4)      = v0;
                            *(float4*)(orow + 16 + t4 * 4) = v1;
                        }
                    }
                }
            }

            cur ^= 1;
        }
    }

    // ================== fused x-path tail ==================
    {
        int mid = blockIdx.x;
        int c = -1, gt = 0, acc_t = 0;
#pragma unroll
        for (int cc = 0; cc < C_; cc++) {
            int t = (g_xcnt[cc] + XGRP - 1) / XGRP;
            if (c < 0 && mid < acc_t + t) { c = cc; gt = mid - acc_t; }
            acc_t += t;
        }
        if (c >= 0) {
            int cnt = g_xcnt[c];
            int xo  = g_xoff[c];
            int s0  = gt * XGRP;
            int m   = min(XGRP, cnt - s0);

            __syncthreads();                      // done with GEMM smem
            int*   s_rows = (int*)smem;           // [8]
            float (*s_obs)[DNEI_] = (float(*)[DNEI_])(smem + 32);

            if (tid < XGRP)
                s_rows[tid] = (tid < m) ? g_xperm[xo + s0 + tid] : -1;
            __syncthreads();
            if (tid < 96) {
                int s = tid / 12, q = tid % 12;
                int rb = s_rows[s];
                float4 v = make_float4(0.f, 0.f, 0.f, 0.f);
                if (rb >= 0) v = *(const float4*)(obs + (size_t)rb * DNEI_ + q * 4);
                *(float4*)(&s_obs[s][q * 4]) = v;
            }
            __syncthreads();

            int ct   = tid & 127;
            int half = tid >> 7;
            int col  = ct * 4;
            const float* W = W_self + (size_t)c * DSELF_ * E_ + col;
            float4 a0 = make_float4(0,0,0,0), a1 = a0, a2 = a0, a3 = a0;
            float4 a4 = a0, a5 = a0, a6 = a0, a7 = a0;
#pragma unroll 4
            for (int j = 0; j < DNEI_; j++) {
                float4 w4 = *(const float4*)(W + (size_t)j * E_);
                float t0 = s_obs[0][j], t1 = s_obs[1][j], t2 = s_obs[2][j], t3 = s_obs[3][j];
                float t4v = s_obs[4][j], t5 = s_obs[5][j], t6 = s_obs[6][j], t7 = s_obs[7][j];
                a0.x += t0*w4.x; a0.y += t0*w4.y; a0.z += t0*w4.z; a0.w += t0*w4.w;
                a1.x += t1*w4.x; a1.y += t1*w4.y; a1.z += t1*w4.z; a1.w += t1*w4.w;
                a2.x += t2*w4.x; a2.y += t2*w4.y; a2.z += t2*w4.z; a2.w += t2*w4.w;
                a3.x += t3*w4.x; a3.y += t3*w4.y; a3.z += t3*w4.z; a3.w += t3*w4.w;
                a4.x += t4v*w4.x; a4.y += t4v*w4.y; a4.z += t4v*w4.z; a4.w += t4v*w4.w;
                a5.x += t5*w4.x; a5.y += t5*w4.y; a5.z += t5*w4.z; a5.w += t5*w4.w;
                a6.x += t6*w4.x; a6.y += t6*w4.y; a6.z += t6*w4.z; a6.w += t6*w4.w;
                a7.x += t7*w4.x; a7.y += t7*w4.y; a7.z += t7*w4.z; a7.w += t7*w4.w;
            }

            float4 av[XGRP] = {a0, a1, a2, a3, a4, a5, a6, a7};
            int kk0 = half * (K_ / 2), kk1 = kk0 + (K_ / 2);
#pragma unroll
            for (int kk = kk0; kk < kk1; kk++) {
                float4 an = *(const float4*)(g_anchor + ((size_t)c * K_ + kk) * E_ + col);
#pragma unroll
                for (int s = 0; s < XGRP; s++) {
                    int rb = s_rows[s];
                    if (rb >= 0) {
                        float4 v = make_float4(av[s].x + an.x, av[s].y + an.y,
                                               av[s].z + an.z, av[s].w + an.w);
                        *(float4*)(out_x + ((size_t)rb * K_ + kk) * E_ + col) = v;
                    }
                }
            }
        }
    }

    // Reset class counters for the next graph replay. All 262 CTAs are one
    // co-resident wave: every CTA read g_cur in its first microsecond; block 0
    // resets at the very end of its (much longer) execution.
    if (blockIdx.x == 0 && tid < CN_) g_cur[tid] = 0;
}

// ---------------- launcher ----------------
extern "C" void kernel_launch(void* const* d_in, const int* in_sizes, int n_in,
                              void* d_out, int out_size) {
    const float* obs         = (const float*)d_in[0];
    const float* neis        = (const float*)d_in[1];
    const float* init_trajs  = (const float*)d_in[2];
    const float* W_self      = (const float*)d_in[3];
    const float* b_self      = (const float*)d_in[4];
    const float* W_nei       = (const float*)d_in[5];
    const float* b_nei       = (const float*)d_in[6];
    const int*   self_labels = (const int*)d_in[7];
    const int*   nei_labels  = (const int*)d_in[8];

    float* out_x   = (float*)d_out;
    float* out_nei = (float*)d_out + X_ELEMS;

    cudaFuncSetAttribute(k_gemm_mma, cudaFuncAttributeMaxDynamicSharedMemorySize, SMEM_BYTES);

    k_fused<<<K1_GRID, 256>>>(neis, nei_labels, W_nei, init_trajs,
                              W_self, b_self, self_labels);
    k_gemm_mma<<<GEMM_GRID, 256, SMEM_BYTES>>>(b_nei, obs, W_self, out_nei, out_x);
}